// round 6
// baseline (speedup 1.0000x reference)
#include <cuda_runtime.h>
#include <cuda_fp16.h>
#include <cstdint>

#define BSZ 4
#define SEQ 2048
#define DIM 1024
#define MTOT (BSZ*SEQ)

// ---------------------------------------------------------------------------
// Packed layout per row of K floats, K/32 chunks of 128B:
//   [64B: 32 fp16 hi][32B: 32 e4m3(v)][32B: 32 e4m3((v-fp16(v))*4096)]
// Row byte stride = K*4.
// ---------------------------------------------------------------------------
__device__ __align__(128) char g_xpk   [(size_t)MTOT * DIM * 4];
__device__ __align__(128) char g_wpk   [(size_t)3 * DIM * DIM * 4];
__device__ __align__(128) char g_w1pk  [(size_t)DIM * 2 * DIM * 4];
__device__ __align__(128) char g_w2pk  [(size_t)DIM * DIM * 4];
__device__ __align__(128) char g_qkpk  [(size_t)2 * MTOT * DIM * 4];
__device__ __align__(128) float g_v    [(size_t)MTOT * DIM];
__device__ __align__(128) char g_vtpk  [(size_t)BSZ * DIM * SEQ * 4];
__device__ __align__(128) float g_scores[(size_t)BSZ * SEQ * SEQ];
__device__ __align__(128) char g_ppk   [(size_t)BSZ * SEQ * SEQ * 4];
__device__ __align__(128) char g_apk   [(size_t)MTOT * DIM * 4];
__device__ __align__(128) char g_hpk   [(size_t)MTOT * DIM * 4];

#define INV4096 2.44140625e-4f

// ---------------------------------------------------------------------------
// Helpers
// ---------------------------------------------------------------------------
__device__ __forceinline__ uint32_t smem_u32(const void* p) {
    uint32_t a;
    asm("{ .reg .u64 t; cvta.to.shared.u64 t, %1; cvt.u32.u64 %0, t; }" : "=r"(a) : "l"(p));
    return a;
}
__device__ __forceinline__ uint32_t swz(uint32_t x) { return x ^ ((x >> 3) & 0x70); }

__device__ __forceinline__ uint16_t e4m3pair(float v0, float v1) {
    uint16_t r;   // low byte = v0
    asm("cvt.rn.satfinite.e4m3x2.f32 %0, %1, %2;" : "=h"(r) : "f"(v1), "f"(v0));
    return r;
}
__device__ __forceinline__ void pack2(float v0, float v1,
                                      uint32_t& f16p, uint16_t& h8p, uint16_t& l8p) {
    __half h0 = __float2half_rn(v0), h1 = __float2half_rn(v1);
    f16p = (uint32_t)__half_as_ushort(h0) | ((uint32_t)__half_as_ushort(h1) << 16);
    h8p = e4m3pair(v0, v1);
    l8p = e4m3pair((v0 - __half2float(h0)) * 4096.f,
                   (v1 - __half2float(h1)) * 4096.f);
}
__device__ __forceinline__ void ldsm4(uint32_t* r, uint32_t addr) {
    asm volatile("ldmatrix.sync.aligned.m8n8.x4.shared.b16 {%0,%1,%2,%3}, [%4];"
                 : "=r"(r[0]), "=r"(r[1]), "=r"(r[2]), "=r"(r[3]) : "r"(addr));
}
__device__ __forceinline__ void mma_f16(float* d, const uint32_t* a, const uint32_t* b) {
    asm volatile(
        "mma.sync.aligned.m16n8k16.row.col.f32.f16.f16.f32 "
        "{%0,%1,%2,%3}, {%4,%5,%6,%7}, {%8,%9}, {%0,%1,%2,%3};"
        : "+f"(d[0]), "+f"(d[1]), "+f"(d[2]), "+f"(d[3])
        : "r"(a[0]), "r"(a[1]), "r"(a[2]), "r"(a[3]), "r"(b[0]), "r"(b[1]));
}
__device__ __forceinline__ void mma_e4m3(float* d, const uint32_t* a, const uint32_t* b) {
    asm volatile(
        "mma.sync.aligned.m16n8k32.row.col.f32.e4m3.e4m3.f32 "
        "{%0,%1,%2,%3}, {%4,%5,%6,%7}, {%8,%9}, {%0,%1,%2,%3};"
        : "+f"(d[0]), "+f"(d[1]), "+f"(d[2]), "+f"(d[3])
        : "r"(a[0]), "r"(a[1]), "r"(a[2]), "r"(a[3]), "r"(b[0]), "r"(b[1]));
}

// ---------------------------------------------------------------------------
// Generic NT GEMM, 128(M)x64(N) tile, 8 warps (32x32 each).
// fp16 main + e4m3 cross-corrections. 4-stage cp.async pipeline, 1 sync/chunk.
// mode: 1=relu, 2=causal block skip, 4=causal k-limit, 8=packed output
// ---------------------------------------------------------------------------
#define TA_BYTES 16384
#define STG 24576
#define NSTG 4
#define GEMM_SMEM (NSTG * STG)

__global__ __launch_bounds__(256, 2) void gemm_mma(
    const char* __restrict__ Ap, const char* __restrict__ Bp,
    long aRB, long bRB, long zsA, long zsB, int kc1,
    const char* __restrict__ Ap2, const char* __restrict__ Bp2,
    long aRB2, long bRB2, int kc2,
    void* Cout, long zsC, int ldc, long cRB,
    float scale, const float* __restrict__ bias, int mode)
{
    int m0 = blockIdx.y * 128, n0 = blockIdx.x * 64;
    if ((mode & 2) && n0 >= m0 + 128) return;
    if (mode & 4) { int ke = (m0 + 128) >> 5; if (ke < kc1) kc1 = ke; }
    int z = blockIdx.z;
    Ap += (long)z * zsA;
    Bp += (long)z * zsB;
    char* Cb = (char*)Cout + (long)z * zsC;

    extern __shared__ char smem[];
    uint32_t sb = smem_u32(smem);
    int tid = threadIdx.x;
    int nch = kc1 + kc2;

    auto issue = [&](int c) {
        uint32_t stg = sb + (uint32_t)(c % NSTG) * STG;
        int cc = c;
        const char* pa; const char* pb; long ra, rb;
        if (c < kc1) { pa = Ap;  pb = Bp;  ra = aRB;  rb = bRB; }
        else         { pa = Ap2; pb = Bp2; ra = aRB2; rb = bRB2; cc = c - kc1; }
        long cOff = (long)cc * 128;
#pragma unroll
        for (int j = 0; j < 6; j++) {
            int slot = tid + j * 256;
            bool isA = slot < 1024;
            int local = isA ? slot : slot - 1024;
            int row = local >> 3, seg = local & 7;
            const char* g = (isA ? pa + (long)(m0 + row) * ra
                                 : pb + (long)(n0 + row) * rb) + cOff + seg * 16;
            uint32_t d = stg + (isA ? 0u : (uint32_t)TA_BYTES)
                             + swz((uint32_t)(row * 128 + seg * 16));
            asm volatile("cp.async.cg.shared.global [%0], [%1], 16;" :: "r"(d), "l"(g));
        }
        asm volatile("cp.async.commit_group;" ::: "memory");
    };
    auto pad = [&]() { asm volatile("cp.async.commit_group;" ::: "memory"); };

    int wid = tid >> 5, lane = tid & 31;
    int wm = wid >> 1, wn = wid & 1;   // 4 (m) x 2 (n) warps
    float acc[2][4][4] = {};    // fp16 main
    float acc2[2][4][4] = {};   // fp8 cross (scaled 4096)

    // prologue: 3 issue slots (pad when short)
#pragma unroll
    for (int c = 0; c < 3; c++) { if (c < nch) issue(c); else pad(); }

    uint32_t aRowLoc = (uint32_t)((wm * 32 + (lane & 15)) * 128 + ((lane >> 4) << 4));
    int bg = lane >> 3;
    uint32_t bRowLoc = (uint32_t)((wn * 32 + (lane & 7) + ((bg >> 1) << 3)) * 128 + ((bg & 1) << 4));

    for (int c = 0; c < nch; c++) {
        asm volatile("cp.async.wait_group 2;" ::: "memory");
        __syncthreads();
        if (c + 3 < nch) issue(c + 3); else pad();

        uint32_t ta = sb + (uint32_t)(c % NSTG) * STG;
        uint32_t tb = ta + TA_BYTES;

        // main fp16: bytes [0,64), two k16 steps
#pragma unroll
        for (int s = 0; s < 2; s++) {
            int ko = s * 32;
            uint32_t af[2][4];
#pragma unroll
            for (int mt = 0; mt < 2; mt++)
                ldsm4(af[mt], ta + swz(aRowLoc + mt * 2048 + ko));
            uint32_t bf[2][4];
#pragma unroll
            for (int bt = 0; bt < 2; bt++)
                ldsm4(bf[bt], tb + swz(bRowLoc + bt * 2048 + ko));
#pragma unroll
            for (int mt = 0; mt < 2; mt++)
#pragma unroll
                for (int nt = 0; nt < 4; nt++)
                    mma_f16(acc[mt][nt], af[mt], &bf[nt >> 1][(nt & 1) * 2]);
        }
        // fp8 crosses: cp0 = Ah8*Bl8s, cp1 = Al8s*Bh8  (one k32 step each)
#pragma unroll
        for (int cp = 0; cp < 2; cp++) {
            int aoff = cp ? 96 : 64;
            int boff = cp ? 64 : 96;
            uint32_t af[2][4];
#pragma unroll
            for (int mt = 0; mt < 2; mt++)
                ldsm4(af[mt], ta + swz(aRowLoc + mt * 2048 + aoff));
            uint32_t bf[2][4];
#pragma unroll
            for (int bt = 0; bt < 2; bt++)
                ldsm4(bf[bt], tb + swz(bRowLoc + bt * 2048 + boff));
#pragma unroll
            for (int mt = 0; mt < 2; mt++)
#pragma unroll
                for (int nt = 0; nt < 4; nt++)
                    mma_e4m3(acc2[mt][nt], af[mt], &bf[nt >> 1][(nt & 1) * 2]);
        }
    }

    // Epilogue
    int ql = lane & 3;
    int r0 = m0 + wm * 32 + (lane >> 2);
    if (mode & 8) {
        int cw = (n0 + wn * 32) >> 5;
        char* cbase = Cb + (long)cw * 128;
#pragma unroll
        for (int mt = 0; mt < 2; mt++) {
#pragma unroll
            for (int half = 0; half < 2; half++) {
                long row = r0 + mt * 16 + half * 8;
                char* rp = cbase + row * cRB;
#pragma unroll
                for (int nt = 0; nt < 4; nt++) {
                    float v0 = (acc[mt][nt][half * 2 + 0] + acc2[mt][nt][half * 2 + 0] * INV4096) * scale;
                    float v1 = (acc[mt][nt][half * 2 + 1] + acc2[mt][nt][half * 2 + 1] * INV4096) * scale;
                    int col = n0 + wn * 32 + nt * 8 + ql * 2;
                    if (bias) { v0 += bias[col]; v1 += bias[col + 1]; }
                    if (mode & 1) { v0 = fmaxf(v0, 0.f); v1 = fmaxf(v1, 0.f); }
                    uint32_t fp; uint16_t h8, l8;
                    pack2(v0, v1, fp, h8, l8);
                    int colk = nt * 8 + ql * 2;
                    *(uint32_t*)(rp + colk * 2) = fp;
                    *(uint16_t*)(rp + 64 + colk) = h8;
                    *(uint16_t*)(rp + 96 + colk) = l8;
                }
            }
        }
    } else {
        float* Cf = (float*)Cb;
#pragma unroll
        for (int mt = 0; mt < 2; mt++) {
#pragma unroll
            for (int half = 0; half < 2; half++) {
                long row = r0 + mt * 16 + half * 8;
#pragma unroll
                for (int nt = 0; nt < 4; nt++) {
                    float v0 = (acc[mt][nt][half * 2 + 0] + acc2[mt][nt][half * 2 + 0] * INV4096) * scale;
                    float v1 = (acc[mt][nt][half * 2 + 1] + acc2[mt][nt][half * 2 + 1] * INV4096) * scale;
                    int col = n0 + wn * 32 + nt * 8 + ql * 2;
                    if (bias) { v0 += bias[col]; v1 += bias[col + 1]; }
                    if (mode & 1) { v0 = fmaxf(v0, 0.f); v1 = fmaxf(v1, 0.f); }
                    *(float2*)(Cf + row * (long)ldc + col) = make_float2(v0, v1);
                }
            }
        }
    }
}

// ---------------------------------------------------------------------------
// Pack fp32 [rows][K] -> packed
// ---------------------------------------------------------------------------
__global__ __launch_bounds__(256) void k_pack(const float* __restrict__ src,
                                              char* __restrict__ dst, int K) {
    long j0 = ((long)blockIdx.x * 256 + threadIdx.x) * 8;
    float4 f0 = *(const float4*)(src + j0);
    float4 f1 = *(const float4*)(src + j0 + 4);
    long row = j0 / K;
    int k0 = (int)(j0 - row * K);
    uint32_t fp[4]; uint16_t h8[4], l8[4];
    pack2(f0.x, f0.y, fp[0], h8[0], l8[0]);
    pack2(f0.z, f0.w, fp[1], h8[1], l8[1]);
    pack2(f1.x, f1.y, fp[2], h8[2], l8[2]);
    pack2(f1.z, f1.w, fp[3], h8[3], l8[3]);
    char* p = dst + row * (long)K * 4 + (k0 >> 5) * 128;
    int kk = k0 & 31;
    *(uint4*)(p + kk * 2) = make_uint4(fp[0], fp[1], fp[2], fp[3]);
    *(uint2*)(p + 64 + kk) = make_uint2((uint32_t)h8[0] | ((uint32_t)h8[1] << 16),
                                        (uint32_t)h8[2] | ((uint32_t)h8[3] << 16));
    *(uint2*)(p + 96 + kk) = make_uint2((uint32_t)l8[0] | ((uint32_t)l8[1] << 16),
                                        (uint32_t)l8[2] | ((uint32_t)l8[3] << 16));
}

// ---------------------------------------------------------------------------
// Transpose + pack: in fp32 [R][C] -> packed rows=C, K=R
// ---------------------------------------------------------------------------
__global__ __launch_bounds__(256) void k_transpack(const float* __restrict__ in,
                                                   char* __restrict__ out,
                                                   int R, int C,
                                                   long inPlane, long outPlaneBytes) {
    in  += (long)blockIdx.z * inPlane;
    out += (long)blockIdx.z * outPlaneBytes;
    int c0 = blockIdx.x * 32, r0 = blockIdx.y * 32;
    __shared__ float t[32][33];
    int tx = threadIdx.x & 31, ty = threadIdx.x >> 5;
#pragma unroll
    for (int i = ty; i < 32; i += 8)
        t[i][tx] = in[(long)(r0 + i) * C + c0 + tx];
    __syncthreads();
    int i = threadIdx.x >> 3;
    int g = (threadIdx.x & 7) * 4;
    float v0 = t[g + 0][i], v1 = t[g + 1][i], v2 = t[g + 2][i], v3 = t[g + 3][i];
    uint32_t fp0, fp1; uint16_t h0, h1, l0, l1;
    pack2(v0, v1, fp0, h0, l0);
    pack2(v2, v3, fp1, h1, l1);
    char* p = out + (long)(c0 + i) * ((long)R * 4) + (r0 >> 5) * 128;
    *(uint2*)(p + g * 2) = make_uint2(fp0, fp1);
    *(uint32_t*)(p + 64 + g) = (uint32_t)h0 | ((uint32_t)h1 << 16);
    *(uint32_t*)(p + 96 + g) = (uint32_t)l0 | ((uint32_t)l1 << 16);
}

// ---------------------------------------------------------------------------
// Causal softmax: fp32 scores row -> packed probs row
// ---------------------------------------------------------------------------
__global__ __launch_bounds__(256) void k_softmax() {
    long rowi = blockIdx.x;
    const float* p = g_scores + rowi * SEQ;
    char* dst = g_ppk + rowi * (SEQ * 4);
    int cnt = (int)(rowi & (SEQ - 1)) + 1;
    int tid = threadIdx.x;
    int j0 = tid * 8;
    __shared__ float red[256];

    float v[8];
    float4 f0 = *(const float4*)(p + j0);
    float4 f1 = *(const float4*)(p + j0 + 4);
    v[0]=f0.x; v[1]=f0.y; v[2]=f0.z; v[3]=f0.w;
    v[4]=f1.x; v[5]=f1.y; v[6]=f1.z; v[7]=f1.w;
    float m = -3.4e38f;
#pragma unroll
    for (int i = 0; i < 8; i++) {
        if (j0 + i >= cnt) v[i] = -3.4e38f;
        m = fmaxf(m, v[i]);
    }
    red[tid] = m;
    __syncthreads();
    for (int s = 128; s > 0; s >>= 1) {
        if (tid < s) red[tid] = fmaxf(red[tid], red[tid + s]);
        __syncthreads();
    }
    m = red[0];
    __syncthreads();
    float sum = 0.f;
#pragma unroll
    for (int i = 0; i < 8; i++) {
        v[i] = (j0 + i < cnt) ? __expf(v[i] - m) : 0.f;
        sum += v[i];
    }
    red[tid] = sum;
    __syncthreads();
    for (int s = 128; s > 0; s >>= 1) {
        if (tid < s) red[tid] += red[tid + s];
        __syncthreads();
    }
    float inv = 1.0f / red[0];
#pragma unroll
    for (int i = 0; i < 8; i++) v[i] *= inv;

    uint32_t fp[4]; uint16_t h8[4], l8[4];
#pragma unroll
    for (int i = 0; i < 4; i++) pack2(v[2 * i], v[2 * i + 1], fp[i], h8[i], l8[i]);
    char* q = dst + (j0 >> 5) * 128;
    int kk = j0 & 31;
    *(uint4*)(q + kk * 2) = make_uint4(fp[0], fp[1], fp[2], fp[3]);
    *(uint2*)(q + 64 + kk) = make_uint2((uint32_t)h8[0] | ((uint32_t)h8[1] << 16),
                                        (uint32_t)h8[2] | ((uint32_t)h8[3] << 16));
    *(uint2*)(q + 96 + kk) = make_uint2((uint32_t)l8[0] | ((uint32_t)l8[1] << 16),
                                        (uint32_t)l8[2] | ((uint32_t)l8[3] << 16));
}

// ---------------------------------------------------------------------------
// Launch
// ---------------------------------------------------------------------------
extern "C" void kernel_launch(void* const* d_in, const int* in_sizes, int n_in,
                              void* d_out, int out_size) {
    const float* x  = (const float*)d_in[0];
    const float* Wq = (const float*)d_in[1];
    const float* Wk = (const float*)d_in[2];
    const float* Wv = (const float*)d_in[3];
    const float* W1 = (const float*)d_in[4];
    const float* b1 = (const float*)d_in[5];
    const float* W2 = (const float*)d_in[6];
    const float* b2 = (const float*)d_in[7];
    float* out = (float*)d_out;

    cudaFuncSetAttribute(gemm_mma, cudaFuncAttributeMaxDynamicSharedMemorySize, GEMM_SMEM);

    void* p;
    cudaGetSymbolAddress(&p, g_xpk);   char* xpk  = (char*)p;
    cudaGetSymbolAddress(&p, g_wpk);   char* wpk  = (char*)p;
    cudaGetSymbolAddress(&p, g_w1pk);  char* w1pk = (char*)p;
    cudaGetSymbolAddress(&p, g_w2pk);  char* w2pk = (char*)p;
    cudaGetSymbolAddress(&p, g_qkpk);  char* qkpk = (char*)p;
    cudaGetSymbolAddress(&p, g_v);     float* v   = (float*)p;
    cudaGetSymbolAddress(&p, g_vtpk);  char* vtpk = (char*)p;
    cudaGetSymbolAddress(&p, g_scores);float* sc  = (float*)p;
    cudaGetSymbolAddress(&p, g_ppk);   char* ppk  = (char*)p;
    cudaGetSymbolAddress(&p, g_apk);   char* apk  = (char*)p;
    cudaGetSymbolAddress(&p, g_hpk);   char* hpk  = (char*)p;

    const long WPL = (long)DIM * DIM * 4;

    k_pack<<<dim3((MTOT * DIM) / (8 * 256)), 256>>>(x, xpk, DIM);
    k_transpack<<<dim3(32, 32, 1), 256>>>(Wq, wpk + 0 * WPL, DIM, DIM, 0, 0);
    k_transpack<<<dim3(32, 32, 1), 256>>>(Wk, wpk + 1 * WPL, DIM, DIM, 0, 0);
    k_transpack<<<dim3(32, 32, 1), 256>>>(Wv, wpk + 2 * WPL, DIM, DIM, 0, 0);
    k_transpack<<<dim3(32, 64, 1), 256>>>(W1, w1pk, 2 * DIM, DIM, 0, 0);
    k_transpack<<<dim3(32, 32, 1), 256>>>(W2, w2pk, DIM, DIM, 0, 0);

    // q,k = x @ Wq/Wk (packed out)
    gemm_mma<<<dim3(16, 64, 2), 256, GEMM_SMEM>>>(
        xpk, wpk, DIM * 4, DIM * 4, 0, WPL, 32,
        0, 0, 0, 0, 0,
        qkpk, (long)MTOT * DIM * 4, 0, DIM * 4,
        1.0f, 0, 8);
    // v = x @ Wv (fp32 out)
    gemm_mma<<<dim3(16, 64, 1), 256, GEMM_SMEM>>>(
        xpk, wpk + 2 * WPL, DIM * 4, DIM * 4, 0, 0, 32,
        0, 0, 0, 0, 0,
        v, 0, DIM, 0,
        1.0f, 0, 0);
    // vT packed per batch
    k_transpack<<<dim3(32, 64, BSZ), 256>>>(v, vtpk, SEQ, DIM,
                                            (long)SEQ * DIM, (long)DIM * SEQ * 4);
    // scores = q k^T / 32 (fp32 out, causal block skip)
    gemm_mma<<<dim3(32, 16, BSZ), 256, GEMM_SMEM>>>(
        qkpk, qkpk + (long)MTOT * DIM * 4,
        DIM * 4, DIM * 4, (long)SEQ * DIM * 4, (long)SEQ * DIM * 4, 32,
        0, 0, 0, 0, 0,
        sc, (long)SEQ * SEQ * 4, SEQ, 0,
        0.03125f, 0, 2);
    k_softmax<<<dim3(BSZ * SEQ), 256>>>();
    // attn = probs @ v (causal k-limit; packed out)
    gemm_mma<<<dim3(16, 16, BSZ), 256, GEMM_SMEM>>>(
        ppk, vtpk, SEQ * 4, SEQ * 4, (long)SEQ * SEQ * 4, (long)DIM * SEQ * 4, 64,
        0, 0, 0, 0, 0,
        apk, (long)SEQ * DIM * 4, 0, DIM * 4,
        1.0f, 0, 4 | 8);
    // h = relu([attn|x] @ W1 + b1)
    gemm_mma<<<dim3(16, 64, 1), 256, GEMM_SMEM>>>(
        apk, w1pk, DIM * 4, 2 * DIM * 4, 0, 0, 32,
        xpk, w1pk + DIM * 4, DIM * 4, 2 * DIM * 4, 32,
        hpk, 0, 0, DIM * 4,
        1.0f, b1, 1 | 8);
    // out = h @ W2 + b2
    gemm_mma<<<dim3(16, 64, 1), 256, GEMM_SMEM>>>(
        hpk, w2pk, DIM * 4, DIM * 4, 0, 0, 32,
        0, 0, 0, 0, 0,
        out, 0, DIM, 0,
        1.0f, b2, 0);
}

// round 7
// speedup vs baseline: 1.1857x; 1.1857x over previous
#include <cuda_runtime.h>
#include <cuda_bf16.h>
#include <cstdint>

#define BSZ 4
#define SEQ 2048
#define DIM 1024
#define MTOT (BSZ*SEQ)

// ---------------------------------------------------------------------------
// Packed layout: per row of K floats, K/32 chunks of 128B: [32 bf16 hi][32 bf16 lo]
// Row byte stride = K*4.
// ---------------------------------------------------------------------------
__device__ __align__(128) char g_xpk   [(size_t)MTOT * DIM * 4];
__device__ __align__(128) char g_wpk   [(size_t)3 * DIM * DIM * 4];
__device__ __align__(128) char g_w1pk  [(size_t)DIM * 2 * DIM * 4];
__device__ __align__(128) char g_w2pk  [(size_t)DIM * DIM * 4];
__device__ __align__(128) char g_qkpk  [(size_t)2 * MTOT * DIM * 4];
__device__ __align__(128) float g_v    [(size_t)MTOT * DIM];
__device__ __align__(128) char g_vtpk  [(size_t)BSZ * DIM * SEQ * 4];
__device__ __align__(128) float g_scores[(size_t)BSZ * SEQ * SEQ];
__device__ __align__(128) char g_ppk   [(size_t)BSZ * SEQ * SEQ * 4];
__device__ __align__(128) char g_apk   [(size_t)MTOT * DIM * 4];
__device__ __align__(128) char g_hpk   [(size_t)MTOT * DIM * 4];

// ---------------------------------------------------------------------------
// Helpers
// ---------------------------------------------------------------------------
__device__ __forceinline__ uint32_t smem_u32(const void* p) {
    uint32_t a;
    asm("{ .reg .u64 t; cvta.to.shared.u64 t, %1; cvt.u32.u64 %0, t; }" : "=r"(a) : "l"(p));
    return a;
}
__device__ __forceinline__ uint32_t swz(uint32_t x) { return x ^ ((x >> 3) & 0x70); }

__device__ __forceinline__ uint32_t bfpair(float v0, float v1) {
    uint32_t r;   // low16 = bf16(v0), high16 = bf16(v1)
    asm("cvt.rn.bf16x2.f32 %0, %1, %2;" : "=r"(r) : "f"(v1), "f"(v0));
    return r;
}
__device__ __forceinline__ uint32_t bflo(float v0, float v1, uint32_t hi) {
    float h0 = __uint_as_float(hi << 16);
    float h1 = __uint_as_float(hi & 0xffff0000u);
    return bfpair(v0 - h0, v1 - h1);
}
__device__ __forceinline__ void ldsm4(uint32_t* r, uint32_t addr) {
    asm volatile("ldmatrix.sync.aligned.m8n8.x4.shared.b16 {%0,%1,%2,%3}, [%4];"
                 : "=r"(r[0]), "=r"(r[1]), "=r"(r[2]), "=r"(r[3]) : "r"(addr));
}
__device__ __forceinline__ void mma16816(float* d, const uint32_t* a, const uint32_t* b) {
    asm volatile(
        "mma.sync.aligned.m16n8k16.row.col.f32.bf16.bf16.f32 "
        "{%0,%1,%2,%3}, {%4,%5,%6,%7}, {%8,%9}, {%0,%1,%2,%3};"
        : "+f"(d[0]), "+f"(d[1]), "+f"(d[2]), "+f"(d[3])
        : "r"(a[0]), "r"(a[1]), "r"(a[2]), "r"(a[3]), "r"(b[0]), "r"(b[1]));
}

// ---------------------------------------------------------------------------
// Generic NT GEMM on packed operands, 128(M)x64(N) tile, 8 warps (32x32 each).
// 3-stage cp.async pipeline, 1 sync/chunk, fragment-reuse 3-term split:
//   acc += Ah*Bh + Ah*Bl + Al*Bh   (Ah/Bh loaded once per k16 step)
// mode: 1=relu, 2=causal block skip, 4=causal k-limit, 8=packed output
// ---------------------------------------------------------------------------
#define TA_BYTES 16384
#define STG 24576
#define GEMM_SMEM (3 * STG)

__global__ __launch_bounds__(256, 3) void gemm_mma(
    const char* __restrict__ Ap, const char* __restrict__ Bp,
    long aRB, long bRB, long zsA, long zsB, int kc1,
    const char* __restrict__ Ap2, const char* __restrict__ Bp2,
    long aRB2, long bRB2, int kc2,
    void* Cout, long zsC, int ldc, long cRB,
    float scale, const float* __restrict__ bias, int mode)
{
    int m0 = blockIdx.y * 128, n0 = blockIdx.x * 64;
    if ((mode & 2) && n0 >= m0 + 128) return;
    if (mode & 4) { int ke = (m0 + 128) >> 5; if (ke < kc1) kc1 = ke; }
    int z = blockIdx.z;
    Ap += (long)z * zsA;
    Bp += (long)z * zsB;
    char* Cb = (char*)Cout + (long)z * zsC;

    extern __shared__ char smem[];
    uint32_t sb = smem_u32(smem);
    int tid = threadIdx.x;
    int nch = kc1 + kc2;

    auto issue = [&](int c) {
        uint32_t stg = sb + (uint32_t)(c % 3) * STG;
        int cc = c;
        const char* pa; const char* pb; long ra, rb;
        if (c < kc1) { pa = Ap;  pb = Bp;  ra = aRB;  rb = bRB; }
        else         { pa = Ap2; pb = Bp2; ra = aRB2; rb = bRB2; cc = c - kc1; }
        long cOff = (long)cc * 128;
#pragma unroll
        for (int j = 0; j < 6; j++) {
            int slot = tid + j * 256;
            bool isA = slot < 1024;
            int local = isA ? slot : slot - 1024;
            int row = local >> 3, seg = local & 7;
            const char* g = (isA ? pa + (long)(m0 + row) * ra
                                 : pb + (long)(n0 + row) * rb) + cOff + seg * 16;
            uint32_t d = stg + (isA ? 0u : (uint32_t)TA_BYTES)
                             + swz((uint32_t)(row * 128 + seg * 16));
            asm volatile("cp.async.cg.shared.global [%0], [%1], 16;" :: "r"(d), "l"(g));
        }
        asm volatile("cp.async.commit_group;" ::: "memory");
    };

    int wid = tid >> 5, lane = tid & 31;
    int wm = wid >> 1, wn = wid & 1;   // 4 (m) x 2 (n) warps
    float acc[2][4][4] = {};

    issue(0);
    if (nch > 1) issue(1);
    else asm volatile("cp.async.commit_group;" ::: "memory");

    uint32_t aRowLoc = (uint32_t)((wm * 32 + (lane & 15)) * 128 + ((lane >> 4) << 4));
    int bg = lane >> 3;
    uint32_t bRowLoc = (uint32_t)((wn * 32 + (lane & 7) + ((bg >> 1) << 3)) * 128 + ((bg & 1) << 4));

    for (int c = 0; c < nch; c++) {
        asm volatile("cp.async.wait_group 1;" ::: "memory");
        __syncthreads();
        if (c + 2 < nch) issue(c + 2);
        else asm volatile("cp.async.commit_group;" ::: "memory");

        uint32_t ta = sb + (uint32_t)(c % 3) * STG;
        uint32_t tb = ta + TA_BYTES;
#pragma unroll
        for (int s = 0; s < 2; s++) {
            int ko = s * 32;
            uint32_t Ah[2][4], Bh[2][4], X[2][4];
            // load hi planes once
#pragma unroll
            for (int mt = 0; mt < 2; mt++)
                ldsm4(Ah[mt], ta + swz(aRowLoc + mt * 2048 + ko));
#pragma unroll
            for (int bt = 0; bt < 2; bt++)
                ldsm4(Bh[bt], tb + swz(bRowLoc + bt * 2048 + ko));
            // Ah * Bh
#pragma unroll
            for (int mt = 0; mt < 2; mt++)
#pragma unroll
                for (int nt = 0; nt < 4; nt++)
                    mma16816(acc[mt][nt], Ah[mt], &Bh[nt >> 1][(nt & 1) * 2]);
            // Ah * Bl
#pragma unroll
            for (int bt = 0; bt < 2; bt++)
                ldsm4(X[bt], tb + swz(bRowLoc + bt * 2048 + 64 + ko));
#pragma unroll
            for (int mt = 0; mt < 2; mt++)
#pragma unroll
                for (int nt = 0; nt < 4; nt++)
                    mma16816(acc[mt][nt], Ah[mt], &X[nt >> 1][(nt & 1) * 2]);
            // Al * Bh
#pragma unroll
            for (int mt = 0; mt < 2; mt++)
                ldsm4(X[mt], ta + swz(aRowLoc + mt * 2048 + 64 + ko));
#pragma unroll
            for (int mt = 0; mt < 2; mt++)
#pragma unroll
                for (int nt = 0; nt < 4; nt++)
                    mma16816(acc[mt][nt], X[mt], &Bh[nt >> 1][(nt & 1) * 2]);
        }
    }

    // Epilogue
    int ql = lane & 3;
    int r0 = m0 + wm * 32 + (lane >> 2);
    if (mode & 8) {
        int cw = (n0 + wn * 32) >> 5;
        char* cbase = Cb + (long)cw * 128;
#pragma unroll
        for (int mt = 0; mt < 2; mt++) {
#pragma unroll
            for (int half = 0; half < 2; half++) {
                long row = r0 + mt * 16 + half * 8;
                char* rp = cbase + row * cRB;
#pragma unroll
                for (int nt = 0; nt < 4; nt++) {
                    float v0 = acc[mt][nt][half * 2 + 0] * scale;
                    float v1 = acc[mt][nt][half * 2 + 1] * scale;
                    int col = n0 + wn * 32 + nt * 8 + ql * 2;
                    if (bias) { v0 += bias[col]; v1 += bias[col + 1]; }
                    if (mode & 1) { v0 = fmaxf(v0, 0.f); v1 = fmaxf(v1, 0.f); }
                    uint32_t hi = bfpair(v0, v1);
                    uint32_t lo = bflo(v0, v1, hi);
                    int wb = (nt * 8 + ql * 2) * 2;
                    *(uint32_t*)(rp + wb) = hi;
                    *(uint32_t*)(rp + wb + 64) = lo;
                }
            }
        }
    } else {
        float* Cf = (float*)Cb;
#pragma unroll
        for (int mt = 0; mt < 2; mt++) {
#pragma unroll
            for (int half = 0; half < 2; half++) {
                long row = r0 + mt * 16 + half * 8;
#pragma unroll
                for (int nt = 0; nt < 4; nt++) {
                    float v0 = acc[mt][nt][half * 2 + 0] * scale;
                    float v1 = acc[mt][nt][half * 2 + 1] * scale;
                    int col = n0 + wn * 32 + nt * 8 + ql * 2;
                    if (bias) { v0 += bias[col]; v1 += bias[col + 1]; }
                    if (mode & 1) { v0 = fmaxf(v0, 0.f); v1 = fmaxf(v1, 0.f); }
                    *(float2*)(Cf + row * (long)ldc + col) = make_float2(v0, v1);
                }
            }
        }
    }
}

// ---------------------------------------------------------------------------
// Pack fp32 [rows][K] -> packed hi|lo
// ---------------------------------------------------------------------------
__global__ __launch_bounds__(256) void k_pack(const float* __restrict__ src,
                                              char* __restrict__ dst, int K) {
    long j0 = ((long)blockIdx.x * 256 + threadIdx.x) * 8;
    float4 f0 = *(const float4*)(src + j0);
    float4 f1 = *(const float4*)(src + j0 + 4);
    long row = j0 / K;
    int k0 = (int)(j0 - row * K);
    uint32_t h0 = bfpair(f0.x, f0.y), h1 = bfpair(f0.z, f0.w);
    uint32_t h2 = bfpair(f1.x, f1.y), h3 = bfpair(f1.z, f1.w);
    uint32_t l0 = bflo(f0.x, f0.y, h0), l1 = bflo(f0.z, f0.w, h1);
    uint32_t l2 = bflo(f1.x, f1.y, h2), l3 = bflo(f1.z, f1.w, h3);
    char* p = dst + row * (long)K * 4 + (k0 >> 5) * 128 + (k0 & 31) * 2;
    *(uint4*)p = make_uint4(h0, h1, h2, h3);
    *(uint4*)(p + 64) = make_uint4(l0, l1, l2, l3);
}

// ---------------------------------------------------------------------------
// Transpose + pack: in fp32 [R][C] -> packed rows=C, K=R
// ---------------------------------------------------------------------------
__global__ __launch_bounds__(256) void k_transpack(const float* __restrict__ in,
                                                   char* __restrict__ out,
                                                   int R, int C,
                                                   long inPlane, long outPlaneBytes) {
    in  += (long)blockIdx.z * inPlane;
    out += (long)blockIdx.z * outPlaneBytes;
    int c0 = blockIdx.x * 32, r0 = blockIdx.y * 32;
    __shared__ float t[32][33];
    int tx = threadIdx.x & 31, ty = threadIdx.x >> 5;
#pragma unroll
    for (int i = ty; i < 32; i += 8)
        t[i][tx] = in[(long)(r0 + i) * C + c0 + tx];
    __syncthreads();
    int i = threadIdx.x >> 3;
    int g = (threadIdx.x & 7) * 4;
    float v0 = t[g + 0][i], v1 = t[g + 1][i], v2 = t[g + 2][i], v3 = t[g + 3][i];
    uint32_t h0 = bfpair(v0, v1), h1 = bfpair(v2, v3);
    uint32_t l0 = bflo(v0, v1, h0), l1 = bflo(v2, v3, h1);
    char* p = out + (long)(c0 + i) * ((long)R * 4) + (r0 >> 5) * 128 + g * 2;
    *(uint2*)p = make_uint2(h0, h1);
    *(uint2*)(p + 64) = make_uint2(l0, l1);
}

// ---------------------------------------------------------------------------
// Causal softmax: fp32 scores row -> packed probs row
// ---------------------------------------------------------------------------
__global__ __launch_bounds__(256) void k_softmax() {
    long rowi = blockIdx.x;
    const float* p = g_scores + rowi * SEQ;
    char* dst = g_ppk + rowi * (SEQ * 4);
    int cnt = (int)(rowi & (SEQ - 1)) + 1;
    int tid = threadIdx.x;
    int j0 = tid * 8;
    __shared__ float red[256];

    float v[8];
    float4 f0 = *(const float4*)(p + j0);
    float4 f1 = *(const float4*)(p + j0 + 4);
    v[0]=f0.x; v[1]=f0.y; v[2]=f0.z; v[3]=f0.w;
    v[4]=f1.x; v[5]=f1.y; v[6]=f1.z; v[7]=f1.w;
    float m = -3.4e38f;
#pragma unroll
    for (int i = 0; i < 8; i++) {
        if (j0 + i >= cnt) v[i] = -3.4e38f;
        m = fmaxf(m, v[i]);
    }
    red[tid] = m;
    __syncthreads();
    for (int s = 128; s > 0; s >>= 1) {
        if (tid < s) red[tid] = fmaxf(red[tid], red[tid + s]);
        __syncthreads();
    }
    m = red[0];
    __syncthreads();
    float sum = 0.f;
#pragma unroll
    for (int i = 0; i < 8; i++) {
        v[i] = (j0 + i < cnt) ? __expf(v[i] - m) : 0.f;
        sum += v[i];
    }
    red[tid] = sum;
    __syncthreads();
    for (int s = 128; s > 0; s >>= 1) {
        if (tid < s) red[tid] += red[tid + s];
        __syncthreads();
    }
    float inv = 1.0f / red[0];
#pragma unroll
    for (int i = 0; i < 8; i++) v[i] *= inv;

    uint32_t h0 = bfpair(v[0], v[1]), h1 = bfpair(v[2], v[3]);
    uint32_t h2 = bfpair(v[4], v[5]), h3 = bfpair(v[6], v[7]);
    uint32_t l0 = bflo(v[0], v[1], h0), l1 = bflo(v[2], v[3], h1);
    uint32_t l2 = bflo(v[4], v[5], h2), l3 = bflo(v[6], v[7], h3);
    char* q = dst + (tid >> 2) * 128 + (tid & 3) * 16;
    *(uint4*)q = make_uint4(h0, h1, h2, h3);
    *(uint4*)(q + 64) = make_uint4(l0, l1, l2, l3);
}

// ---------------------------------------------------------------------------
// Launch
// ---------------------------------------------------------------------------
extern "C" void kernel_launch(void* const* d_in, const int* in_sizes, int n_in,
                              void* d_out, int out_size) {
    const float* x  = (const float*)d_in[0];
    const float* Wq = (const float*)d_in[1];
    const float* Wk = (const float*)d_in[2];
    const float* Wv = (const float*)d_in[3];
    const float* W1 = (const float*)d_in[4];
    const float* b1 = (const float*)d_in[5];
    const float* W2 = (const float*)d_in[6];
    const float* b2 = (const float*)d_in[7];
    float* out = (float*)d_out;

    cudaFuncSetAttribute(gemm_mma, cudaFuncAttributeMaxDynamicSharedMemorySize, GEMM_SMEM);

    void* p;
    cudaGetSymbolAddress(&p, g_xpk);   char* xpk  = (char*)p;
    cudaGetSymbolAddress(&p, g_wpk);   char* wpk  = (char*)p;
    cudaGetSymbolAddress(&p, g_w1pk);  char* w1pk = (char*)p;
    cudaGetSymbolAddress(&p, g_w2pk);  char* w2pk = (char*)p;
    cudaGetSymbolAddress(&p, g_qkpk);  char* qkpk = (char*)p;
    cudaGetSymbolAddress(&p, g_v);     float* v   = (float*)p;
    cudaGetSymbolAddress(&p, g_vtpk);  char* vtpk = (char*)p;
    cudaGetSymbolAddress(&p, g_scores);float* sc  = (float*)p;
    cudaGetSymbolAddress(&p, g_ppk);   char* ppk  = (char*)p;
    cudaGetSymbolAddress(&p, g_apk);   char* apk  = (char*)p;
    cudaGetSymbolAddress(&p, g_hpk);   char* hpk  = (char*)p;

    const long WPL = (long)DIM * DIM * 4;

    k_pack<<<dim3((MTOT * DIM) / (8 * 256)), 256>>>(x, xpk, DIM);
    k_transpack<<<dim3(32, 32, 1), 256>>>(Wq, wpk + 0 * WPL, DIM, DIM, 0, 0);
    k_transpack<<<dim3(32, 32, 1), 256>>>(Wk, wpk + 1 * WPL, DIM, DIM, 0, 0);
    k_transpack<<<dim3(32, 32, 1), 256>>>(Wv, wpk + 2 * WPL, DIM, DIM, 0, 0);
    k_transpack<<<dim3(32, 64, 1), 256>>>(W1, w1pk, 2 * DIM, DIM, 0, 0);
    k_transpack<<<dim3(32, 32, 1), 256>>>(W2, w2pk, DIM, DIM, 0, 0);

    // q,k = x @ Wq/Wk (packed out)
    gemm_mma<<<dim3(16, 64, 2), 256, GEMM_SMEM>>>(
        xpk, wpk, DIM * 4, DIM * 4, 0, WPL, 32,
        0, 0, 0, 0, 0,
        qkpk, (long)MTOT * DIM * 4, 0, DIM * 4,
        1.0f, 0, 8);
    // v = x @ Wv (fp32 out)
    gemm_mma<<<dim3(16, 64, 1), 256, GEMM_SMEM>>>(
        xpk, wpk + 2 * WPL, DIM * 4, DIM * 4, 0, 0, 32,
        0, 0, 0, 0, 0,
        v, 0, DIM, 0,
        1.0f, 0, 0);
    // vT packed per batch
    k_transpack<<<dim3(32, 64, BSZ), 256>>>(v, vtpk, SEQ, DIM,
                                            (long)SEQ * DIM, (long)DIM * SEQ * 4);
    // scores = q k^T / 32 (fp32 out, causal block skip)
    gemm_mma<<<dim3(32, 16, BSZ), 256, GEMM_SMEM>>>(
        qkpk, qkpk + (long)MTOT * DIM * 4,
        DIM * 4, DIM * 4, (long)SEQ * DIM * 4, (long)SEQ * DIM * 4, 32,
        0, 0, 0, 0, 0,
        sc, (long)SEQ * SEQ * 4, SEQ, 0,
        0.03125f, 0, 2);
    k_softmax<<<dim3(BSZ * SEQ), 256>>>();
    // attn = probs @ v (causal k-limit; packed out)
    gemm_mma<<<dim3(16, 16, BSZ), 256, GEMM_SMEM>>>(
        ppk, vtpk, SEQ * 4, SEQ * 4, (long)SEQ * SEQ * 4, (long)DIM * SEQ * 4, 64,
        0, 0, 0, 0, 0,
        apk, (long)SEQ * DIM * 4, 0, DIM * 4,
        1.0f, 0, 4 | 8);
    // h = relu([attn|x] @ W1 + b1)
    gemm_mma<<<dim3(16, 64, 1), 256, GEMM_SMEM>>>(
        apk, w1pk, DIM * 4, 2 * DIM * 4, 0, 0, 32,
        xpk, w1pk + DIM * 4, DIM * 4, 2 * DIM * 4, 32,
        hpk, 0, 0, DIM * 4,
        1.0f, b1, 1 | 8);
    // out = h @ W2 + b2
    gemm_mma<<<dim3(16, 64, 1), 256, GEMM_SMEM>>>(
        hpk, w2pk, DIM * 4, DIM * 4, 0, 0, 32,
        0, 0, 0, 0, 0,
        out, 0, DIM, 0,
        1.0f, b2, 0);
}

// round 8
// speedup vs baseline: 1.4901x; 1.2567x over previous
#include <cuda_runtime.h>
#include <cuda_fp16.h>
#include <cstdint>

#define BSZ 4
#define SEQ 2048
#define DIM 1024
#define MTOT (BSZ*SEQ)

// ---------------------------------------------------------------------------
// Packed layout: per row of K floats, K/32 chunks of 128B:
//   [64B: 32 fp16 hi][64B: 32 fp16 lo = v - fp16(v)]
// Row byte stride = K*4.
// ---------------------------------------------------------------------------
__device__ __align__(128) char g_xpk   [(size_t)MTOT * DIM * 4];
__device__ __align__(128) char g_wpk   [(size_t)3 * DIM * DIM * 4];
__device__ __align__(128) char g_w1pk  [(size_t)DIM * 2 * DIM * 4];
__device__ __align__(128) char g_w2pk  [(size_t)DIM * DIM * 4];
__device__ __align__(128) char g_qkpk  [(size_t)2 * MTOT * DIM * 4];
__device__ __align__(128) float g_v    [(size_t)MTOT * DIM];
__device__ __align__(128) char g_vtpk  [(size_t)BSZ * DIM * SEQ * 4];
__device__ __align__(128) float g_scores[(size_t)BSZ * SEQ * SEQ];
__device__ __align__(128) char g_ppk   [(size_t)BSZ * SEQ * SEQ * 4];
__device__ __align__(128) char g_apk   [(size_t)MTOT * DIM * 4];
__device__ __align__(128) char g_hpk   [(size_t)MTOT * DIM * 4];

// ---------------------------------------------------------------------------
// Helpers
// ---------------------------------------------------------------------------
__device__ __forceinline__ uint32_t smem_u32(const void* p) {
    uint32_t a;
    asm("{ .reg .u64 t; cvta.to.shared.u64 t, %1; cvt.u32.u64 %0, t; }" : "=r"(a) : "l"(p));
    return a;
}
__device__ __forceinline__ uint32_t swz(uint32_t x) { return x ^ ((x >> 3) & 0x70); }

__device__ __forceinline__ uint32_t f16pair(float v0, float v1) {
    uint32_t r;   // low16 = fp16(v0), high16 = fp16(v1)
    asm("cvt.rn.f16x2.f32 %0, %1, %2;" : "=r"(r) : "f"(v1), "f"(v0));
    return r;
}
__device__ __forceinline__ uint32_t f16lo(float v0, float v1, uint32_t hi) {
    __half2 h = *reinterpret_cast<__half2*>(&hi);
    return f16pair(v0 - __half2float(__low2half(h)),
                   v1 - __half2float(__high2half(h)));
}
__device__ __forceinline__ void ldsm4(uint32_t* r, uint32_t addr) {
    asm volatile("ldmatrix.sync.aligned.m8n8.x4.shared.b16 {%0,%1,%2,%3}, [%4];"
                 : "=r"(r[0]), "=r"(r[1]), "=r"(r[2]), "=r"(r[3]) : "r"(addr));
}
__device__ __forceinline__ void mma_f16(float* d, const uint32_t* a, const uint32_t* b) {
    asm volatile(
        "mma.sync.aligned.m16n8k16.row.col.f32.f16.f16.f32 "
        "{%0,%1,%2,%3}, {%4,%5,%6,%7}, {%8,%9}, {%0,%1,%2,%3};"
        : "+f"(d[0]), "+f"(d[1]), "+f"(d[2]), "+f"(d[3])
        : "r"(a[0]), "r"(a[1]), "r"(a[2]), "r"(a[3]), "r"(b[0]), "r"(b[1]));
}

// ---------------------------------------------------------------------------
// Generic NT GEMM on packed operands, 128(M)x64(N) tile, 8 warps (32x32 each).
// 3-stage cp.async pipeline, 1 sync/chunk.
// FULL=0: acc += Ah*Bh + Al*Bh                  (A-split only; B fp16-rounded)
// FULL=1: acc += Ah*Bh + Al*Bh + Ah*Bl          (both split; for softmax input)
// mode: 1=relu, 2=causal block skip, 4=causal k-limit, 8=packed output
// ---------------------------------------------------------------------------
#define TA_BYTES 16384
#define STG 24576
#define GEMM_SMEM (3 * STG)

template <int FULL>
__global__ __launch_bounds__(256, 3) void gemm_mma(
    const char* __restrict__ Ap, const char* __restrict__ Bp,
    long aRB, long bRB, long zsA, long zsB, int kc1,
    const char* __restrict__ Ap2, const char* __restrict__ Bp2,
    long aRB2, long bRB2, int kc2,
    void* Cout, long zsC, int ldc, long cRB,
    float scale, const float* __restrict__ bias, int mode)
{
    int m0 = blockIdx.y * 128, n0 = blockIdx.x * 64;
    if ((mode & 2) && n0 >= m0 + 128) return;
    if (mode & 4) { int ke = (m0 + 128) >> 5; if (ke < kc1) kc1 = ke; }
    int z = blockIdx.z;
    Ap += (long)z * zsA;
    Bp += (long)z * zsB;
    char* Cb = (char*)Cout + (long)z * zsC;

    extern __shared__ char smem[];
    uint32_t sb = smem_u32(smem);
    int tid = threadIdx.x;
    int nch = kc1 + kc2;

    auto issue = [&](int c) {
        uint32_t stg = sb + (uint32_t)(c % 3) * STG;
        int cc = c;
        const char* pa; const char* pb; long ra, rb;
        if (c < kc1) { pa = Ap;  pb = Bp;  ra = aRB;  rb = bRB; }
        else         { pa = Ap2; pb = Bp2; ra = aRB2; rb = bRB2; cc = c - kc1; }
        long cOff = (long)cc * 128;
#pragma unroll
        for (int j = 0; j < 6; j++) {
            int slot = tid + j * 256;
            bool isA = slot < 1024;
            int local = isA ? slot : slot - 1024;
            int row = local >> 3, seg = local & 7;
            const char* g = (isA ? pa + (long)(m0 + row) * ra
                                 : pb + (long)(n0 + row) * rb) + cOff + seg * 16;
            uint32_t d = stg + (isA ? 0u : (uint32_t)TA_BYTES)
                             + swz((uint32_t)(row * 128 + seg * 16));
            asm volatile("cp.async.cg.shared.global [%0], [%1], 16;" :: "r"(d), "l"(g));
        }
        asm volatile("cp.async.commit_group;" ::: "memory");
    };

    int wid = tid >> 5, lane = tid & 31;
    int wm = wid >> 1, wn = wid & 1;   // 4 (m) x 2 (n) warps
    float acc[2][4][4] = {};

    issue(0);
    if (nch > 1) issue(1);
    else asm volatile("cp.async.commit_group;" ::: "memory");

    uint32_t aRowLoc = (uint32_t)((wm * 32 + (lane & 15)) * 128 + ((lane >> 4) << 4));
    int bg = lane >> 3;
    uint32_t bRowLoc = (uint32_t)((wn * 32 + (lane & 7) + ((bg >> 1) << 3)) * 128 + ((bg & 1) << 4));

    for (int c = 0; c < nch; c++) {
        asm volatile("cp.async.wait_group 1;" ::: "memory");
        __syncthreads();
        if (c + 2 < nch) issue(c + 2);
        else asm volatile("cp.async.commit_group;" ::: "memory");

        uint32_t ta = sb + (uint32_t)(c % 3) * STG;
        uint32_t tb = ta + TA_BYTES;
#pragma unroll
        for (int s = 0; s < 2; s++) {
            int ko = s * 32;
            uint32_t Ah[2][4], Bh[2][4], X[2][4];
            // hi planes
#pragma unroll
            for (int mt = 0; mt < 2; mt++)
                ldsm4(Ah[mt], ta + swz(aRowLoc + mt * 2048 + ko));
#pragma unroll
            for (int bt = 0; bt < 2; bt++)
                ldsm4(Bh[bt], tb + swz(bRowLoc + bt * 2048 + ko));
            // Ah * Bh
#pragma unroll
            for (int mt = 0; mt < 2; mt++)
#pragma unroll
                for (int nt = 0; nt < 4; nt++)
                    mma_f16(acc[mt][nt], Ah[mt], &Bh[nt >> 1][(nt & 1) * 2]);
            // Al * Bh
#pragma unroll
            for (int mt = 0; mt < 2; mt++)
                ldsm4(X[mt], ta + swz(aRowLoc + mt * 2048 + 64 + ko));
#pragma unroll
            for (int mt = 0; mt < 2; mt++)
#pragma unroll
                for (int nt = 0; nt < 4; nt++)
                    mma_f16(acc[mt][nt], X[mt], &Bh[nt >> 1][(nt & 1) * 2]);
            if (FULL) {
                // Ah * Bl
#pragma unroll
                for (int bt = 0; bt < 2; bt++)
                    ldsm4(X[bt], tb + swz(bRowLoc + bt * 2048 + 64 + ko));
#pragma unroll
                for (int mt = 0; mt < 2; mt++)
#pragma unroll
                    for (int nt = 0; nt < 4; nt++)
                        mma_f16(acc[mt][nt], Ah[mt], &X[nt >> 1][(nt & 1) * 2]);
            }
        }
    }

    // Epilogue
    int ql = lane & 3;
    int r0 = m0 + wm * 32 + (lane >> 2);
    if (mode & 8) {
        int cw = (n0 + wn * 32) >> 5;
        char* cbase = Cb + (long)cw * 128;
#pragma unroll
        for (int mt = 0; mt < 2; mt++) {
#pragma unroll
            for (int half = 0; half < 2; half++) {
                long row = r0 + mt * 16 + half * 8;
                char* rp = cbase + row * cRB;
#pragma unroll
                for (int nt = 0; nt < 4; nt++) {
                    float v0 = acc[mt][nt][half * 2 + 0] * scale;
                    float v1 = acc[mt][nt][half * 2 + 1] * scale;
                    int col = n0 + wn * 32 + nt * 8 + ql * 2;
                    if (bias) { v0 += bias[col]; v1 += bias[col + 1]; }
                    if (mode & 1) { v0 = fmaxf(v0, 0.f); v1 = fmaxf(v1, 0.f); }
                    uint32_t hi = f16pair(v0, v1);
                    uint32_t lo = f16lo(v0, v1, hi);
                    int wb = (nt * 8 + ql * 2) * 2;
                    *(uint32_t*)(rp + wb) = hi;
                    *(uint32_t*)(rp + wb + 64) = lo;
                }
            }
        }
    } else {
        float* Cf = (float*)Cb;
#pragma unroll
        for (int mt = 0; mt < 2; mt++) {
#pragma unroll
            for (int half = 0; half < 2; half++) {
                long row = r0 + mt * 16 + half * 8;
#pragma unroll
                for (int nt = 0; nt < 4; nt++) {
                    float v0 = acc[mt][nt][half * 2 + 0] * scale;
                    float v1 = acc[mt][nt][half * 2 + 1] * scale;
                    int col = n0 + wn * 32 + nt * 8 + ql * 2;
                    if (bias) { v0 += bias[col]; v1 += bias[col + 1]; }
                    if (mode & 1) { v0 = fmaxf(v0, 0.f); v1 = fmaxf(v1, 0.f); }
                    *(float2*)(Cf + row * (long)ldc + col) = make_float2(v0, v1);
                }
            }
        }
    }
}

// ---------------------------------------------------------------------------
// Pack fp32 [rows][K] -> packed hi|lo
// ---------------------------------------------------------------------------
__global__ __launch_bounds__(256) void k_pack(const float* __restrict__ src,
                                              char* __restrict__ dst, int K) {
    long j0 = ((long)blockIdx.x * 256 + threadIdx.x) * 8;
    float4 f0 = *(const float4*)(src + j0);
    float4 f1 = *(const float4*)(src + j0 + 4);
    long row = j0 / K;
    int k0 = (int)(j0 - row * K);
    uint32_t h0 = f16pair(f0.x, f0.y), h1 = f16pair(f0.z, f0.w);
    uint32_t h2 = f16pair(f1.x, f1.y), h3 = f16pair(f1.z, f1.w);
    uint32_t l0 = f16lo(f0.x, f0.y, h0), l1 = f16lo(f0.z, f0.w, h1);
    uint32_t l2 = f16lo(f1.x, f1.y, h2), l3 = f16lo(f1.z, f1.w, h3);
    char* p = dst + row * (long)K * 4 + (k0 >> 5) * 128 + (k0 & 31) * 2;
    *(uint4*)p = make_uint4(h0, h1, h2, h3);
    *(uint4*)(p + 64) = make_uint4(l0, l1, l2, l3);
}

// ---------------------------------------------------------------------------
// Transpose + pack: in fp32 [R][C] -> packed rows=C, K=R
// ---------------------------------------------------------------------------
__global__ __launch_bounds__(256) void k_transpack(const float* __restrict__ in,
                                                   char* __restrict__ out,
                                                   int R, int C,
                                                   long inPlane, long outPlaneBytes) {
    in  += (long)blockIdx.z * inPlane;
    out += (long)blockIdx.z * outPlaneBytes;
    int c0 = blockIdx.x * 32, r0 = blockIdx.y * 32;
    __shared__ float t[32][33];
    int tx = threadIdx.x & 31, ty = threadIdx.x >> 5;
#pragma unroll
    for (int i = ty; i < 32; i += 8)
        t[i][tx] = in[(long)(r0 + i) * C + c0 + tx];
    __syncthreads();
    int i = threadIdx.x >> 3;
    int g = (threadIdx.x & 7) * 4;
    float v0 = t[g + 0][i], v1 = t[g + 1][i], v2 = t[g + 2][i], v3 = t[g + 3][i];
    uint32_t h0 = f16pair(v0, v1), h1 = f16pair(v2, v3);
    uint32_t l0 = f16lo(v0, v1, h0), l1 = f16lo(v2, v3, h1);
    char* p = out + (long)(c0 + i) * ((long)R * 4) + (r0 >> 5) * 128 + g * 2;
    *(uint2*)p = make_uint2(h0, h1);
    *(uint2*)(p + 64) = make_uint2(l0, l1);
}

// ---------------------------------------------------------------------------
// Causal softmax: fp32 scores row -> packed probs row
// ---------------------------------------------------------------------------
__global__ __launch_bounds__(256) void k_softmax() {
    long rowi = blockIdx.x;
    const float* p = g_scores + rowi * SEQ;
    char* dst = g_ppk + rowi * (SEQ * 4);
    int cnt = (int)(rowi & (SEQ - 1)) + 1;
    int tid = threadIdx.x;
    int j0 = tid * 8;
    __shared__ float red[256];

    float v[8];
    float4 f0 = *(const float4*)(p + j0);
    float4 f1 = *(const float4*)(p + j0 + 4);
    v[0]=f0.x; v[1]=f0.y; v[2]=f0.z; v[3]=f0.w;
    v[4]=f1.x; v[5]=f1.y; v[6]=f1.z; v[7]=f1.w;
    float m = -3.4e38f;
#pragma unroll
    for (int i = 0; i < 8; i++) {
        if (j0 + i >= cnt) v[i] = -3.4e38f;
        m = fmaxf(m, v[i]);
    }
    red[tid] = m;
    __syncthreads();
    for (int s = 128; s > 0; s >>= 1) {
        if (tid < s) red[tid] = fmaxf(red[tid], red[tid + s]);
        __syncthreads();
    }
    m = red[0];
    __syncthreads();
    float sum = 0.f;
#pragma unroll
    for (int i = 0; i < 8; i++) {
        v[i] = (j0 + i < cnt) ? __expf(v[i] - m) : 0.f;
        sum += v[i];
    }
    red[tid] = sum;
    __syncthreads();
    for (int s = 128; s > 0; s >>= 1) {
        if (tid < s) red[tid] += red[tid + s];
        __syncthreads();
    }
    float inv = 1.0f / red[0];
#pragma unroll
    for (int i = 0; i < 8; i++) v[i] *= inv;

    uint32_t h0 = f16pair(v[0], v[1]), h1 = f16pair(v[2], v[3]);
    uint32_t h2 = f16pair(v[4], v[5]), h3 = f16pair(v[6], v[7]);
    uint32_t l0 = f16lo(v[0], v[1], h0), l1 = f16lo(v[2], v[3], h1);
    uint32_t l2 = f16lo(v[4], v[5], h2), l3 = f16lo(v[6], v[7], h3);
    char* q = dst + (tid >> 2) * 128 + (tid & 3) * 16;
    *(uint4*)q = make_uint4(h0, h1, h2, h3);
    *(uint4*)(q + 64) = make_uint4(l0, l1, l2, l3);
}

// ---------------------------------------------------------------------------
// Launch
// ---------------------------------------------------------------------------
extern "C" void kernel_launch(void* const* d_in, const int* in_sizes, int n_in,
                              void* d_out, int out_size) {
    const float* x  = (const float*)d_in[0];
    const float* Wq = (const float*)d_in[1];
    const float* Wk = (const float*)d_in[2];
    const float* Wv = (const float*)d_in[3];
    const float* W1 = (const float*)d_in[4];
    const float* b1 = (const float*)d_in[5];
    const float* W2 = (const float*)d_in[6];
    const float* b2 = (const float*)d_in[7];
    float* out = (float*)d_out;

    cudaFuncSetAttribute(gemm_mma<0>, cudaFuncAttributeMaxDynamicSharedMemorySize, GEMM_SMEM);
    cudaFuncSetAttribute(gemm_mma<1>, cudaFuncAttributeMaxDynamicSharedMemorySize, GEMM_SMEM);

    void* p;
    cudaGetSymbolAddress(&p, g_xpk);   char* xpk  = (char*)p;
    cudaGetSymbolAddress(&p, g_wpk);   char* wpk  = (char*)p;
    cudaGetSymbolAddress(&p, g_w1pk);  char* w1pk = (char*)p;
    cudaGetSymbolAddress(&p, g_w2pk);  char* w2pk = (char*)p;
    cudaGetSymbolAddress(&p, g_qkpk);  char* qkpk = (char*)p;
    cudaGetSymbolAddress(&p, g_v);     float* v   = (float*)p;
    cudaGetSymbolAddress(&p, g_vtpk);  char* vtpk = (char*)p;
    cudaGetSymbolAddress(&p, g_scores);float* sc  = (float*)p;
    cudaGetSymbolAddress(&p, g_ppk);   char* ppk  = (char*)p;
    cudaGetSymbolAddress(&p, g_apk);   char* apk  = (char*)p;
    cudaGetSymbolAddress(&p, g_hpk);   char* hpk  = (char*)p;

    const long WPL = (long)DIM * DIM * 4;

    k_pack<<<dim3((MTOT * DIM) / (8 * 256)), 256>>>(x, xpk, DIM);
    k_transpack<<<dim3(32, 32, 1), 256>>>(Wq, wpk + 0 * WPL, DIM, DIM, 0, 0);
    k_transpack<<<dim3(32, 32, 1), 256>>>(Wk, wpk + 1 * WPL, DIM, DIM, 0, 0);
    k_transpack<<<dim3(32, 32, 1), 256>>>(Wv, wpk + 2 * WPL, DIM, DIM, 0, 0);
    k_transpack<<<dim3(32, 64, 1), 256>>>(W1, w1pk, 2 * DIM, DIM, 0, 0);
    k_transpack<<<dim3(32, 32, 1), 256>>>(W2, w2pk, DIM, DIM, 0, 0);

    // q,k = x @ Wq/Wk (packed out; A=x split, W fp16-rounded)
    gemm_mma<0><<<dim3(16, 64, 2), 256, GEMM_SMEM>>>(
        xpk, wpk, DIM * 4, DIM * 4, 0, WPL, 32,
        0, 0, 0, 0, 0,
        qkpk, (long)MTOT * DIM * 4, 0, DIM * 4,
        1.0f, 0, 8);
    // v = x @ Wv (fp32 out)
    gemm_mma<0><<<dim3(16, 64, 1), 256, GEMM_SMEM>>>(
        xpk, wpk + 2 * WPL, DIM * 4, DIM * 4, 0, 0, 32,
        0, 0, 0, 0, 0,
        v, 0, DIM, 0,
        1.0f, 0, 0);
    // vT packed per batch
    k_transpack<<<dim3(32, 64, BSZ), 256>>>(v, vtpk, SEQ, DIM,
                                            (long)SEQ * DIM, (long)DIM * SEQ * 4);
    // scores = q k^T / 32 (FULL split: feeds softmax; fp32 out, causal skip)
    gemm_mma<1><<<dim3(32, 16, BSZ), 256, GEMM_SMEM>>>(
        qkpk, qkpk + (long)MTOT * DIM * 4,
        DIM * 4, DIM * 4, (long)SEQ * DIM * 4, (long)SEQ * DIM * 4, 32,
        0, 0, 0, 0, 0,
        sc, (long)SEQ * SEQ * 4, SEQ, 0,
        0.03125f, 0, 2);
    k_softmax<<<dim3(BSZ * SEQ), 256>>>();
    // attn = probs @ v (A=probs split; causal k-limit; packed out)
    gemm_mma<0><<<dim3(16, 16, BSZ), 256, GEMM_SMEM>>>(
        ppk, vtpk, SEQ * 4, SEQ * 4, (long)SEQ * SEQ * 4, (long)DIM * SEQ * 4, 64,
        0, 0, 0, 0, 0,
        apk, (long)SEQ * DIM * 4, 0, DIM * 4,
        1.0f, 0, 4 | 8);
    // h = relu([attn|x] @ W1 + b1)
    gemm_mma<0><<<dim3(16, 64, 1), 256, GEMM_SMEM>>>(
        apk, w1pk, DIM * 4, 2 * DIM * 4, 0, 0, 32,
        xpk, w1pk + DIM * 4, DIM * 4, 2 * DIM * 4, 32,
        hpk, 0, 0, DIM * 4,
        1.0f, b1, 1 | 8);
    // out = h @ W2 + b2
    gemm_mma<0><<<dim3(16, 64, 1), 256, GEMM_SMEM>>>(
        hpk, w2pk, DIM * 4, DIM * 4, 0, 0, 32,
        0, 0, 0, 0, 0,
        out, 0, DIM, 0,
        1.0f, b2, 0);
}

// round 9
// speedup vs baseline: 1.8198x; 1.2213x over previous
#include <cuda_runtime.h>
#include <cuda_fp16.h>
#include <cstdint>

#define BSZ 4
#define SEQ 2048
#define DIM 1024
#define MTOT (BSZ*SEQ)

// ---------------------------------------------------------------------------
// Packed layout: per row of K floats, K/32 chunks of 128B:
//   [64B: 32 fp16 hi][64B: 32 fp16 lo = v - fp16(v)]
// Row byte stride = K*4.
// ---------------------------------------------------------------------------
__device__ __align__(128) char g_xpk   [(size_t)MTOT * DIM * 4];
__device__ __align__(128) char g_wpk   [(size_t)3 * DIM * DIM * 4];
__device__ __align__(128) char g_w1pk  [(size_t)DIM * 2 * DIM * 4];
__device__ __align__(128) char g_w2pk  [(size_t)DIM * DIM * 4];
__device__ __align__(128) char g_qkpk  [(size_t)2 * MTOT * DIM * 4];
__device__ __align__(128) float g_v    [(size_t)MTOT * DIM];
__device__ __align__(128) char g_vtpk  [(size_t)BSZ * DIM * SEQ * 4];
__device__ __align__(128) float g_scores[(size_t)BSZ * SEQ * SEQ];
__device__ __align__(128) char g_ppk   [(size_t)BSZ * SEQ * SEQ * 4];
__device__ __align__(128) char g_apk   [(size_t)MTOT * DIM * 4];
__device__ __align__(128) char g_hpk   [(size_t)MTOT * DIM * 4];

// ---------------------------------------------------------------------------
// Helpers
// ---------------------------------------------------------------------------
__device__ __forceinline__ uint32_t smem_u32(const void* p) {
    uint32_t a;
    asm("{ .reg .u64 t; cvta.to.shared.u64 t, %1; cvt.u32.u64 %0, t; }" : "=r"(a) : "l"(p));
    return a;
}
__device__ __forceinline__ uint32_t swz(uint32_t x) { return x ^ ((x >> 3) & 0x70); }

__device__ __forceinline__ uint32_t f16pair(float v0, float v1) {
    uint32_t r;   // low16 = fp16(v0), high16 = fp16(v1)
    asm("cvt.rn.f16x2.f32 %0, %1, %2;" : "=r"(r) : "f"(v1), "f"(v0));
    return r;
}
__device__ __forceinline__ uint32_t f16lo(float v0, float v1, uint32_t hi) {
    __half2 h = *reinterpret_cast<__half2*>(&hi);
    return f16pair(v0 - __half2float(__low2half(h)),
                   v1 - __half2float(__high2half(h)));
}
__device__ __forceinline__ void ldsm4(uint32_t* r, uint32_t addr) {
    asm volatile("ldmatrix.sync.aligned.m8n8.x4.shared.b16 {%0,%1,%2,%3}, [%4];"
                 : "=r"(r[0]), "=r"(r[1]), "=r"(r[2]), "=r"(r[3]) : "r"(addr));
}
__device__ __forceinline__ void mma_f16(float* d, const uint32_t* a, const uint32_t* b) {
    asm volatile(
        "mma.sync.aligned.m16n8k16.row.col.f32.f16.f16.f32 "
        "{%0,%1,%2,%3}, {%4,%5,%6,%7}, {%8,%9}, {%0,%1,%2,%3};"
        : "+f"(d[0]), "+f"(d[1]), "+f"(d[2]), "+f"(d[3])
        : "r"(a[0]), "r"(a[1]), "r"(a[2]), "r"(a[3]), "r"(b[0]), "r"(b[1]));
}

// ---------------------------------------------------------------------------
// Generic NT GEMM on packed operands, 128(M)x64(N) tile, 8 warps (32x32 each).
// 3-stage cp.async pipeline, 1 sync/chunk.
// PASSES=1: acc += Ah*Bh                       (pure fp16)
// PASSES=2: acc += Ah*Bh + Al*Bh               (A split; B fp16-rounded)
// PASSES=3: acc += Ah*Bh + Ah*Bl + Al*Bh       (both split; softmax input)
// mode: 1=relu, 2=causal block skip, 4=causal k-limit, 8=packed output
// ---------------------------------------------------------------------------
#define TA_BYTES 16384
#define STG 24576
#define GEMM_SMEM (3 * STG)

template <int PASSES>
__global__ __launch_bounds__(256, 3) void gemm_mma(
    const char* __restrict__ Ap, const char* __restrict__ Bp,
    long aRB, long bRB, long zsA, long zsB, int kc1,
    const char* __restrict__ Ap2, const char* __restrict__ Bp2,
    long aRB2, long bRB2, int kc2,
    void* Cout, long zsC, int ldc, long cRB,
    float scale, const float* __restrict__ bias, int mode)
{
    int m0 = blockIdx.y * 128, n0 = blockIdx.x * 64;
    if ((mode & 2) && n0 >= m0 + 128) return;
    if (mode & 4) { int ke = (m0 + 128) >> 5; if (ke < kc1) kc1 = ke; }
    int z = blockIdx.z;
    Ap += (long)z * zsA;
    Bp += (long)z * zsB;
    char* Cb = (char*)Cout + (long)z * zsC;

    extern __shared__ char smem[];
    uint32_t sb = smem_u32(smem);
    int tid = threadIdx.x;
    int nch = kc1 + kc2;

    auto issue = [&](int c) {
        uint32_t stg = sb + (uint32_t)(c % 3) * STG;
        int cc = c;
        const char* pa; const char* pb; long ra, rb;
        if (c < kc1) { pa = Ap;  pb = Bp;  ra = aRB;  rb = bRB; }
        else         { pa = Ap2; pb = Bp2; ra = aRB2; rb = bRB2; cc = c - kc1; }
        long cOff = (long)cc * 128;
#pragma unroll
        for (int j = 0; j < 6; j++) {
            int slot = tid + j * 256;
            bool isA = slot < 1024;
            int local = isA ? slot : slot - 1024;
            int row = local >> 3, seg = local & 7;
            const char* g = (isA ? pa + (long)(m0 + row) * ra
                                 : pb + (long)(n0 + row) * rb) + cOff + seg * 16;
            uint32_t d = stg + (isA ? 0u : (uint32_t)TA_BYTES)
                             + swz((uint32_t)(row * 128 + seg * 16));
            asm volatile("cp.async.cg.shared.global [%0], [%1], 16;" :: "r"(d), "l"(g));
        }
        asm volatile("cp.async.commit_group;" ::: "memory");
    };

    int wid = tid >> 5, lane = tid & 31;
    int wm = wid >> 1, wn = wid & 1;   // 4 (m) x 2 (n) warps
    float acc[2][4][4] = {};

    issue(0);
    if (nch > 1) issue(1);
    else asm volatile("cp.async.commit_group;" ::: "memory");

    uint32_t aRowLoc = (uint32_t)((wm * 32 + (lane & 15)) * 128 + ((lane >> 4) << 4));
    int bg = lane >> 3;
    uint32_t bRowLoc = (uint32_t)((wn * 32 + (lane & 7) + ((bg >> 1) << 3)) * 128 + ((bg & 1) << 4));

    for (int c = 0; c < nch; c++) {
        asm volatile("cp.async.wait_group 1;" ::: "memory");
        __syncthreads();
        if (c + 2 < nch) issue(c + 2);
        else asm volatile("cp.async.commit_group;" ::: "memory");

        uint32_t ta = sb + (uint32_t)(c % 3) * STG;
        uint32_t tb = ta + TA_BYTES;
#pragma unroll
        for (int s = 0; s < 2; s++) {
            int ko = s * 32;
            uint32_t Ah[2][4], Bh[2][4], X[2][4];
            // hi planes
#pragma unroll
            for (int mt = 0; mt < 2; mt++)
                ldsm4(Ah[mt], ta + swz(aRowLoc + mt * 2048 + ko));
#pragma unroll
            for (int bt = 0; bt < 2; bt++)
                ldsm4(Bh[bt], tb + swz(bRowLoc + bt * 2048 + ko));
            // Ah * Bh
#pragma unroll
            for (int mt = 0; mt < 2; mt++)
#pragma unroll
                for (int nt = 0; nt < 4; nt++)
                    mma_f16(acc[mt][nt], Ah[mt], &Bh[nt >> 1][(nt & 1) * 2]);
            if (PASSES >= 3) {
                // Ah * Bl
#pragma unroll
                for (int bt = 0; bt < 2; bt++)
                    ldsm4(X[bt], tb + swz(bRowLoc + bt * 2048 + 64 + ko));
#pragma unroll
                for (int mt = 0; mt < 2; mt++)
#pragma unroll
                    for (int nt = 0; nt < 4; nt++)
                        mma_f16(acc[mt][nt], Ah[mt], &X[nt >> 1][(nt & 1) * 2]);
            }
            if (PASSES >= 2) {
                // Al * Bh
#pragma unroll
                for (int mt = 0; mt < 2; mt++)
                    ldsm4(X[mt], ta + swz(aRowLoc + mt * 2048 + 64 + ko));
#pragma unroll
                for (int mt = 0; mt < 2; mt++)
#pragma unroll
                    for (int nt = 0; nt < 4; nt++)
                        mma_f16(acc[mt][nt], X[mt], &Bh[nt >> 1][(nt & 1) * 2]);
            }
        }
    }

    // Epilogue
    int ql = lane & 3;
    int r0 = m0 + wm * 32 + (lane >> 2);
    if (mode & 8) {
        int cw = (n0 + wn * 32) >> 5;
        char* cbase = Cb + (long)cw * 128;
#pragma unroll
        for (int mt = 0; mt < 2; mt++) {
#pragma unroll
            for (int half = 0; half < 2; half++) {
                long row = r0 + mt * 16 + half * 8;
                char* rp = cbase + row * cRB;
#pragma unroll
                for (int nt = 0; nt < 4; nt++) {
                    float v0 = acc[mt][nt][half * 2 + 0] * scale;
                    float v1 = acc[mt][nt][half * 2 + 1] * scale;
                    int col = n0 + wn * 32 + nt * 8 + ql * 2;
                    if (bias) { v0 += bias[col]; v1 += bias[col + 1]; }
                    if (mode & 1) { v0 = fmaxf(v0, 0.f); v1 = fmaxf(v1, 0.f); }
                    uint32_t hi = f16pair(v0, v1);
                    uint32_t lo = f16lo(v0, v1, hi);
                    int wb = (nt * 8 + ql * 2) * 2;
                    *(uint32_t*)(rp + wb) = hi;
                    *(uint32_t*)(rp + wb + 64) = lo;
                }
            }
        }
    } else {
        float* Cf = (float*)Cb;
#pragma unroll
        for (int mt = 0; mt < 2; mt++) {
#pragma unroll
            for (int half = 0; half < 2; half++) {
                long row = r0 + mt * 16 + half * 8;
#pragma unroll
                for (int nt = 0; nt < 4; nt++) {
                    float v0 = acc[mt][nt][half * 2 + 0] * scale;
                    float v1 = acc[mt][nt][half * 2 + 1] * scale;
                    int col = n0 + wn * 32 + nt * 8 + ql * 2;
                    if (bias) { v0 += bias[col]; v1 += bias[col + 1]; }
                    if (mode & 1) { v0 = fmaxf(v0, 0.f); v1 = fmaxf(v1, 0.f); }
                    *(float2*)(Cf + row * (long)ldc + col) = make_float2(v0, v1);
                }
            }
        }
    }
}

// ---------------------------------------------------------------------------
// Pack fp32 [rows][K] -> packed hi|lo
// ---------------------------------------------------------------------------
__global__ __launch_bounds__(256) void k_pack(const float* __restrict__ src,
                                              char* __restrict__ dst, int K) {
    long j0 = ((long)blockIdx.x * 256 + threadIdx.x) * 8;
    float4 f0 = *(const float4*)(src + j0);
    float4 f1 = *(const float4*)(src + j0 + 4);
    long row = j0 / K;
    int k0 = (int)(j0 - row * K);
    uint32_t h0 = f16pair(f0.x, f0.y), h1 = f16pair(f0.z, f0.w);
    uint32_t h2 = f16pair(f1.x, f1.y), h3 = f16pair(f1.z, f1.w);
    uint32_t l0 = f16lo(f0.x, f0.y, h0), l1 = f16lo(f0.z, f0.w, h1);
    uint32_t l2 = f16lo(f1.x, f1.y, h2), l3 = f16lo(f1.z, f1.w, h3);
    char* p = dst + row * (long)K * 4 + (k0 >> 5) * 128 + (k0 & 31) * 2;
    *(uint4*)p = make_uint4(h0, h1, h2, h3);
    *(uint4*)(p + 64) = make_uint4(l0, l1, l2, l3);
}

// ---------------------------------------------------------------------------
// Transpose + pack: in fp32 [R][C] -> packed rows=C, K=R
// ---------------------------------------------------------------------------
__global__ __launch_bounds__(256) void k_transpack(const float* __restrict__ in,
                                                   char* __restrict__ out,
                                                   int R, int C,
                                                   long inPlane, long outPlaneBytes) {
    in  += (long)blockIdx.z * inPlane;
    out += (long)blockIdx.z * outPlaneBytes;
    int c0 = blockIdx.x * 32, r0 = blockIdx.y * 32;
    __shared__ float t[32][33];
    int tx = threadIdx.x & 31, ty = threadIdx.x >> 5;
#pragma unroll
    for (int i = ty; i < 32; i += 8)
        t[i][tx] = in[(long)(r0 + i) * C + c0 + tx];
    __syncthreads();
    int i = threadIdx.x >> 3;
    int g = (threadIdx.x & 7) * 4;
    float v0 = t[g + 0][i], v1 = t[g + 1][i], v2 = t[g + 2][i], v3 = t[g + 3][i];
    uint32_t h0 = f16pair(v0, v1), h1 = f16pair(v2, v3);
    uint32_t l0 = f16lo(v0, v1, h0), l1 = f16lo(v2, v3, h1);
    char* p = out + (long)(c0 + i) * ((long)R * 4) + (r0 >> 5) * 128 + g * 2;
    *(uint2*)p = make_uint2(h0, h1);
    *(uint2*)(p + 64) = make_uint2(l0, l1);
}

// ---------------------------------------------------------------------------
// Causal softmax: fp32 scores row -> packed probs row
// ---------------------------------------------------------------------------
__global__ __launch_bounds__(256) void k_softmax() {
    long rowi = blockIdx.x;
    const float* p = g_scores + rowi * SEQ;
    char* dst = g_ppk + rowi * (SEQ * 4);
    int cnt = (int)(rowi & (SEQ - 1)) + 1;
    int tid = threadIdx.x;
    int j0 = tid * 8;
    __shared__ float red[256];

    float v[8];
    float4 f0 = *(const float4*)(p + j0);
    float4 f1 = *(const float4*)(p + j0 + 4);
    v[0]=f0.x; v[1]=f0.y; v[2]=f0.z; v[3]=f0.w;
    v[4]=f1.x; v[5]=f1.y; v[6]=f1.z; v[7]=f1.w;
    float m = -3.4e38f;
#pragma unroll
    for (int i = 0; i < 8; i++) {
        if (j0 + i >= cnt) v[i] = -3.4e38f;
        m = fmaxf(m, v[i]);
    }
    red[tid] = m;
    __syncthreads();
    for (int s = 128; s > 0; s >>= 1) {
        if (tid < s) red[tid] = fmaxf(red[tid], red[tid + s]);
        __syncthreads();
    }
    m = red[0];
    __syncthreads();
    float sum = 0.f;
#pragma unroll
    for (int i = 0; i < 8; i++) {
        v[i] = (j0 + i < cnt) ? __expf(v[i] - m) : 0.f;
        sum += v[i];
    }
    red[tid] = sum;
    __syncthreads();
    for (int s = 128; s > 0; s >>= 1) {
        if (tid < s) red[tid] += red[tid + s];
        __syncthreads();
    }
    float inv = 1.0f / red[0];
#pragma unroll
    for (int i = 0; i < 8; i++) v[i] *= inv;

    uint32_t h0 = f16pair(v[0], v[1]), h1 = f16pair(v[2], v[3]);
    uint32_t h2 = f16pair(v[4], v[5]), h3 = f16pair(v[6], v[7]);
    uint32_t l0 = f16lo(v[0], v[1], h0), l1 = f16lo(v[2], v[3], h1);
    uint32_t l2 = f16lo(v[4], v[5], h2), l3 = f16lo(v[6], v[7], h3);
    char* q = dst + (tid >> 2) * 128 + (tid & 3) * 16;
    *(uint4*)q = make_uint4(h0, h1, h2, h3);
    *(uint4*)(q + 64) = make_uint4(l0, l1, l2, l3);
}

// ---------------------------------------------------------------------------
// Launch
// ---------------------------------------------------------------------------
extern "C" void kernel_launch(void* const* d_in, const int* in_sizes, int n_in,
                              void* d_out, int out_size) {
    const float* x  = (const float*)d_in[0];
    const float* Wq = (const float*)d_in[1];
    const float* Wk = (const float*)d_in[2];
    const float* Wv = (const float*)d_in[3];
    const float* W1 = (const float*)d_in[4];
    const float* b1 = (const float*)d_in[5];
    const float* W2 = (const float*)d_in[6];
    const float* b2 = (const float*)d_in[7];
    float* out = (float*)d_out;

    cudaFuncSetAttribute(gemm_mma<1>, cudaFuncAttributeMaxDynamicSharedMemorySize, GEMM_SMEM);
    cudaFuncSetAttribute(gemm_mma<2>, cudaFuncAttributeMaxDynamicSharedMemorySize, GEMM_SMEM);
    cudaFuncSetAttribute(gemm_mma<3>, cudaFuncAttributeMaxDynamicSharedMemorySize, GEMM_SMEM);

    void* p;
    cudaGetSymbolAddress(&p, g_xpk);   char* xpk  = (char*)p;
    cudaGetSymbolAddress(&p, g_wpk);   char* wpk  = (char*)p;
    cudaGetSymbolAddress(&p, g_w1pk);  char* w1pk = (char*)p;
    cudaGetSymbolAddress(&p, g_w2pk);  char* w2pk = (char*)p;
    cudaGetSymbolAddress(&p, g_qkpk);  char* qkpk = (char*)p;
    cudaGetSymbolAddress(&p, g_v);     float* v   = (float*)p;
    cudaGetSymbolAddress(&p, g_vtpk);  char* vtpk = (char*)p;
    cudaGetSymbolAddress(&p, g_scores);float* sc  = (float*)p;
    cudaGetSymbolAddress(&p, g_ppk);   char* ppk  = (char*)p;
    cudaGetSymbolAddress(&p, g_apk);   char* apk  = (char*)p;
    cudaGetSymbolAddress(&p, g_hpk);   char* hpk  = (char*)p;

    const long WPL = (long)DIM * DIM * 4;

    k_pack<<<dim3((MTOT * DIM) / (8 * 256)), 256>>>(x, xpk, DIM);
    k_transpack<<<dim3(32, 32, 1), 256>>>(Wq, wpk + 0 * WPL, DIM, DIM, 0, 0);
    k_transpack<<<dim3(32, 32, 1), 256>>>(Wk, wpk + 1 * WPL, DIM, DIM, 0, 0);
    k_transpack<<<dim3(32, 32, 1), 256>>>(Wv, wpk + 2 * WPL, DIM, DIM, 0, 0);
    k_transpack<<<dim3(32, 64, 1), 256>>>(W1, w1pk, 2 * DIM, DIM, 0, 0);
    k_transpack<<<dim3(32, 32, 1), 256>>>(W2, w2pk, DIM, DIM, 0, 0);

    // q,k = x @ Wq/Wk (packed out; 2-pass: feeds softmax logits)
    gemm_mma<2><<<dim3(16, 64, 2), 256, GEMM_SMEM>>>(
        xpk, wpk, DIM * 4, DIM * 4, 0, WPL, 32,
        0, 0, 0, 0, 0,
        qkpk, (long)MTOT * DIM * 4, 0, DIM * 4,
        1.0f, 0, 8);
    // v = x @ Wv (fp32 out; 1-pass: linear path)
    gemm_mma<1><<<dim3(16, 64, 1), 256, GEMM_SMEM>>>(
        xpk, wpk + 2 * WPL, DIM * 4, DIM * 4, 0, 0, 32,
        0, 0, 0, 0, 0,
        v, 0, DIM, 0,
        1.0f, 0, 0);
    // vT packed per batch
    k_transpack<<<dim3(32, 64, BSZ), 256>>>(v, vtpk, SEQ, DIM,
                                            (long)SEQ * DIM, (long)DIM * SEQ * 4);
    // scores = q k^T / 32 (3-pass: softmax input; fp32 out, causal skip)
    gemm_mma<3><<<dim3(32, 16, BSZ), 256, GEMM_SMEM>>>(
        qkpk, qkpk + (long)MTOT * DIM * 4,
        DIM * 4, DIM * 4, (long)SEQ * DIM * 4, (long)SEQ * DIM * 4, 32,
        0, 0, 0, 0, 0,
        sc, (long)SEQ * SEQ * 4, SEQ, 0,
        0.03125f, 0, 2);
    k_softmax<<<dim3(BSZ * SEQ), 256>>>();
    // attn = probs @ v (1-pass; causal k-limit; packed out)
    gemm_mma<1><<<dim3(16, 16, BSZ), 256, GEMM_SMEM>>>(
        ppk, vtpk, SEQ * 4, SEQ * 4, (long)SEQ * SEQ * 4, (long)DIM * SEQ * 4, 64,
        0, 0, 0, 0, 0,
        apk, (long)SEQ * DIM * 4, 0, DIM * 4,
        1.0f, 0, 4 | 8);
    // h = relu([attn|x] @ W1 + b1)  (1-pass)
    gemm_mma<1><<<dim3(16, 64, 1), 256, GEMM_SMEM>>>(
        apk, w1pk, DIM * 4, 2 * DIM * 4, 0, 0, 32,
        xpk, w1pk + DIM * 4, DIM * 4, 2 * DIM * 4, 32,
        hpk, 0, 0, DIM * 4,
        1.0f, b1, 1 | 8);
    // out = h @ W2 + b2 (1-pass)
    gemm_mma<1><<<dim3(16, 64, 1), 256, GEMM_SMEM>>>(
        hpk, w2pk, DIM * 4, DIM * 4, 0, 0, 32,
        0, 0, 0, 0, 0,
        out, 0, DIM, 0,
        1.0f, b2, 0);
}

// round 10
// speedup vs baseline: 1.9757x; 1.0857x over previous
#include <cuda_runtime.h>
#include <cuda_fp16.h>
#include <cstdint>

#define BSZ 4
#define SEQ 2048
#define DIM 1024
#define MTOT (BSZ*SEQ)

// ---------------------------------------------------------------------------
// Layouts:
//  FULL packed: per row of K floats, K/32 chunks of 128B [64B hi | 64B lo],
//               row stride K*4 bytes.     (xpk, qkpk)
//  HALF packed: K/32 chunks of 64B [hi only], row stride K*2 bytes.
//               (weights, vtpk, ppk, apk, hpk)
// ---------------------------------------------------------------------------
__device__ __align__(128) char g_xpk   [(size_t)MTOT * DIM * 4];
__device__ __align__(128) char g_wpk   [(size_t)3 * DIM * DIM * 2];
__device__ __align__(128) char g_w1pk  [(size_t)DIM * 2 * DIM * 2];
__device__ __align__(128) char g_w2pk  [(size_t)DIM * DIM * 2];
__device__ __align__(128) char g_qkpk  [(size_t)2 * MTOT * DIM * 4];
__device__ __align__(128) float g_v    [(size_t)MTOT * DIM];
__device__ __align__(128) char g_vtpk  [(size_t)BSZ * DIM * SEQ * 2];
__device__ __align__(128) float g_scores[(size_t)BSZ * SEQ * SEQ];
__device__ __align__(128) char g_ppk   [(size_t)BSZ * SEQ * SEQ * 2];
__device__ __align__(128) char g_apk   [(size_t)MTOT * DIM * 2];
__device__ __align__(128) char g_hpk   [(size_t)MTOT * DIM * 2];

// ---------------------------------------------------------------------------
// Helpers
// ---------------------------------------------------------------------------
__device__ __forceinline__ uint32_t smem_u32(const void* p) {
    uint32_t a;
    asm("{ .reg .u64 t; cvta.to.shared.u64 t, %1; cvt.u32.u64 %0, t; }" : "=r"(a) : "l"(p));
    return a;
}
__device__ __forceinline__ uint32_t swz(uint32_t x) { return x ^ ((x >> 3) & 0x70); }

__device__ __forceinline__ uint32_t f16pair(float v0, float v1) {
    uint32_t r;   // low16 = fp16(v0), high16 = fp16(v1)
    asm("cvt.rn.f16x2.f32 %0, %1, %2;" : "=r"(r) : "f"(v1), "f"(v0));
    return r;
}
__device__ __forceinline__ uint32_t f16lo(float v0, float v1, uint32_t hi) {
    __half2 h = *reinterpret_cast<__half2*>(&hi);
    return f16pair(v0 - __half2float(__low2half(h)),
                   v1 - __half2float(__high2half(h)));
}
__device__ __forceinline__ void ldsm4(uint32_t* r, uint32_t addr) {
    asm volatile("ldmatrix.sync.aligned.m8n8.x4.shared.b16 {%0,%1,%2,%3}, [%4];"
                 : "=r"(r[0]), "=r"(r[1]), "=r"(r[2]), "=r"(r[3]) : "r"(addr));
}
__device__ __forceinline__ void mma_f16(float* d, const uint32_t* a, const uint32_t* b) {
    asm volatile(
        "mma.sync.aligned.m16n8k16.row.col.f32.f16.f16.f32 "
        "{%0,%1,%2,%3}, {%4,%5,%6,%7}, {%8,%9}, {%0,%1,%2,%3};"
        : "+f"(d[0]), "+f"(d[1]), "+f"(d[2]), "+f"(d[3])
        : "r"(a[0]), "r"(a[1]), "r"(a[2]), "r"(a[3]), "r"(b[0]), "r"(b[1]));
}

// ---------------------------------------------------------------------------
// Generic NT GEMM, 128(M)x64(N) tile, 8 warps (32x32 each).
// 3-stage cp.async pipeline, 1 sync/chunk.
// PASSES=1: Ah*Bh          (copies hi planes only)
// PASSES=2: Ah*Bh + Al*Bh  (copies A full, B hi)
// PASSES=3: + Ah*Bl        (copies both full)
// aCS/bCS: gmem chunk byte stride (128 full, 64 half) per operand/segment.
// mode: 1=relu, 2=causal skip, 4=causal k-limit, 8=full packed out,
//       16=half packed out
// ---------------------------------------------------------------------------
#define TA_BYTES 16384
#define STG 24576
#define GEMM_SMEM (3 * STG)

template <int PASSES>
__global__ __launch_bounds__(256, 3) void gemm_mma(
    const char* __restrict__ Ap, const char* __restrict__ Bp,
    long aRB, long bRB, int aCS, int bCS, long zsA, long zsB, int kc1,
    const char* __restrict__ Ap2, const char* __restrict__ Bp2,
    long aRB2, long bRB2, int aCS2, int bCS2, int kc2,
    void* Cout, long zsC, int ldc, long cRB,
    float scale, const float* __restrict__ bias, int mode)
{
    int m0 = blockIdx.y * 128, n0 = blockIdx.x * 64;
    if ((mode & 2) && n0 >= m0 + 128) return;
    if (mode & 4) { int ke = (m0 + 128) >> 5; if (ke < kc1) kc1 = ke; }
    int z = blockIdx.z;
    Ap += (long)z * zsA;
    Bp += (long)z * zsB;
    char* Cb = (char*)Cout + (long)z * zsC;

    extern __shared__ char smem[];
    uint32_t sb = smem_u32(smem);
    int tid = threadIdx.x;
    int nch = kc1 + kc2;

    constexpr int SEGA = (PASSES >= 2) ? 8 : 4;
    constexpr int SEGB = (PASSES == 3) ? 8 : 4;
    constexpr int SLA  = 128 * SEGA;
    constexpr int ITER = (SLA + 64 * SEGB) / 256;

    auto issue = [&](int c) {
        uint32_t stg = sb + (uint32_t)(c % 3) * STG;
        int cc = c;
        const char* pa; const char* pb; long ra, rb; int acs, bcs;
        if (c < kc1) { pa = Ap;  pb = Bp;  ra = aRB;  rb = bRB;  acs = aCS;  bcs = bCS; }
        else { pa = Ap2; pb = Bp2; ra = aRB2; rb = bRB2; acs = aCS2; bcs = bCS2; cc = c - kc1; }
#pragma unroll
        for (int j = 0; j < ITER; j++) {
            int slot = tid + j * 256;
            const char* g; uint32_t d;
            if (slot < SLA) {
                int row = slot / SEGA, seg = slot % SEGA;
                g = pa + (long)(m0 + row) * ra + (long)cc * acs + seg * 16;
                d = stg + swz((uint32_t)(row * 128 + seg * 16));
            } else {
                int local = slot - SLA;
                int row = local / SEGB, seg = local % SEGB;
                g = pb + (long)(n0 + row) * rb + (long)cc * bcs + seg * 16;
                d = stg + (uint32_t)TA_BYTES + swz((uint32_t)(row * 128 + seg * 16));
            }
            asm volatile("cp.async.cg.shared.global [%0], [%1], 16;" :: "r"(d), "l"(g));
        }
        asm volatile("cp.async.commit_group;" ::: "memory");
    };

    int wid = tid >> 5, lane = tid & 31;
    int wm = wid >> 1, wn = wid & 1;   // 4 (m) x 2 (n) warps
    float acc[2][4][4] = {};

    issue(0);
    if (nch > 1) issue(1);
    else asm volatile("cp.async.commit_group;" ::: "memory");

    uint32_t aRowLoc = (uint32_t)((wm * 32 + (lane & 15)) * 128 + ((lane >> 4) << 4));
    int bg = lane >> 3;
    uint32_t bRowLoc = (uint32_t)((wn * 32 + (lane & 7) + ((bg >> 1) << 3)) * 128 + ((bg & 1) << 4));

    for (int c = 0; c < nch; c++) {
        asm volatile("cp.async.wait_group 1;" ::: "memory");
        __syncthreads();
        if (c + 2 < nch) issue(c + 2);
        else asm volatile("cp.async.commit_group;" ::: "memory");

        uint32_t ta = sb + (uint32_t)(c % 3) * STG;
        uint32_t tb = ta + TA_BYTES;
#pragma unroll
        for (int s = 0; s < 2; s++) {
            int ko = s * 32;
            uint32_t Ah[2][4], Bh[2][4], X[2][4];
#pragma unroll
            for (int mt = 0; mt < 2; mt++)
                ldsm4(Ah[mt], ta + swz(aRowLoc + mt * 2048 + ko));
#pragma unroll
            for (int bt = 0; bt < 2; bt++)
                ldsm4(Bh[bt], tb + swz(bRowLoc + bt * 2048 + ko));
#pragma unroll
            for (int mt = 0; mt < 2; mt++)
#pragma unroll
                for (int nt = 0; nt < 4; nt++)
                    mma_f16(acc[mt][nt], Ah[mt], &Bh[nt >> 1][(nt & 1) * 2]);
            if (PASSES >= 3) {
#pragma unroll
                for (int bt = 0; bt < 2; bt++)
                    ldsm4(X[bt], tb + swz(bRowLoc + bt * 2048 + 64 + ko));
#pragma unroll
                for (int mt = 0; mt < 2; mt++)
#pragma unroll
                    for (int nt = 0; nt < 4; nt++)
                        mma_f16(acc[mt][nt], Ah[mt], &X[nt >> 1][(nt & 1) * 2]);
            }
            if (PASSES >= 2) {
#pragma unroll
                for (int mt = 0; mt < 2; mt++)
                    ldsm4(X[mt], ta + swz(aRowLoc + mt * 2048 + 64 + ko));
#pragma unroll
                for (int mt = 0; mt < 2; mt++)
#pragma unroll
                    for (int nt = 0; nt < 4; nt++)
                        mma_f16(acc[mt][nt], X[mt], &Bh[nt >> 1][(nt & 1) * 2]);
            }
        }
    }

    // Epilogue
    int ql = lane & 3;
    int r0 = m0 + wm * 32 + (lane >> 2);
    if (mode & 8) {            // full packed out (hi + lo)
        int cw = (n0 + wn * 32) >> 5;
        char* cbase = Cb + (long)cw * 128;
#pragma unroll
        for (int mt = 0; mt < 2; mt++) {
#pragma unroll
            for (int half = 0; half < 2; half++) {
                long row = r0 + mt * 16 + half * 8;
                char* rp = cbase + row * cRB;
#pragma unroll
                for (int nt = 0; nt < 4; nt++) {
                    float v0 = acc[mt][nt][half * 2 + 0] * scale;
                    float v1 = acc[mt][nt][half * 2 + 1] * scale;
                    int col = n0 + wn * 32 + nt * 8 + ql * 2;
                    if (bias) { v0 += bias[col]; v1 += bias[col + 1]; }
                    if (mode & 1) { v0 = fmaxf(v0, 0.f); v1 = fmaxf(v1, 0.f); }
                    uint32_t hi = f16pair(v0, v1);
                    uint32_t lo = f16lo(v0, v1, hi);
                    int wb = (nt * 8 + ql * 2) * 2;
                    *(uint32_t*)(rp + wb) = hi;
                    *(uint32_t*)(rp + wb + 64) = lo;
                }
            }
        }
    } else if (mode & 16) {    // half packed out (hi only)
        int cw = (n0 + wn * 32) >> 5;
        char* cbase = Cb + (long)cw * 64;
#pragma unroll
        for (int mt = 0; mt < 2; mt++) {
#pragma unroll
            for (int half = 0; half < 2; half++) {
                long row = r0 + mt * 16 + half * 8;
                char* rp = cbase + row * cRB;
#pragma unroll
                for (int nt = 0; nt < 4; nt++) {
                    float v0 = acc[mt][nt][half * 2 + 0] * scale;
                    float v1 = acc[mt][nt][half * 2 + 1] * scale;
                    int col = n0 + wn * 32 + nt * 8 + ql * 2;
                    if (bias) { v0 += bias[col]; v1 += bias[col + 1]; }
                    if (mode & 1) { v0 = fmaxf(v0, 0.f); v1 = fmaxf(v1, 0.f); }
                    *(uint32_t*)(rp + (nt * 8 + ql * 2) * 2) = f16pair(v0, v1);
                }
            }
        }
    } else {                   // fp32 out
        float* Cf = (float*)Cb;
#pragma unroll
        for (int mt = 0; mt < 2; mt++) {
#pragma unroll
            for (int half = 0; half < 2; half++) {
                long row = r0 + mt * 16 + half * 8;
#pragma unroll
                for (int nt = 0; nt < 4; nt++) {
                    float v0 = acc[mt][nt][half * 2 + 0] * scale;
                    float v1 = acc[mt][nt][half * 2 + 1] * scale;
                    int col = n0 + wn * 32 + nt * 8 + ql * 2;
                    if (bias) { v0 += bias[col]; v1 += bias[col + 1]; }
                    if (mode & 1) { v0 = fmaxf(v0, 0.f); v1 = fmaxf(v1, 0.f); }
                    *(float2*)(Cf + row * (long)ldc + col) = make_float2(v0, v1);
                }
            }
        }
    }
}

// ---------------------------------------------------------------------------
// Pack fp32 [rows][K] -> FULL packed hi|lo
// ---------------------------------------------------------------------------
__global__ __launch_bounds__(256) void k_pack(const float* __restrict__ src,
                                              char* __restrict__ dst, int K) {
    long j0 = ((long)blockIdx.x * 256 + threadIdx.x) * 8;
    float4 f0 = *(const float4*)(src + j0);
    float4 f1 = *(const float4*)(src + j0 + 4);
    long row = j0 / K;
    int k0 = (int)(j0 - row * K);
    uint32_t h0 = f16pair(f0.x, f0.y), h1 = f16pair(f0.z, f0.w);
    uint32_t h2 = f16pair(f1.x, f1.y), h3 = f16pair(f1.z, f1.w);
    uint32_t l0 = f16lo(f0.x, f0.y, h0), l1 = f16lo(f0.z, f0.w, h1);
    uint32_t l2 = f16lo(f1.x, f1.y, h2), l3 = f16lo(f1.z, f1.w, h3);
    char* p = dst + row * (long)K * 4 + (k0 >> 5) * 128 + (k0 & 31) * 2;
    *(uint4*)p = make_uint4(h0, h1, h2, h3);
    *(uint4*)(p + 64) = make_uint4(l0, l1, l2, l3);
}

// ---------------------------------------------------------------------------
// Transpose + pack: in fp32 [R][C] -> packed rows=C, K=R.
// half=1: HALF layout (hi only, row stride R*2); half=0: FULL.
// ---------------------------------------------------------------------------
__global__ __launch_bounds__(256) void k_transpack(const float* __restrict__ in,
                                                   char* __restrict__ out,
                                                   int R, int C,
                                                   long inPlane, long outPlaneBytes,
                                                   int half) {
    in  += (long)blockIdx.z * inPlane;
    out += (long)blockIdx.z * outPlaneBytes;
    int c0 = blockIdx.x * 32, r0 = blockIdx.y * 32;
    __shared__ float t[32][33];
    int tx = threadIdx.x & 31, ty = threadIdx.x >> 5;
#pragma unroll
    for (int i = ty; i < 32; i += 8)
        t[i][tx] = in[(long)(r0 + i) * C + c0 + tx];
    __syncthreads();
    int i = threadIdx.x >> 3;
    int g = (threadIdx.x & 7) * 4;
    float v0 = t[g + 0][i], v1 = t[g + 1][i], v2 = t[g + 2][i], v3 = t[g + 3][i];
    uint32_t h0 = f16pair(v0, v1), h1 = f16pair(v2, v3);
    if (half) {
        char* p = out + (long)(c0 + i) * ((long)R * 2) + (r0 >> 5) * 64 + g * 2;
        *(uint2*)p = make_uint2(h0, h1);
    } else {
        uint32_t l0 = f16lo(v0, v1, h0), l1 = f16lo(v2, v3, h1);
        char* p = out + (long)(c0 + i) * ((long)R * 4) + (r0 >> 5) * 128 + g * 2;
        *(uint2*)p = make_uint2(h0, h1);
        *(uint2*)(p + 64) = make_uint2(l0, l1);
    }
}

// ---------------------------------------------------------------------------
// Causal softmax: fp32 scores row -> HALF packed probs row
// ---------------------------------------------------------------------------
__global__ __launch_bounds__(256) void k_softmax() {
    long rowi = blockIdx.x;
    const float* p = g_scores + rowi * SEQ;
    char* dst = g_ppk + rowi * (SEQ * 2);
    int cnt = (int)(rowi & (SEQ - 1)) + 1;
    int tid = threadIdx.x;
    int j0 = tid * 8;
    __shared__ float red[256];

    float v[8];
    float4 f0 = *(const float4*)(p + j0);
    float4 f1 = *(const float4*)(p + j0 + 4);
    v[0]=f0.x; v[1]=f0.y; v[2]=f0.z; v[3]=f0.w;
    v[4]=f1.x; v[5]=f1.y; v[6]=f1.z; v[7]=f1.w;
    float m = -3.4e38f;
#pragma unroll
    for (int i = 0; i < 8; i++) {
        if (j0 + i >= cnt) v[i] = -3.4e38f;
        m = fmaxf(m, v[i]);
    }
    red[tid] = m;
    __syncthreads();
    for (int s = 128; s > 0; s >>= 1) {
        if (tid < s) red[tid] = fmaxf(red[tid], red[tid + s]);
        __syncthreads();
    }
    m = red[0];
    __syncthreads();
    float sum = 0.f;
#pragma unroll
    for (int i = 0; i < 8; i++) {
        v[i] = (j0 + i < cnt) ? __expf(v[i] - m) : 0.f;
        sum += v[i];
    }
    red[tid] = sum;
    __syncthreads();
    for (int s = 128; s > 0; s >>= 1) {
        if (tid < s) red[tid] += red[tid + s];
        __syncthreads();
    }
    float inv = 1.0f / red[0];
#pragma unroll
    for (int i = 0; i < 8; i++) v[i] *= inv;

    uint32_t h0 = f16pair(v[0], v[1]), h1 = f16pair(v[2], v[3]);
    uint32_t h2 = f16pair(v[4], v[5]), h3 = f16pair(v[6], v[7]);
    char* q = dst + (tid >> 2) * 64 + (tid & 3) * 16;
    *(uint4*)q = make_uint4(h0, h1, h2, h3);
}

// ---------------------------------------------------------------------------
// Launch
// ---------------------------------------------------------------------------
extern "C" void kernel_launch(void* const* d_in, const int* in_sizes, int n_in,
                              void* d_out, int out_size) {
    const float* x  = (const float*)d_in[0];
    const float* Wq = (const float*)d_in[1];
    const float* Wk = (const float*)d_in[2];
    const float* Wv = (const float*)d_in[3];
    const float* W1 = (const float*)d_in[4];
    const float* b1 = (const float*)d_in[5];
    const float* W2 = (const float*)d_in[6];
    const float* b2 = (const float*)d_in[7];
    float* out = (float*)d_out;

    cudaFuncSetAttribute(gemm_mma<1>, cudaFuncAttributeMaxDynamicSharedMemorySize, GEMM_SMEM);
    cudaFuncSetAttribute(gemm_mma<2>, cudaFuncAttributeMaxDynamicSharedMemorySize, GEMM_SMEM);
    cudaFuncSetAttribute(gemm_mma<3>, cudaFuncAttributeMaxDynamicSharedMemorySize, GEMM_SMEM);

    void* p;
    cudaGetSymbolAddress(&p, g_xpk);   char* xpk  = (char*)p;
    cudaGetSymbolAddress(&p, g_wpk);   char* wpk  = (char*)p;
    cudaGetSymbolAddress(&p, g_w1pk);  char* w1pk = (char*)p;
    cudaGetSymbolAddress(&p, g_w2pk);  char* w2pk = (char*)p;
    cudaGetSymbolAddress(&p, g_qkpk);  char* qkpk = (char*)p;
    cudaGetSymbolAddress(&p, g_v);     float* v   = (float*)p;
    cudaGetSymbolAddress(&p, g_vtpk);  char* vtpk = (char*)p;
    cudaGetSymbolAddress(&p, g_scores);float* sc  = (float*)p;
    cudaGetSymbolAddress(&p, g_ppk);   char* ppk  = (char*)p;
    cudaGetSymbolAddress(&p, g_apk);   char* apk  = (char*)p;
    cudaGetSymbolAddress(&p, g_hpk);   char* hpk  = (char*)p;

    const long WPL = (long)DIM * DIM * 2;   // half-packed weight plane bytes

    k_pack<<<dim3((MTOT * DIM) / (8 * 256)), 256>>>(x, xpk, DIM);
    k_transpack<<<dim3(32, 32, 1), 256>>>(Wq, wpk + 0 * WPL, DIM, DIM, 0, 0, 1);
    k_transpack<<<dim3(32, 32, 1), 256>>>(Wk, wpk + 1 * WPL, DIM, DIM, 0, 0, 1);
    k_transpack<<<dim3(32, 32, 1), 256>>>(Wv, wpk + 2 * WPL, DIM, DIM, 0, 0, 1);
    k_transpack<<<dim3(32, 64, 1), 256>>>(W1, w1pk, 2 * DIM, DIM, 0, 0, 1);
    k_transpack<<<dim3(32, 32, 1), 256>>>(W2, w2pk, DIM, DIM, 0, 0, 1);

    // q,k = x @ Wq/Wk (2-pass; A=xpk FULL, B=wpk HALF; out qkpk FULL)
    gemm_mma<2><<<dim3(16, 64, 2), 256, GEMM_SMEM>>>(
        xpk, wpk, DIM * 4, DIM * 2, 128, 64, 0, WPL, 32,
        0, 0, 0, 0, 0, 0, 0,
        qkpk, (long)MTOT * DIM * 4, 0, DIM * 4,
        1.0f, 0, 8);
    // v = x @ Wv (1-pass; hi-only copies; fp32 out)
    gemm_mma<1><<<dim3(16, 64, 1), 256, GEMM_SMEM>>>(
        xpk, wpk + 2 * WPL, DIM * 4, DIM * 2, 128, 64, 0, 0, 32,
        0, 0, 0, 0, 0, 0, 0,
        v, 0, DIM, 0,
        1.0f, 0, 0);
    // vT HALF packed per batch
    k_transpack<<<dim3(32, 64, BSZ), 256>>>(v, vtpk, SEQ, DIM,
                                            (long)SEQ * DIM, (long)DIM * SEQ * 2, 1);
    // scores = q k^T / 32 (3-pass; both FULL; fp32 out, causal skip)
    gemm_mma<3><<<dim3(32, 16, BSZ), 256, GEMM_SMEM>>>(
        qkpk, qkpk + (long)MTOT * DIM * 4,
        DIM * 4, DIM * 4, 128, 128, (long)SEQ * DIM * 4, (long)SEQ * DIM * 4, 32,
        0, 0, 0, 0, 0, 0, 0,
        sc, (long)SEQ * SEQ * 4, SEQ, 0,
        0.03125f, 0, 2);
    k_softmax<<<dim3(BSZ * SEQ), 256>>>();
    // attn = probs @ v (1-pass; A=ppk HALF, B=vtpk HALF; causal k-limit; HALF out)
    gemm_mma<1><<<dim3(16, 16, BSZ), 256, GEMM_SMEM>>>(
        ppk, vtpk, SEQ * 2, SEQ * 2, 64, 64, (long)SEQ * SEQ * 2, (long)DIM * SEQ * 2, 64,
        0, 0, 0, 0, 0, 0, 0,
        apk, (long)SEQ * DIM * 2, 0, DIM * 2,
        1.0f, 0, 4 | 16);
    // h = relu([attn|x] @ W1 + b1) (1-pass; A=apk HALF + xpk FULL(hi); B=w1pk HALF; HALF out)
    gemm_mma<1><<<dim3(16, 64, 1), 256, GEMM_SMEM>>>(
        apk, w1pk, DIM * 2, 2 * DIM * 2, 64, 64, 0, 0, 32,
        xpk, w1pk + 2048, DIM * 4, 2 * DIM * 2, 128, 64, 32,
        hpk, 0, 0, DIM * 2,
        1.0f, b1, 1 | 16);
    // out = h @ W2 + b2 (1-pass; A=hpk HALF, B=w2pk HALF; fp32 out)
    gemm_mma<1><<<dim3(16, 64, 1), 256, GEMM_SMEM>>>(
        hpk, w2pk, DIM * 2, DIM * 2, 64, 64, 0, 0, 32,
        0, 0, 0, 0, 0, 0, 0,
        out, 0, DIM, 0,
        1.0f, b2, 0);
}

// round 11
// speedup vs baseline: 2.0733x; 1.0494x over previous
#include <cuda_runtime.h>
#include <cuda_fp16.h>
#include <cstdint>

#define BSZ 4
#define SEQ 2048
#define DIM 1024
#define MTOT (BSZ*SEQ)

// ---------------------------------------------------------------------------
// Layouts:
//  FULL packed: per row of K floats, K/32 chunks of 128B [64B hi | 64B lo],
//               row stride K*4 bytes.     (xpk, qpk)
//  HALF packed: K/32 chunks of 64B [hi only], row stride K*2 bytes.
//               (weights, kpk, vtpk, ppk, apk, hpk)
// ---------------------------------------------------------------------------
__device__ __align__(128) char g_xpk   [(size_t)MTOT * DIM * 4];
__device__ __align__(128) char g_wpk   [(size_t)3 * DIM * DIM * 2];
__device__ __align__(128) char g_w1pk  [(size_t)DIM * 2 * DIM * 2];
__device__ __align__(128) char g_w2pk  [(size_t)DIM * DIM * 2];
__device__ __align__(128) char g_qpk   [(size_t)MTOT * DIM * 4];
__device__ __align__(128) char g_kpk   [(size_t)MTOT * DIM * 2];
__device__ __align__(128) float g_v    [(size_t)MTOT * DIM];
__device__ __align__(128) char g_vtpk  [(size_t)BSZ * DIM * SEQ * 2];
__device__ __align__(128) float g_scores[(size_t)BSZ * SEQ * SEQ];
__device__ __align__(128) char g_ppk   [(size_t)BSZ * SEQ * SEQ * 2];
__device__ __align__(128) char g_apk   [(size_t)MTOT * DIM * 2];
__device__ __align__(128) char g_hpk   [(size_t)MTOT * DIM * 2];

// ---------------------------------------------------------------------------
// Helpers
// ---------------------------------------------------------------------------
__device__ __forceinline__ uint32_t smem_u32(const void* p) {
    uint32_t a;
    asm("{ .reg .u64 t; cvta.to.shared.u64 t, %1; cvt.u32.u64 %0, t; }" : "=r"(a) : "l"(p));
    return a;
}
__device__ __forceinline__ uint32_t swz(uint32_t x) { return x ^ ((x >> 3) & 0x70); }

__device__ __forceinline__ uint32_t f16pair(float v0, float v1) {
    uint32_t r;   // low16 = fp16(v0), high16 = fp16(v1)
    asm("cvt.rn.f16x2.f32 %0, %1, %2;" : "=r"(r) : "f"(v1), "f"(v0));
    return r;
}
__device__ __forceinline__ uint32_t f16lo(float v0, float v1, uint32_t hi) {
    __half2 h = *reinterpret_cast<__half2*>(&hi);
    return f16pair(v0 - __half2float(__low2half(h)),
                   v1 - __half2float(__high2half(h)));
}
__device__ __forceinline__ void ldsm4(uint32_t* r, uint32_t addr) {
    asm volatile("ldmatrix.sync.aligned.m8n8.x4.shared.b16 {%0,%1,%2,%3}, [%4];"
                 : "=r"(r[0]), "=r"(r[1]), "=r"(r[2]), "=r"(r[3]) : "r"(addr));
}
__device__ __forceinline__ void mma_f16(float* d, const uint32_t* a, const uint32_t* b) {
    asm volatile(
        "mma.sync.aligned.m16n8k16.row.col.f32.f16.f16.f32 "
        "{%0,%1,%2,%3}, {%4,%5,%6,%7}, {%8,%9}, {%0,%1,%2,%3};"
        : "+f"(d[0]), "+f"(d[1]), "+f"(d[2]), "+f"(d[3])
        : "r"(a[0]), "r"(a[1]), "r"(a[2]), "r"(a[3]), "r"(b[0]), "r"(b[1]));
}

// ---------------------------------------------------------------------------
// Generic NT GEMM, 128(M)x64(N) tile, 8 warps (32x32 each).
// 3-stage cp.async pipeline, 1 sync/chunk.
// PASSES=1: Ah*Bh          (copies hi planes only)
// PASSES=2: Ah*Bh + Al*Bh  (copies A full, B hi)
// PASSES=3: + Ah*Bl        (copies both full)
// aCS/bCS: gmem chunk byte stride (128 full, 64 half) per operand/segment.
// mode: 1=relu, 2=causal skip, 4=causal k-limit, 8=full packed out,
//       16=half packed out
// ---------------------------------------------------------------------------
#define TA_BYTES 16384
#define STG 24576
#define GEMM_SMEM (3 * STG)

template <int PASSES>
__global__ __launch_bounds__(256, 3) void gemm_mma(
    const char* __restrict__ Ap, const char* __restrict__ Bp,
    long aRB, long bRB, int aCS, int bCS, long zsA, long zsB, int kc1,
    const char* __restrict__ Ap2, const char* __restrict__ Bp2,
    long aRB2, long bRB2, int aCS2, int bCS2, int kc2,
    void* Cout, long zsC, int ldc, long cRB,
    float scale, const float* __restrict__ bias, int mode)
{
    int m0 = blockIdx.y * 128, n0 = blockIdx.x * 64;
    if ((mode & 2) && n0 >= m0 + 128) return;
    if (mode & 4) { int ke = (m0 + 128) >> 5; if (ke < kc1) kc1 = ke; }
    int z = blockIdx.z;
    Ap += (long)z * zsA;
    Bp += (long)z * zsB;
    char* Cb = (char*)Cout + (long)z * zsC;

    extern __shared__ char smem[];
    uint32_t sb = smem_u32(smem);
    int tid = threadIdx.x;
    int nch = kc1 + kc2;

    constexpr int SEGA = (PASSES >= 2) ? 8 : 4;
    constexpr int SEGB = (PASSES == 3) ? 8 : 4;
    constexpr int SLA  = 128 * SEGA;
    constexpr int ITER = (SLA + 64 * SEGB) / 256;

    auto issue = [&](int c) {
        uint32_t stg = sb + (uint32_t)(c % 3) * STG;
        int cc = c;
        const char* pa; const char* pb; long ra, rb; int acs, bcs;
        if (c < kc1) { pa = Ap;  pb = Bp;  ra = aRB;  rb = bRB;  acs = aCS;  bcs = bCS; }
        else { pa = Ap2; pb = Bp2; ra = aRB2; rb = bRB2; acs = aCS2; bcs = bCS2; cc = c - kc1; }
#pragma unroll
        for (int j = 0; j < ITER; j++) {
            int slot = tid + j * 256;
            const char* g; uint32_t d;
            if (slot < SLA) {
                int row = slot / SEGA, seg = slot % SEGA;
                g = pa + (long)(m0 + row) * ra + (long)cc * acs + seg * 16;
                d = stg + swz((uint32_t)(row * 128 + seg * 16));
            } else {
                int local = slot - SLA;
                int row = local / SEGB, seg = local % SEGB;
                g = pb + (long)(n0 + row) * rb + (long)cc * bcs + seg * 16;
                d = stg + (uint32_t)TA_BYTES + swz((uint32_t)(row * 128 + seg * 16));
            }
            asm volatile("cp.async.cg.shared.global [%0], [%1], 16;" :: "r"(d), "l"(g));
        }
        asm volatile("cp.async.commit_group;" ::: "memory");
    };

    int wid = tid >> 5, lane = tid & 31;
    int wm = wid >> 1, wn = wid & 1;   // 4 (m) x 2 (n) warps
    float acc[2][4][4] = {};

    issue(0);
    if (nch > 1) issue(1);
    else asm volatile("cp.async.commit_group;" ::: "memory");

    uint32_t aRowLoc = (uint32_t)((wm * 32 + (lane & 15)) * 128 + ((lane >> 4) << 4));
    int bg = lane >> 3;
    uint32_t bRowLoc = (uint32_t)((wn * 32 + (lane & 7) + ((bg >> 1) << 3)) * 128 + ((bg & 1) << 4));

    for (int c = 0; c < nch; c++) {
        asm volatile("cp.async.wait_group 1;" ::: "memory");
        __syncthreads();
        if (c + 2 < nch) issue(c + 2);
        else asm volatile("cp.async.commit_group;" ::: "memory");

        uint32_t ta = sb + (uint32_t)(c % 3) * STG;
        uint32_t tb = ta + TA_BYTES;
#pragma unroll
        for (int s = 0; s < 2; s++) {
            int ko = s * 32;
            uint32_t Ah[2][4], Bh[2][4], X[2][4];
#pragma unroll
            for (int mt = 0; mt < 2; mt++)
                ldsm4(Ah[mt], ta + swz(aRowLoc + mt * 2048 + ko));
#pragma unroll
            for (int bt = 0; bt < 2; bt++)
                ldsm4(Bh[bt], tb + swz(bRowLoc + bt * 2048 + ko));
#pragma unroll
            for (int mt = 0; mt < 2; mt++)
#pragma unroll
                for (int nt = 0; nt < 4; nt++)
                    mma_f16(acc[mt][nt], Ah[mt], &Bh[nt >> 1][(nt & 1) * 2]);
            if (PASSES >= 3) {
#pragma unroll
                for (int bt = 0; bt < 2; bt++)
                    ldsm4(X[bt], tb + swz(bRowLoc + bt * 2048 + 64 + ko));
#pragma unroll
                for (int mt = 0; mt < 2; mt++)
#pragma unroll
                    for (int nt = 0; nt < 4; nt++)
                        mma_f16(acc[mt][nt], Ah[mt], &X[nt >> 1][(nt & 1) * 2]);
            }
            if (PASSES >= 2) {
#pragma unroll
                for (int mt = 0; mt < 2; mt++)
                    ldsm4(X[mt], ta + swz(aRowLoc + mt * 2048 + 64 + ko));
#pragma unroll
                for (int mt = 0; mt < 2; mt++)
#pragma unroll
                    for (int nt = 0; nt < 4; nt++)
                        mma_f16(acc[mt][nt], X[mt], &Bh[nt >> 1][(nt & 1) * 2]);
            }
        }
    }

    // Epilogue
    int ql = lane & 3;
    int r0 = m0 + wm * 32 + (lane >> 2);
    if (mode & 8) {            // full packed out (hi + lo)
        int cw = (n0 + wn * 32) >> 5;
        char* cbase = Cb + (long)cw * 128;
#pragma unroll
        for (int mt = 0; mt < 2; mt++) {
#pragma unroll
            for (int half = 0; half < 2; half++) {
                long row = r0 + mt * 16 + half * 8;
                char* rp = cbase + row * cRB;
#pragma unroll
                for (int nt = 0; nt < 4; nt++) {
                    float v0 = acc[mt][nt][half * 2 + 0] * scale;
                    float v1 = acc[mt][nt][half * 2 + 1] * scale;
                    int col = n0 + wn * 32 + nt * 8 + ql * 2;
                    if (bias) { v0 += bias[col]; v1 += bias[col + 1]; }
                    if (mode & 1) { v0 = fmaxf(v0, 0.f); v1 = fmaxf(v1, 0.f); }
                    uint32_t hi = f16pair(v0, v1);
                    uint32_t lo = f16lo(v0, v1, hi);
                    int wb = (nt * 8 + ql * 2) * 2;
                    *(uint32_t*)(rp + wb) = hi;
                    *(uint32_t*)(rp + wb + 64) = lo;
                }
            }
        }
    } else if (mode & 16) {    // half packed out (hi only)
        int cw = (n0 + wn * 32) >> 5;
        char* cbase = Cb + (long)cw * 64;
#pragma unroll
        for (int mt = 0; mt < 2; mt++) {
#pragma unroll
            for (int half = 0; half < 2; half++) {
                long row = r0 + mt * 16 + half * 8;
                char* rp = cbase + row * cRB;
#pragma unroll
                for (int nt = 0; nt < 4; nt++) {
                    float v0 = acc[mt][nt][half * 2 + 0] * scale;
                    float v1 = acc[mt][nt][half * 2 + 1] * scale;
                    int col = n0 + wn * 32 + nt * 8 + ql * 2;
                    if (bias) { v0 += bias[col]; v1 += bias[col + 1]; }
                    if (mode & 1) { v0 = fmaxf(v0, 0.f); v1 = fmaxf(v1, 0.f); }
                    *(uint32_t*)(rp + (nt * 8 + ql * 2) * 2) = f16pair(v0, v1);
                }
            }
        }
    } else {                   // fp32 out
        float* Cf = (float*)Cb;
#pragma unroll
        for (int mt = 0; mt < 2; mt++) {
#pragma unroll
            for (int half = 0; half < 2; half++) {
                long row = r0 + mt * 16 + half * 8;
#pragma unroll
                for (int nt = 0; nt < 4; nt++) {
                    float v0 = acc[mt][nt][half * 2 + 0] * scale;
                    float v1 = acc[mt][nt][half * 2 + 1] * scale;
                    int col = n0 + wn * 32 + nt * 8 + ql * 2;
                    if (bias) { v0 += bias[col]; v1 += bias[col + 1]; }
                    if (mode & 1) { v0 = fmaxf(v0, 0.f); v1 = fmaxf(v1, 0.f); }
                    *(float2*)(Cf + row * (long)ldc + col) = make_float2(v0, v1);
                }
            }
        }
    }
}

// ---------------------------------------------------------------------------
// Pack fp32 [rows][K] -> FULL packed hi|lo
// ---------------------------------------------------------------------------
__global__ __launch_bounds__(256) void k_pack(const float* __restrict__ src,
                                              char* __restrict__ dst, int K) {
    long j0 = ((long)blockIdx.x * 256 + threadIdx.x) * 8;
    float4 f0 = *(const float4*)(src + j0);
    float4 f1 = *(const float4*)(src + j0 + 4);
    long row = j0 / K;
    int k0 = (int)(j0 - row * K);
    uint32_t h0 = f16pair(f0.x, f0.y), h1 = f16pair(f0.z, f0.w);
    uint32_t h2 = f16pair(f1.x, f1.y), h3 = f16pair(f1.z, f1.w);
    uint32_t l0 = f16lo(f0.x, f0.y, h0), l1 = f16lo(f0.z, f0.w, h1);
    uint32_t l2 = f16lo(f1.x, f1.y, h2), l3 = f16lo(f1.z, f1.w, h3);
    char* p = dst + row * (long)K * 4 + (k0 >> 5) * 128 + (k0 & 31) * 2;
    *(uint4*)p = make_uint4(h0, h1, h2, h3);
    *(uint4*)(p + 64) = make_uint4(l0, l1, l2, l3);
}

// ---------------------------------------------------------------------------
// Transpose + pack: in fp32 [R][C] -> packed rows=C, K=R.
// half=1: HALF layout (hi only); half=0: FULL.
// ---------------------------------------------------------------------------
__global__ __launch_bounds__(256) void k_transpack(const float* __restrict__ in,
                                                   char* __restrict__ out,
                                                   int R, int C,
                                                   long inPlane, long outPlaneBytes,
                                                   int half) {
    in  += (long)blockIdx.z * inPlane;
    out += (long)blockIdx.z * outPlaneBytes;
    int c0 = blockIdx.x * 32, r0 = blockIdx.y * 32;
    __shared__ float t[32][33];
    int tx = threadIdx.x & 31, ty = threadIdx.x >> 5;
#pragma unroll
    for (int i = ty; i < 32; i += 8)
        t[i][tx] = in[(long)(r0 + i) * C + c0 + tx];
    __syncthreads();
    int i = threadIdx.x >> 3;
    int g = (threadIdx.x & 7) * 4;
    float v0 = t[g + 0][i], v1 = t[g + 1][i], v2 = t[g + 2][i], v3 = t[g + 3][i];
    uint32_t h0 = f16pair(v0, v1), h1 = f16pair(v2, v3);
    if (half) {
        char* p = out + (long)(c0 + i) * ((long)R * 2) + (r0 >> 5) * 64 + g * 2;
        *(uint2*)p = make_uint2(h0, h1);
    } else {
        uint32_t l0 = f16lo(v0, v1, h0), l1 = f16lo(v2, v3, h1);
        char* p = out + (long)(c0 + i) * ((long)R * 4) + (r0 >> 5) * 128 + g * 2;
        *(uint2*)p = make_uint2(h0, h1);
        *(uint2*)(p + 64) = make_uint2(l0, l1);
    }
}

// ---------------------------------------------------------------------------
// Causal softmax: fp32 scores row -> HALF packed probs row
// ---------------------------------------------------------------------------
__global__ __launch_bounds__(256) void k_softmax() {
    long rowi = blockIdx.x;
    const float* p = g_scores + rowi * SEQ;
    char* dst = g_ppk + rowi * (SEQ * 2);
    int cnt = (int)(rowi & (SEQ - 1)) + 1;
    int tid = threadIdx.x;
    int j0 = tid * 8;
    __shared__ float red[256];

    float v[8];
    float4 f0 = *(const float4*)(p + j0);
    float4 f1 = *(const float4*)(p + j0 + 4);
    v[0]=f0.x; v[1]=f0.y; v[2]=f0.z; v[3]=f0.w;
    v[4]=f1.x; v[5]=f1.y; v[6]=f1.z; v[7]=f1.w;
    float m = -3.4e38f;
#pragma unroll
    for (int i = 0; i < 8; i++) {
        if (j0 + i >= cnt) v[i] = -3.4e38f;
        m = fmaxf(m, v[i]);
    }
    red[tid] = m;
    __syncthreads();
    for (int s = 128; s > 0; s >>= 1) {
        if (tid < s) red[tid] = fmaxf(red[tid], red[tid + s]);
        __syncthreads();
    }
    m = red[0];
    __syncthreads();
    float sum = 0.f;
#pragma unroll
    for (int i = 0; i < 8; i++) {
        v[i] = (j0 + i < cnt) ? __expf(v[i] - m) : 0.f;
        sum += v[i];
    }
    red[tid] = sum;
    __syncthreads();
    for (int s = 128; s > 0; s >>= 1) {
        if (tid < s) red[tid] += red[tid + s];
        __syncthreads();
    }
    float inv = 1.0f / red[0];
#pragma unroll
    for (int i = 0; i < 8; i++) v[i] *= inv;

    uint32_t h0 = f16pair(v[0], v[1]), h1 = f16pair(v[2], v[3]);
    uint32_t h2 = f16pair(v[4], v[5]), h3 = f16pair(v[6], v[7]);
    char* q = dst + (tid >> 2) * 64 + (tid & 3) * 16;
    *(uint4*)q = make_uint4(h0, h1, h2, h3);
}

// ---------------------------------------------------------------------------
// Launch
// ---------------------------------------------------------------------------
extern "C" void kernel_launch(void* const* d_in, const int* in_sizes, int n_in,
                              void* d_out, int out_size) {
    const float* x  = (const float*)d_in[0];
    const float* Wq = (const float*)d_in[1];
    const float* Wk = (const float*)d_in[2];
    const float* Wv = (const float*)d_in[3];
    const float* W1 = (const float*)d_in[4];
    const float* b1 = (const float*)d_in[5];
    const float* W2 = (const float*)d_in[6];
    const float* b2 = (const float*)d_in[7];
    float* out = (float*)d_out;

    cudaFuncSetAttribute(gemm_mma<1>, cudaFuncAttributeMaxDynamicSharedMemorySize, GEMM_SMEM);
    cudaFuncSetAttribute(gemm_mma<2>, cudaFuncAttributeMaxDynamicSharedMemorySize, GEMM_SMEM);

    void* p;
    cudaGetSymbolAddress(&p, g_xpk);   char* xpk  = (char*)p;
    cudaGetSymbolAddress(&p, g_wpk);   char* wpk  = (char*)p;
    cudaGetSymbolAddress(&p, g_w1pk);  char* w1pk = (char*)p;
    cudaGetSymbolAddress(&p, g_w2pk);  char* w2pk = (char*)p;
    cudaGetSymbolAddress(&p, g_qpk);   char* qpk  = (char*)p;
    cudaGetSymbolAddress(&p, g_kpk);   char* kpk  = (char*)p;
    cudaGetSymbolAddress(&p, g_v);     float* v   = (float*)p;
    cudaGetSymbolAddress(&p, g_vtpk);  char* vtpk = (char*)p;
    cudaGetSymbolAddress(&p, g_scores);float* sc  = (float*)p;
    cudaGetSymbolAddress(&p, g_ppk);   char* ppk  = (char*)p;
    cudaGetSymbolAddress(&p, g_apk);   char* apk  = (char*)p;
    cudaGetSymbolAddress(&p, g_hpk);   char* hpk  = (char*)p;

    const long WPL = (long)DIM * DIM * 2;   // half-packed weight plane bytes

    k_pack<<<dim3((MTOT * DIM) / (8 * 256)), 256>>>(x, xpk, DIM);
    k_transpack<<<dim3(32, 32, 1), 256>>>(Wq, wpk + 0 * WPL, DIM, DIM, 0, 0, 1);
    k_transpack<<<dim3(32, 32, 1), 256>>>(Wk, wpk + 1 * WPL, DIM, DIM, 0, 0, 1);
    k_transpack<<<dim3(32, 32, 1), 256>>>(Wv, wpk + 2 * WPL, DIM, DIM, 0, 0, 1);
    k_transpack<<<dim3(32, 64, 1), 256>>>(W1, w1pk, 2 * DIM, DIM, 0, 0, 1);
    k_transpack<<<dim3(32, 32, 1), 256>>>(W2, w2pk, DIM, DIM, 0, 0, 1);

    // q = x @ Wq (2-pass; FULL out — lo plane feeds scores A-split)
    gemm_mma<2><<<dim3(16, 64, 1), 256, GEMM_SMEM>>>(
        xpk, wpk, DIM * 4, DIM * 2, 128, 64, 0, 0, 32,
        0, 0, 0, 0, 0, 0, 0,
        qpk, 0, 0, DIM * 4,
        1.0f, 0, 8);
    // k = x @ Wk (2-pass; HALF out — lo never consumed)
    gemm_mma<2><<<dim3(16, 64, 1), 256, GEMM_SMEM>>>(
        xpk, wpk + 1 * WPL, DIM * 4, DIM * 2, 128, 64, 0, 0, 32,
        0, 0, 0, 0, 0, 0, 0,
        kpk, 0, 0, DIM * 2,
        1.0f, 0, 16);
    // v = x @ Wv (1-pass; fp32 out)
    gemm_mma<1><<<dim3(16, 64, 1), 256, GEMM_SMEM>>>(
        xpk, wpk + 2 * WPL, DIM * 4, DIM * 2, 128, 64, 0, 0, 32,
        0, 0, 0, 0, 0, 0, 0,
        v, 0, DIM, 0,
        1.0f, 0, 0);
    // vT HALF packed per batch
    k_transpack<<<dim3(32, 64, BSZ), 256>>>(v, vtpk, SEQ, DIM,
                                            (long)SEQ * DIM, (long)DIM * SEQ * 2, 1);
    // scores = q k^T / 32 (2-pass: A=qpk FULL split, B=kpk HALF; causal skip)
    gemm_mma<2><<<dim3(32, 16, BSZ), 256, GEMM_SMEM>>>(
        qpk, kpk, DIM * 4, DIM * 2, 128, 64,
        (long)SEQ * DIM * 4, (long)SEQ * DIM * 2, 32,
        0, 0, 0, 0, 0, 0, 0,
        sc, (long)SEQ * SEQ * 4, SEQ, 0,
        0.03125f, 0, 2);
    k_softmax<<<dim3(BSZ * SEQ), 256>>>();
    // attn = probs @ v (1-pass; HALF in/out; causal k-limit)
    gemm_mma<1><<<dim3(16, 16, BSZ), 256, GEMM_SMEM>>>(
        ppk, vtpk, SEQ * 2, SEQ * 2, 64, 64, (long)SEQ * SEQ * 2, (long)DIM * SEQ * 2, 64,
        0, 0, 0, 0, 0, 0, 0,
        apk, (long)SEQ * DIM * 2, 0, DIM * 2,
        1.0f, 0, 4 | 16);
    // h = relu([attn|x] @ W1 + b1) (1-pass; HALF out)
    gemm_mma<1><<<dim3(16, 64, 1), 256, GEMM_SMEM>>>(
        apk, w1pk, DIM * 2, 2 * DIM * 2, 64, 64, 0, 0, 32,
        xpk, w1pk + 2048, DIM * 4, 2 * DIM * 2, 128, 64, 32,
        hpk, 0, 0, DIM * 2,
        1.0f, b1, 1 | 16);
    // out = h @ W2 + b2 (1-pass; fp32 out)
    gemm_mma<1><<<dim3(16, 64, 1), 256, GEMM_SMEM>>>(
        hpk, w2pk, DIM * 2, DIM * 2, 64, 64, 0, 0, 32,
        0, 0, 0, 0, 0, 0, 0,
        out, 0, DIM, 0,
        1.0f, b2, 0);
}

// round 12
// speedup vs baseline: 2.2303x; 1.0757x over previous
#include <cuda_runtime.h>
#include <cuda_fp16.h>
#include <cstdint>

#define BSZ 4
#define SEQ 2048
#define DIM 1024
#define MTOT (BSZ*SEQ)

// ---------------------------------------------------------------------------
// Layouts:
//  FULL packed: per row of K floats, K/32 chunks of 128B [64B hi | 64B lo],
//               row stride K*4 bytes.     (xpk only)
//  HALF packed: K/32 chunks of 64B [hi only], row stride K*2 bytes.
//               (weights, qpk, kpk, vtpk, ppk, apk, hpk)
// ---------------------------------------------------------------------------
__device__ __align__(128) char g_xpk   [(size_t)MTOT * DIM * 4];
__device__ __align__(128) char g_wpk   [(size_t)3 * DIM * DIM * 2];
__device__ __align__(128) char g_w1pk  [(size_t)DIM * 2 * DIM * 2];
__device__ __align__(128) char g_w2pk  [(size_t)DIM * DIM * 2];
__device__ __align__(128) char g_qpk   [(size_t)MTOT * DIM * 2];
__device__ __align__(128) char g_kpk   [(size_t)MTOT * DIM * 2];
__device__ __align__(128) float g_v    [(size_t)MTOT * DIM];
__device__ __align__(128) char g_vtpk  [(size_t)BSZ * DIM * SEQ * 2];
__device__ __align__(128) float g_scores[(size_t)BSZ * SEQ * SEQ];
__device__ __align__(128) char g_ppk   [(size_t)BSZ * SEQ * SEQ * 2];
__device__ __align__(128) char g_apk   [(size_t)MTOT * DIM * 2];
__device__ __align__(128) char g_hpk   [(size_t)MTOT * DIM * 2];

// ---------------------------------------------------------------------------
// Helpers
// ---------------------------------------------------------------------------
__device__ __forceinline__ uint32_t smem_u32(const void* p) {
    uint32_t a;
    asm("{ .reg .u64 t; cvta.to.shared.u64 t, %1; cvt.u32.u64 %0, t; }" : "=r"(a) : "l"(p));
    return a;
}
__device__ __forceinline__ uint32_t swz(uint32_t x) { return x ^ ((x >> 3) & 0x70); }

__device__ __forceinline__ uint32_t f16pair(float v0, float v1) {
    uint32_t r;   // low16 = fp16(v0), high16 = fp16(v1)
    asm("cvt.rn.f16x2.f32 %0, %1, %2;" : "=r"(r) : "f"(v1), "f"(v0));
    return r;
}
__device__ __forceinline__ uint32_t f16lo(float v0, float v1, uint32_t hi) {
    __half2 h = *reinterpret_cast<__half2*>(&hi);
    return f16pair(v0 - __half2float(__low2half(h)),
                   v1 - __half2float(__high2half(h)));
}
__device__ __forceinline__ void ldsm4(uint32_t* r, uint32_t addr) {
    asm volatile("ldmatrix.sync.aligned.m8n8.x4.shared.b16 {%0,%1,%2,%3}, [%4];"
                 : "=r"(r[0]), "=r"(r[1]), "=r"(r[2]), "=r"(r[3]) : "r"(addr));
}
__device__ __forceinline__ void mma_f16(float* d, const uint32_t* a, const uint32_t* b) {
    asm volatile(
        "mma.sync.aligned.m16n8k16.row.col.f32.f16.f16.f32 "
        "{%0,%1,%2,%3}, {%4,%5,%6,%7}, {%8,%9}, {%0,%1,%2,%3};"
        : "+f"(d[0]), "+f"(d[1]), "+f"(d[2]), "+f"(d[3])
        : "r"(a[0]), "r"(a[1]), "r"(a[2]), "r"(a[3]), "r"(b[0]), "r"(b[1]));
}

// ---------------------------------------------------------------------------
// Generic NT GEMM, 128(M)x64(N) tile, 8 warps (32x32 each).
// 3-stage cp.async pipeline, 1 sync/chunk.
// PASSES=1: Ah*Bh          (copies hi planes only)
// PASSES=2: Ah*Bh + Al*Bh  (copies A full, B hi)
// aCS/bCS: gmem chunk byte stride (128 full, 64 half) per operand/segment.
// mode: 1=relu, 2=causal skip, 4=causal k-limit, 8=full packed out,
//       16=half packed out
// ---------------------------------------------------------------------------
#define TA_BYTES 16384
#define STG 24576
#define GEMM_SMEM (3 * STG)

template <int PASSES>
__global__ __launch_bounds__(256, 3) void gemm_mma(
    const char* __restrict__ Ap, const char* __restrict__ Bp,
    long aRB, long bRB, int aCS, int bCS, long zsA, long zsB, int kc1,
    const char* __restrict__ Ap2, const char* __restrict__ Bp2,
    long aRB2, long bRB2, int aCS2, int bCS2, int kc2,
    void* Cout, long zsC, int ldc, long cRB,
    float scale, const float* __restrict__ bias, int mode)
{
    int m0 = blockIdx.y * 128, n0 = blockIdx.x * 64;
    if ((mode & 2) && n0 >= m0 + 128) return;
    if (mode & 4) { int ke = (m0 + 128) >> 5; if (ke < kc1) kc1 = ke; }
    int z = blockIdx.z;
    Ap += (long)z * zsA;
    Bp += (long)z * zsB;
    char* Cb = (char*)Cout + (long)z * zsC;

    extern __shared__ char smem[];
    uint32_t sb = smem_u32(smem);
    int tid = threadIdx.x;
    int nch = kc1 + kc2;

    constexpr int SEGA = (PASSES >= 2) ? 8 : 4;
    constexpr int SEGB = 4;
    constexpr int SLA  = 128 * SEGA;
    constexpr int ITER = (SLA + 64 * SEGB) / 256;

    auto issue = [&](int c) {
        uint32_t stg = sb + (uint32_t)(c % 3) * STG;
        int cc = c;
        const char* pa; const char* pb; long ra, rb; int acs, bcs;
        if (c < kc1) { pa = Ap;  pb = Bp;  ra = aRB;  rb = bRB;  acs = aCS;  bcs = bCS; }
        else { pa = Ap2; pb = Bp2; ra = aRB2; rb = bRB2; acs = aCS2; bcs = bCS2; cc = c - kc1; }
#pragma unroll
        for (int j = 0; j < ITER; j++) {
            int slot = tid + j * 256;
            const char* g; uint32_t d;
            if (slot < SLA) {
                int row = slot / SEGA, seg = slot % SEGA;
                g = pa + (long)(m0 + row) * ra + (long)cc * acs + seg * 16;
                d = stg + swz((uint32_t)(row * 128 + seg * 16));
            } else {
                int local = slot - SLA;
                int row = local / SEGB, seg = local % SEGB;
                g = pb + (long)(n0 + row) * rb + (long)cc * bcs + seg * 16;
                d = stg + (uint32_t)TA_BYTES + swz((uint32_t)(row * 128 + seg * 16));
            }
            asm volatile("cp.async.cg.shared.global [%0], [%1], 16;" :: "r"(d), "l"(g));
        }
        asm volatile("cp.async.commit_group;" ::: "memory");
    };

    int wid = tid >> 5, lane = tid & 31;
    int wm = wid >> 1, wn = wid & 1;   // 4 (m) x 2 (n) warps
    float acc[2][4][4] = {};

    issue(0);
    if (nch > 1) issue(1);
    else asm volatile("cp.async.commit_group;" ::: "memory");

    uint32_t aRowLoc = (uint32_t)((wm * 32 + (lane & 15)) * 128 + ((lane >> 4) << 4));
    int bg = lane >> 3;
    uint32_t bRowLoc = (uint32_t)((wn * 32 + (lane & 7) + ((bg >> 1) << 3)) * 128 + ((bg & 1) << 4));

    for (int c = 0; c < nch; c++) {
        asm volatile("cp.async.wait_group 1;" ::: "memory");
        __syncthreads();
        if (c + 2 < nch) issue(c + 2);
        else asm volatile("cp.async.commit_group;" ::: "memory");

        uint32_t ta = sb + (uint32_t)(c % 3) * STG;
        uint32_t tb = ta + TA_BYTES;
#pragma unroll
        for (int s = 0; s < 2; s++) {
            int ko = s * 32;
            uint32_t Ah[2][4], Bh[2][4], X[2][4];
#pragma unroll
            for (int mt = 0; mt < 2; mt++)
                ldsm4(Ah[mt], ta + swz(aRowLoc + mt * 2048 + ko));
#pragma unroll
            for (int bt = 0; bt < 2; bt++)
                ldsm4(Bh[bt], tb + swz(bRowLoc + bt * 2048 + ko));
#pragma unroll
            for (int mt = 0; mt < 2; mt++)
#pragma unroll
                for (int nt = 0; nt < 4; nt++)
                    mma_f16(acc[mt][nt], Ah[mt], &Bh[nt >> 1][(nt & 1) * 2]);
            if (PASSES >= 2) {
#pragma unroll
                for (int mt = 0; mt < 2; mt++)
                    ldsm4(X[mt], ta + swz(aRowLoc + mt * 2048 + 64 + ko));
#pragma unroll
                for (int mt = 0; mt < 2; mt++)
#pragma unroll
                    for (int nt = 0; nt < 4; nt++)
                        mma_f16(acc[mt][nt], X[mt], &Bh[nt >> 1][(nt & 1) * 2]);
            }
        }
    }

    // Epilogue
    int ql = lane & 3;
    int r0 = m0 + wm * 32 + (lane >> 2);
    if (mode & 8) {            // full packed out (hi + lo)
        int cw = (n0 + wn * 32) >> 5;
        char* cbase = Cb + (long)cw * 128;
#pragma unroll
        for (int mt = 0; mt < 2; mt++) {
#pragma unroll
            for (int half = 0; half < 2; half++) {
                long row = r0 + mt * 16 + half * 8;
                char* rp = cbase + row * cRB;
#pragma unroll
                for (int nt = 0; nt < 4; nt++) {
                    float v0 = acc[mt][nt][half * 2 + 0] * scale;
                    float v1 = acc[mt][nt][half * 2 + 1] * scale;
                    int col = n0 + wn * 32 + nt * 8 + ql * 2;
                    if (bias) { v0 += bias[col]; v1 += bias[col + 1]; }
                    if (mode & 1) { v0 = fmaxf(v0, 0.f); v1 = fmaxf(v1, 0.f); }
                    uint32_t hi = f16pair(v0, v1);
                    uint32_t lo = f16lo(v0, v1, hi);
                    int wb = (nt * 8 + ql * 2) * 2;
                    *(uint32_t*)(rp + wb) = hi;
                    *(uint32_t*)(rp + wb + 64) = lo;
                }
            }
        }
    } else if (mode & 16) {    // half packed out (hi only)
        int cw = (n0 + wn * 32) >> 5;
        char* cbase = Cb + (long)cw * 64;
#pragma unroll
        for (int mt = 0; mt < 2; mt++) {
#pragma unroll
            for (int half = 0; half < 2; half++) {
                long row = r0 + mt * 16 + half * 8;
                char* rp = cbase + row * cRB;
#pragma unroll
                for (int nt = 0; nt < 4; nt++) {
                    float v0 = acc[mt][nt][half * 2 + 0] * scale;
                    float v1 = acc[mt][nt][half * 2 + 1] * scale;
                    int col = n0 + wn * 32 + nt * 8 + ql * 2;
                    if (bias) { v0 += bias[col]; v1 += bias[col + 1]; }
                    if (mode & 1) { v0 = fmaxf(v0, 0.f); v1 = fmaxf(v1, 0.f); }
                    *(uint32_t*)(rp + (nt * 8 + ql * 2) * 2) = f16pair(v0, v1);
                }
            }
        }
    } else {                   // fp32 out
        float* Cf = (float*)Cb;
#pragma unroll
        for (int mt = 0; mt < 2; mt++) {
#pragma unroll
            for (int half = 0; half < 2; half++) {
                long row = r0 + mt * 16 + half * 8;
#pragma unroll
                for (int nt = 0; nt < 4; nt++) {
                    float v0 = acc[mt][nt][half * 2 + 0] * scale;
                    float v1 = acc[mt][nt][half * 2 + 1] * scale;
                    int col = n0 + wn * 32 + nt * 8 + ql * 2;
                    if (bias) { v0 += bias[col]; v1 += bias[col + 1]; }
                    if (mode & 1) { v0 = fmaxf(v0, 0.f); v1 = fmaxf(v1, 0.f); }
                    *(float2*)(Cf + row * (long)ldc + col) = make_float2(v0, v1);
                }
            }
        }
    }
}

// ---------------------------------------------------------------------------
// Pack fp32 [rows][K] -> FULL packed hi|lo
// ---------------------------------------------------------------------------
__global__ __launch_bounds__(256) void k_pack(const float* __restrict__ src,
                                              char* __restrict__ dst, int K) {
    long j0 = ((long)blockIdx.x * 256 + threadIdx.x) * 8;
    float4 f0 = *(const float4*)(src + j0);
    float4 f1 = *(const float4*)(src + j0 + 4);
    long row = j0 / K;
    int k0 = (int)(j0 - row * K);
    uint32_t h0 = f16pair(f0.x, f0.y), h1 = f16pair(f0.z, f0.w);
    uint32_t h2 = f16pair(f1.x, f1.y), h3 = f16pair(f1.z, f1.w);
    uint32_t l0 = f16lo(f0.x, f0.y, h0), l1 = f16lo(f0.z, f0.w, h1);
    uint32_t l2 = f16lo(f1.x, f1.y, h2), l3 = f16lo(f1.z, f1.w, h3);
    char* p = dst + row * (long)K * 4 + (k0 >> 5) * 128 + (k0 & 31) * 2;
    *(uint4*)p = make_uint4(h0, h1, h2, h3);
    *(uint4*)(p + 64) = make_uint4(l0, l1, l2, l3);
}

// ---------------------------------------------------------------------------
// Transpose + pack: in fp32 [R][C] -> packed rows=C, K=R.
// half=1: HALF layout (hi only); half=0: FULL.
// ---------------------------------------------------------------------------
__global__ __launch_bounds__(256) void k_transpack(const float* __restrict__ in,
                                                   char* __restrict__ out,
                                                   int R, int C,
                                                   long inPlane, long outPlaneBytes,
                                                   int half) {
    in  += (long)blockIdx.z * inPlane;
    out += (long)blockIdx.z * outPlaneBytes;
    int c0 = blockIdx.x * 32, r0 = blockIdx.y * 32;
    __shared__ float t[32][33];
    int tx = threadIdx.x & 31, ty = threadIdx.x >> 5;
#pragma unroll
    for (int i = ty; i < 32; i += 8)
        t[i][tx] = in[(long)(r0 + i) * C + c0 + tx];
    __syncthreads();
    int i = threadIdx.x >> 3;
    int g = (threadIdx.x & 7) * 4;
    float v0 = t[g + 0][i], v1 = t[g + 1][i], v2 = t[g + 2][i], v3 = t[g + 3][i];
    uint32_t h0 = f16pair(v0, v1), h1 = f16pair(v2, v3);
    if (half) {
        char* p = out + (long)(c0 + i) * ((long)R * 2) + (r0 >> 5) * 64 + g * 2;
        *(uint2*)p = make_uint2(h0, h1);
    } else {
        uint32_t l0 = f16lo(v0, v1, h0), l1 = f16lo(v2, v3, h1);
        char* p = out + (long)(c0 + i) * ((long)R * 4) + (r0 >> 5) * 128 + g * 2;
        *(uint2*)p = make_uint2(h0, h1);
        *(uint2*)(p + 64) = make_uint2(l0, l1);
    }
}

// ---------------------------------------------------------------------------
// Causal softmax: fp32 scores row -> HALF packed probs row
// ---------------------------------------------------------------------------
__global__ __launch_bounds__(256) void k_softmax() {
    long rowi = blockIdx.x;
    const float* p = g_scores + rowi * SEQ;
    char* dst = g_ppk + rowi * (SEQ * 2);
    int cnt = (int)(rowi & (SEQ - 1)) + 1;
    int tid = threadIdx.x;
    int j0 = tid * 8;
    __shared__ float red[256];

    float v[8];
    float4 f0 = *(const float4*)(p + j0);
    float4 f1 = *(const float4*)(p + j0 + 4);
    v[0]=f0.x; v[1]=f0.y; v[2]=f0.z; v[3]=f0.w;
    v[4]=f1.x; v[5]=f1.y; v[6]=f1.z; v[7]=f1.w;
    float m = -3.4e38f;
#pragma unroll
    for (int i = 0; i < 8; i++) {
        if (j0 + i >= cnt) v[i] = -3.4e38f;
        m = fmaxf(m, v[i]);
    }
    red[tid] = m;
    __syncthreads();
    for (int s = 128; s > 0; s >>= 1) {
        if (tid < s) red[tid] = fmaxf(red[tid], red[tid + s]);
        __syncthreads();
    }
    m = red[0];
    __syncthreads();
    float sum = 0.f;
#pragma unroll
    for (int i = 0; i < 8; i++) {
        v[i] = (j0 + i < cnt) ? __expf(v[i] - m) : 0.f;
        sum += v[i];
    }
    red[tid] = sum;
    __syncthreads();
    for (int s = 128; s > 0; s >>= 1) {
        if (tid < s) red[tid] += red[tid + s];
        __syncthreads();
    }
    float inv = 1.0f / red[0];
#pragma unroll
    for (int i = 0; i < 8; i++) v[i] *= inv;

    uint32_t h0 = f16pair(v[0], v[1]), h1 = f16pair(v[2], v[3]);
    uint32_t h2 = f16pair(v[4], v[5]), h3 = f16pair(v[6], v[7]);
    char* q = dst + (tid >> 2) * 64 + (tid & 3) * 16;
    *(uint4*)q = make_uint4(h0, h1, h2, h3);
}

// ---------------------------------------------------------------------------
// Launch
// ---------------------------------------------------------------------------
extern "C" void kernel_launch(void* const* d_in, const int* in_sizes, int n_in,
                              void* d_out, int out_size) {
    const float* x  = (const float*)d_in[0];
    const float* Wq = (const float*)d_in[1];
    const float* Wk = (const float*)d_in[2];
    const float* Wv = (const float*)d_in[3];
    const float* W1 = (const float*)d_in[4];
    const float* b1 = (const float*)d_in[5];
    const float* W2 = (const float*)d_in[6];
    const float* b2 = (const float*)d_in[7];
    float* out = (float*)d_out;

    cudaFuncSetAttribute(gemm_mma<1>, cudaFuncAttributeMaxDynamicSharedMemorySize, GEMM_SMEM);
    cudaFuncSetAttribute(gemm_mma<2>, cudaFuncAttributeMaxDynamicSharedMemorySize, GEMM_SMEM);

    void* p;
    cudaGetSymbolAddress(&p, g_xpk);   char* xpk  = (char*)p;
    cudaGetSymbolAddress(&p, g_wpk);   char* wpk  = (char*)p;
    cudaGetSymbolAddress(&p, g_w1pk);  char* w1pk = (char*)p;
    cudaGetSymbolAddress(&p, g_w2pk);  char* w2pk = (char*)p;
    cudaGetSymbolAddress(&p, g_qpk);   char* qpk  = (char*)p;
    cudaGetSymbolAddress(&p, g_kpk);   char* kpk  = (char*)p;
    cudaGetSymbolAddress(&p, g_v);     float* v   = (float*)p;
    cudaGetSymbolAddress(&p, g_vtpk);  char* vtpk = (char*)p;
    cudaGetSymbolAddress(&p, g_scores);float* sc  = (float*)p;
    cudaGetSymbolAddress(&p, g_ppk);   char* ppk  = (char*)p;
    cudaGetSymbolAddress(&p, g_apk);   char* apk  = (char*)p;
    cudaGetSymbolAddress(&p, g_hpk);   char* hpk  = (char*)p;

    const long WPL = (long)DIM * DIM * 2;   // half-packed weight plane bytes

    k_pack<<<dim3((MTOT * DIM) / (8 * 256)), 256>>>(x, xpk, DIM);
    k_transpack<<<dim3(32, 32, 1), 256>>>(Wq, wpk + 0 * WPL, DIM, DIM, 0, 0, 1);
    k_transpack<<<dim3(32, 32, 1), 256>>>(Wk, wpk + 1 * WPL, DIM, DIM, 0, 0, 1);
    k_transpack<<<dim3(32, 32, 1), 256>>>(Wv, wpk + 2 * WPL, DIM, DIM, 0, 0, 1);
    k_transpack<<<dim3(32, 64, 1), 256>>>(W1, w1pk, 2 * DIM, DIM, 0, 0, 1);
    k_transpack<<<dim3(32, 32, 1), 256>>>(W2, w2pk, DIM, DIM, 0, 0, 1);

    // q = x @ Wq (2-pass; HALF out — scores is now 1-pass, lo unused)
    gemm_mma<2><<<dim3(16, 64, 1), 256, GEMM_SMEM>>>(
        xpk, wpk, DIM * 4, DIM * 2, 128, 64, 0, 0, 32,
        0, 0, 0, 0, 0, 0, 0,
        qpk, 0, 0, DIM * 2,
        1.0f, 0, 16);
    // k = x @ Wk (2-pass; HALF out)
    gemm_mma<2><<<dim3(16, 64, 1), 256, GEMM_SMEM>>>(
        xpk, wpk + 1 * WPL, DIM * 4, DIM * 2, 128, 64, 0, 0, 32,
        0, 0, 0, 0, 0, 0, 0,
        kpk, 0, 0, DIM * 2,
        1.0f, 0, 16);
    // v = x @ Wv (1-pass; fp32 out)
    gemm_mma<1><<<dim3(16, 64, 1), 256, GEMM_SMEM>>>(
        xpk, wpk + 2 * WPL, DIM * 4, DIM * 2, 128, 64, 0, 0, 32,
        0, 0, 0, 0, 0, 0, 0,
        v, 0, DIM, 0,
        1.0f, 0, 0);
    // vT HALF packed per batch
    k_transpack<<<dim3(32, 64, BSZ), 256>>>(v, vtpk, SEQ, DIM,
                                            (long)SEQ * DIM, (long)DIM * SEQ * 2, 1);
    // scores = q k^T / 32 (1-pass fp16; both HALF; causal skip)
    gemm_mma<1><<<dim3(32, 16, BSZ), 256, GEMM_SMEM>>>(
        qpk, kpk, DIM * 2, DIM * 2, 64, 64,
        (long)SEQ * DIM * 2, (long)SEQ * DIM * 2, 32,
        0, 0, 0, 0, 0, 0, 0,
        sc, (long)SEQ * SEQ * 4, SEQ, 0,
        0.03125f, 0, 2);
    k_softmax<<<dim3(BSZ * SEQ), 256>>>();
    // attn = probs @ v (1-pass; HALF in/out; causal k-limit)
    gemm_mma<1><<<dim3(16, 16, BSZ), 256, GEMM_SMEM>>>(
        ppk, vtpk, SEQ * 2, SEQ * 2, 64, 64, (long)SEQ * SEQ * 2, (long)DIM * SEQ * 2, 64,
        0, 0, 0, 0, 0, 0, 0,
        apk, (long)SEQ * DIM * 2, 0, DIM * 2,
        1.0f, 0, 4 | 16);
    // h = relu([attn|x] @ W1 + b1) (1-pass; HALF out)
    gemm_mma<1><<<dim3(16, 64, 1), 256, GEMM_SMEM>>>(
        apk, w1pk, DIM * 2, 2 * DIM * 2, 64, 64, 0, 0, 32,
        xpk, w1pk + 2048, DIM * 4, 2 * DIM * 2, 128, 64, 32,
        hpk, 0, 0, DIM * 2,
        1.0f, b1, 1 | 16);
    // out = h @ W2 + b2 (1-pass; fp32 out)
    gemm_mma<1><<<dim3(16, 64, 1), 256, GEMM_SMEM>>>(
        hpk, w2pk, DIM * 2, DIM * 2, 64, 64, 0, 0, 32,
        0, 0, 0, 0, 0, 0, 0,
        out, 0, DIM, 0,
        1.0f, b2, 0);
}

// round 13
// speedup vs baseline: 2.6377x; 1.1827x over previous
#include <cuda_runtime.h>
#include <cuda_fp16.h>
#include <cstdint>

#define BSZ 4
#define SEQ 2048
#define DIM 1024
#define MTOT (BSZ*SEQ)

// ---------------------------------------------------------------------------
// HALF packed layout everywhere: per row of K floats, K/32 chunks of 64B
// [32 fp16], row stride K*2 bytes.
// ---------------------------------------------------------------------------
__device__ __align__(128) char g_xpk   [(size_t)MTOT * DIM * 2];
__device__ __align__(128) char g_wpk   [(size_t)3 * DIM * DIM * 2];
__device__ __align__(128) char g_w1pk  [(size_t)DIM * 2 * DIM * 2];
__device__ __align__(128) char g_w2pk  [(size_t)DIM * DIM * 2];
__device__ __align__(128) char g_qpk   [(size_t)MTOT * DIM * 2];
__device__ __align__(128) char g_kpk   [(size_t)MTOT * DIM * 2];
__device__ __align__(128) float g_v    [(size_t)MTOT * DIM];
__device__ __align__(128) char g_vtpk  [(size_t)BSZ * DIM * SEQ * 2];
__device__ __align__(128) float g_scores[(size_t)BSZ * SEQ * SEQ];
__device__ __align__(128) char g_ppk   [(size_t)BSZ * SEQ * SEQ * 2];
__device__ __align__(128) char g_apk   [(size_t)MTOT * DIM * 2];
__device__ __align__(128) char g_hpk   [(size_t)MTOT * DIM * 2];

// ---------------------------------------------------------------------------
// Helpers
// ---------------------------------------------------------------------------
__device__ __forceinline__ uint32_t smem_u32(const void* p) {
    uint32_t a;
    asm("{ .reg .u64 t; cvta.to.shared.u64 t, %1; cvt.u32.u64 %0, t; }" : "=r"(a) : "l"(p));
    return a;
}
__device__ __forceinline__ uint32_t swz(uint32_t x) { return x ^ ((x >> 3) & 0x70); }

__device__ __forceinline__ uint32_t f16pair(float v0, float v1) {
    uint32_t r;   // low16 = fp16(v0), high16 = fp16(v1)
    asm("cvt.rn.f16x2.f32 %0, %1, %2;" : "=r"(r) : "f"(v1), "f"(v0));
    return r;
}
__device__ __forceinline__ void ldsm4(uint32_t* r, uint32_t addr) {
    asm volatile("ldmatrix.sync.aligned.m8n8.x4.shared.b16 {%0,%1,%2,%3}, [%4];"
                 : "=r"(r[0]), "=r"(r[1]), "=r"(r[2]), "=r"(r[3]) : "r"(addr));
}
__device__ __forceinline__ void mma_f16(float* d, const uint32_t* a, const uint32_t* b) {
    asm volatile(
        "mma.sync.aligned.m16n8k16.row.col.f32.f16.f16.f32 "
        "{%0,%1,%2,%3}, {%4,%5,%6,%7}, {%8,%9}, {%0,%1,%2,%3};"
        : "+f"(d[0]), "+f"(d[1]), "+f"(d[2]), "+f"(d[3])
        : "r"(a[0]), "r"(a[1]), "r"(a[2]), "r"(a[3]), "r"(b[0]), "r"(b[1]));
}

// ---------------------------------------------------------------------------
// NT GEMM, 128(M)x64(N) tile, 8 warps (32x32 each), pure fp16 operands,
// fp32 accumulate. 3-stage cp.async pipeline, 1 sync/chunk.
// mode: 1=relu, 2=causal skip, 4=causal k-limit, 16=half packed out
// ---------------------------------------------------------------------------
#define TA_BYTES 16384
#define STG 24576
#define GEMM_SMEM (3 * STG)

__global__ __launch_bounds__(256, 3) void gemm_mma(
    const char* __restrict__ Ap, const char* __restrict__ Bp,
    long aRB, long bRB, long zsA, long zsB, int kc1,
    const char* __restrict__ Ap2, const char* __restrict__ Bp2,
    long aRB2, long bRB2, int kc2,
    void* Cout, long zsC, int ldc, long cRB,
    float scale, const float* __restrict__ bias, int mode)
{
    int m0 = blockIdx.y * 128, n0 = blockIdx.x * 64;
    if ((mode & 2) && n0 >= m0 + 128) return;
    if (mode & 4) { int ke = (m0 + 128) >> 5; if (ke < kc1) kc1 = ke; }
    int z = blockIdx.z;
    Ap += (long)z * zsA;
    Bp += (long)z * zsB;
    char* Cb = (char*)Cout + (long)z * zsC;

    extern __shared__ char smem[];
    uint32_t sb = smem_u32(smem);
    int tid = threadIdx.x;
    int nch = kc1 + kc2;

    // copy: A tile 128 rows x 64B (512 slots of 16B), B tile 64 rows x 64B (256)
    auto issue = [&](int c) {
        uint32_t stg = sb + (uint32_t)(c % 3) * STG;
        int cc = c;
        const char* pa; const char* pb; long ra, rb;
        if (c < kc1) { pa = Ap;  pb = Bp;  ra = aRB;  rb = bRB; }
        else         { pa = Ap2; pb = Bp2; ra = aRB2; rb = bRB2; cc = c - kc1; }
        long cOff = (long)cc * 64;
#pragma unroll
        for (int j = 0; j < 3; j++) {
            int slot = tid + j * 256;
            const char* g; uint32_t d;
            if (slot < 512) {
                int row = slot >> 2, seg = slot & 3;
                g = pa + (long)(m0 + row) * ra + cOff + seg * 16;
                d = stg + swz((uint32_t)(row * 128 + seg * 16));
            } else {
                int local = slot - 512;
                int row = local >> 2, seg = local & 3;
                g = pb + (long)(n0 + row) * rb + cOff + seg * 16;
                d = stg + (uint32_t)TA_BYTES + swz((uint32_t)(row * 128 + seg * 16));
            }
            asm volatile("cp.async.cg.shared.global [%0], [%1], 16;" :: "r"(d), "l"(g));
        }
        asm volatile("cp.async.commit_group;" ::: "memory");
    };

    int wid = tid >> 5, lane = tid & 31;
    int wm = wid >> 1, wn = wid & 1;   // 4 (m) x 2 (n) warps
    float acc[2][4][4] = {};

    issue(0);
    if (nch > 1) issue(1);
    else asm volatile("cp.async.commit_group;" ::: "memory");

    uint32_t aRowLoc = (uint32_t)((wm * 32 + (lane & 15)) * 128 + ((lane >> 4) << 4));
    int bg = lane >> 3;
    uint32_t bRowLoc = (uint32_t)((wn * 32 + (lane & 7) + ((bg >> 1) << 3)) * 128 + ((bg & 1) << 4));

    for (int c = 0; c < nch; c++) {
        asm volatile("cp.async.wait_group 1;" ::: "memory");
        __syncthreads();
        if (c + 2 < nch) issue(c + 2);
        else asm volatile("cp.async.commit_group;" ::: "memory");

        uint32_t ta = sb + (uint32_t)(c % 3) * STG;
        uint32_t tb = ta + TA_BYTES;
#pragma unroll
        for (int s = 0; s < 2; s++) {
            int ko = s * 32;
            uint32_t Ah[2][4], Bh[2][4];
#pragma unroll
            for (int mt = 0; mt < 2; mt++)
                ldsm4(Ah[mt], ta + swz(aRowLoc + mt * 2048 + ko));
#pragma unroll
            for (int bt = 0; bt < 2; bt++)
                ldsm4(Bh[bt], tb + swz(bRowLoc + bt * 2048 + ko));
#pragma unroll
            for (int mt = 0; mt < 2; mt++)
#pragma unroll
                for (int nt = 0; nt < 4; nt++)
                    mma_f16(acc[mt][nt], Ah[mt], &Bh[nt >> 1][(nt & 1) * 2]);
        }
    }

    // Epilogue
    int ql = lane & 3;
    int r0 = m0 + wm * 32 + (lane >> 2);
    if (mode & 16) {           // half packed out
        int cw = (n0 + wn * 32) >> 5;
        char* cbase = Cb + (long)cw * 64;
#pragma unroll
        for (int mt = 0; mt < 2; mt++) {
#pragma unroll
            for (int half = 0; half < 2; half++) {
                long row = r0 + mt * 16 + half * 8;
                char* rp = cbase + row * cRB;
#pragma unroll
                for (int nt = 0; nt < 4; nt++) {
                    float v0 = acc[mt][nt][half * 2 + 0] * scale;
                    float v1 = acc[mt][nt][half * 2 + 1] * scale;
                    int col = n0 + wn * 32 + nt * 8 + ql * 2;
                    if (bias) { v0 += bias[col]; v1 += bias[col + 1]; }
                    if (mode & 1) { v0 = fmaxf(v0, 0.f); v1 = fmaxf(v1, 0.f); }
                    *(uint32_t*)(rp + (nt * 8 + ql * 2) * 2) = f16pair(v0, v1);
                }
            }
        }
    } else {                   // fp32 out
        float* Cf = (float*)Cb;
#pragma unroll
        for (int mt = 0; mt < 2; mt++) {
#pragma unroll
            for (int half = 0; half < 2; half++) {
                long row = r0 + mt * 16 + half * 8;
#pragma unroll
                for (int nt = 0; nt < 4; nt++) {
                    float v0 = acc[mt][nt][half * 2 + 0] * scale;
                    float v1 = acc[mt][nt][half * 2 + 1] * scale;
                    int col = n0 + wn * 32 + nt * 8 + ql * 2;
                    if (bias) { v0 += bias[col]; v1 += bias[col + 1]; }
                    if (mode & 1) { v0 = fmaxf(v0, 0.f); v1 = fmaxf(v1, 0.f); }
                    *(float2*)(Cf + row * (long)ldc + col) = make_float2(v0, v1);
                }
            }
        }
    }
}

// ---------------------------------------------------------------------------
// Pack fp32 [rows][K] -> HALF packed (hi only)
// ---------------------------------------------------------------------------
__global__ __launch_bounds__(256) void k_pack(const float* __restrict__ src,
                                              char* __restrict__ dst, int K) {
    long j0 = ((long)blockIdx.x * 256 + threadIdx.x) * 8;
    float4 f0 = *(const float4*)(src + j0);
    float4 f1 = *(const float4*)(src + j0 + 4);
    long row = j0 / K;
    int k0 = (int)(j0 - row * K);
    uint32_t h0 = f16pair(f0.x, f0.y), h1 = f16pair(f0.z, f0.w);
    uint32_t h2 = f16pair(f1.x, f1.y), h3 = f16pair(f1.z, f1.w);
    char* p = dst + row * (long)K * 2 + (k0 >> 5) * 64 + (k0 & 31) * 2;
    *(uint4*)p = make_uint4(h0, h1, h2, h3);
}

// ---------------------------------------------------------------------------
// Transpose + pack: in fp32 [R][C] -> HALF packed rows=C, K=R
// ---------------------------------------------------------------------------
__global__ __launch_bounds__(256) void k_transpack(const float* __restrict__ in,
                                                   char* __restrict__ out,
                                                   int R, int C,
                                                   long inPlane, long outPlaneBytes) {
    in  += (long)blockIdx.z * inPlane;
    out += (long)blockIdx.z * outPlaneBytes;
    int c0 = blockIdx.x * 32, r0 = blockIdx.y * 32;
    __shared__ float t[32][33];
    int tx = threadIdx.x & 31, ty = threadIdx.x >> 5;
#pragma unroll
    for (int i = ty; i < 32; i += 8)
        t[i][tx] = in[(long)(r0 + i) * C + c0 + tx];
    __syncthreads();
    int i = threadIdx.x >> 3;
    int g = (threadIdx.x & 7) * 4;
    float v0 = t[g + 0][i], v1 = t[g + 1][i], v2 = t[g + 2][i], v3 = t[g + 3][i];
    uint32_t h0 = f16pair(v0, v1), h1 = f16pair(v2, v3);
    char* p = out + (long)(c0 + i) * ((long)R * 2) + (r0 >> 5) * 64 + g * 2;
    *(uint2*)p = make_uint2(h0, h1);
}

// ---------------------------------------------------------------------------
// Causal softmax: fp32 scores row -> HALF packed probs row
// ---------------------------------------------------------------------------
__global__ __launch_bounds__(256) void k_softmax() {
    long rowi = blockIdx.x;
    const float* p = g_scores + rowi * SEQ;
    char* dst = g_ppk + rowi * (SEQ * 2);
    int cnt = (int)(rowi & (SEQ - 1)) + 1;
    int tid = threadIdx.x;
    int j0 = tid * 8;
    __shared__ float red[256];

    float v[8];
    float4 f0 = *(const float4*)(p + j0);
    float4 f1 = *(const float4*)(p + j0 + 4);
    v[0]=f0.x; v[1]=f0.y; v[2]=f0.z; v[3]=f0.w;
    v[4]=f1.x; v[5]=f1.y; v[6]=f1.z; v[7]=f1.w;
    float m = -3.4e38f;
#pragma unroll
    for (int i = 0; i < 8; i++) {
        if (j0 + i >= cnt) v[i] = -3.4e38f;
        m = fmaxf(m, v[i]);
    }
    red[tid] = m;
    __syncthreads();
    for (int s = 128; s > 0; s >>= 1) {
        if (tid < s) red[tid] = fmaxf(red[tid], red[tid + s]);
        __syncthreads();
    }
    m = red[0];
    __syncthreads();
    float sum = 0.f;
#pragma unroll
    for (int i = 0; i < 8; i++) {
        v[i] = (j0 + i < cnt) ? __expf(v[i] - m) : 0.f;
        sum += v[i];
    }
    red[tid] = sum;
    __syncthreads();
    for (int s = 128; s > 0; s >>= 1) {
        if (tid < s) red[tid] += red[tid + s];
        __syncthreads();
    }
    float inv = 1.0f / red[0];
#pragma unroll
    for (int i = 0; i < 8; i++) v[i] *= inv;

    uint32_t h0 = f16pair(v[0], v[1]), h1 = f16pair(v[2], v[3]);
    uint32_t h2 = f16pair(v[4], v[5]), h3 = f16pair(v[6], v[7]);
    char* q = dst + (tid >> 2) * 64 + (tid & 3) * 16;
    *(uint4*)q = make_uint4(h0, h1, h2, h3);
}

// ---------------------------------------------------------------------------
// Launch
// ---------------------------------------------------------------------------
extern "C" void kernel_launch(void* const* d_in, const int* in_sizes, int n_in,
                              void* d_out, int out_size) {
    const float* x  = (const float*)d_in[0];
    const float* Wq = (const float*)d_in[1];
    const float* Wk = (const float*)d_in[2];
    const float* Wv = (const float*)d_in[3];
    const float* W1 = (const float*)d_in[4];
    const float* b1 = (const float*)d_in[5];
    const float* W2 = (const float*)d_in[6];
    const float* b2 = (const float*)d_in[7];
    float* out = (float*)d_out;

    cudaFuncSetAttribute(gemm_mma, cudaFuncAttributeMaxDynamicSharedMemorySize, GEMM_SMEM);

    void* p;
    cudaGetSymbolAddress(&p, g_xpk);   char* xpk  = (char*)p;
    cudaGetSymbolAddress(&p, g_wpk);   char* wpk  = (char*)p;
    cudaGetSymbolAddress(&p, g_w1pk);  char* w1pk = (char*)p;
    cudaGetSymbolAddress(&p, g_w2pk);  char* w2pk = (char*)p;
    cudaGetSymbolAddress(&p, g_qpk);   char* qpk  = (char*)p;
    cudaGetSymbolAddress(&p, g_kpk);   char* kpk  = (char*)p;
    cudaGetSymbolAddress(&p, g_v);     float* v   = (float*)p;
    cudaGetSymbolAddress(&p, g_vtpk);  char* vtpk = (char*)p;
    cudaGetSymbolAddress(&p, g_scores);float* sc  = (float*)p;
    cudaGetSymbolAddress(&p, g_ppk);   char* ppk  = (char*)p;
    cudaGetSymbolAddress(&p, g_apk);   char* apk  = (char*)p;
    cudaGetSymbolAddress(&p, g_hpk);   char* hpk  = (char*)p;

    const long WPL = (long)DIM * DIM * 2;   // half-packed weight plane bytes

    k_pack<<<dim3((MTOT * DIM) / (8 * 256)), 256>>>(x, xpk, DIM);
    k_transpack<<<dim3(32, 32, 1), 256>>>(Wq, wpk + 0 * WPL, DIM, DIM, 0, 0);
    k_transpack<<<dim3(32, 32, 1), 256>>>(Wk, wpk + 1 * WPL, DIM, DIM, 0, 0);
    k_transpack<<<dim3(32, 32, 1), 256>>>(Wv, wpk + 2 * WPL, DIM, DIM, 0, 0);
    k_transpack<<<dim3(32, 64, 1), 256>>>(W1, w1pk, 2 * DIM, DIM, 0, 0);
    k_transpack<<<dim3(32, 32, 1), 256>>>(W2, w2pk, DIM, DIM, 0, 0);

    // q = x @ Wq (1-pass; HALF out)
    gemm_mma<<<dim3(16, 64, 1), 256, GEMM_SMEM>>>(
        xpk, wpk, DIM * 2, DIM * 2, 0, 0, 32,
        0, 0, 0, 0, 0,
        qpk, 0, 0, DIM * 2,
        1.0f, 0, 16);
    // k = x @ Wk (1-pass; HALF out)
    gemm_mma<<<dim3(16, 64, 1), 256, GEMM_SMEM>>>(
        xpk, wpk + 1 * WPL, DIM * 2, DIM * 2, 0, 0, 32,
        0, 0, 0, 0, 0,
        kpk, 0, 0, DIM * 2,
        1.0f, 0, 16);
    // v = x @ Wv (1-pass; fp32 out)
    gemm_mma<<<dim3(16, 64, 1), 256, GEMM_SMEM>>>(
        xpk, wpk + 2 * WPL, DIM * 2, DIM * 2, 0, 0, 32,
        0, 0, 0, 0, 0,
        v, 0, DIM, 0,
        1.0f, 0, 0);
    // vT HALF packed per batch
    k_transpack<<<dim3(32, 64, BSZ), 256>>>(v, vtpk, SEQ, DIM,
                                            (long)SEQ * DIM, (long)DIM * SEQ * 2);
    // scores = q k^T / 32 (1-pass fp16; causal skip; fp32 out)
    gemm_mma<<<dim3(32, 16, BSZ), 256, GEMM_SMEM>>>(
        qpk, kpk, DIM * 2, DIM * 2,
        (long)SEQ * DIM * 2, (long)SEQ * DIM * 2, 32,
        0, 0, 0, 0, 0,
        sc, (long)SEQ * SEQ * 4, SEQ, 0,
        0.03125f, 0, 2);
    k_softmax<<<dim3(BSZ * SEQ), 256>>>();
    // attn = probs @ v (1-pass; causal k-limit; HALF out)
    gemm_mma<<<dim3(16, 16, BSZ), 256, GEMM_SMEM>>>(
        ppk, vtpk, SEQ * 2, SEQ * 2, (long)SEQ * SEQ * 2, (long)DIM * SEQ * 2, 64,
        0, 0, 0, 0, 0,
        apk, (long)SEQ * DIM * 2, 0, DIM * 2,
        1.0f, 0, 4 | 16);
    // h = relu([attn|x] @ W1 + b1) (1-pass; HALF out)
    gemm_mma<<<dim3(16, 64, 1), 256, GEMM_SMEM>>>(
        apk, w1pk, DIM * 2, 2 * DIM * 2, 0, 0, 32,
        xpk, w1pk + 2048, DIM * 2, 2 * DIM * 2, 32,
        hpk, 0, 0, DIM * 2,
        1.0f, b1, 1 | 16);
    // out = h @ W2 + b2 (1-pass; fp32 out)
    gemm_mma<<<dim3(16, 64, 1), 256, GEMM_SMEM>>>(
        hpk, w2pk, DIM * 2, DIM * 2, 0, 0, 32,
        0, 0, 0, 0, 0,
        out, 0, DIM, 0,
        1.0f, b2, 0);
}

// round 14
// speedup vs baseline: 2.6994x; 1.0234x over previous
#include <cuda_runtime.h>
#include <cuda_fp16.h>
#include <cstdint>

#define BSZ 4
#define SEQ 2048
#define DIM 1024
#define MTOT (BSZ*SEQ)

// ---------------------------------------------------------------------------
// HALF packed layout everywhere: per row of K floats, K/32 chunks of 64B
// [32 fp16], row stride K*2 bytes.
// ---------------------------------------------------------------------------
__device__ __align__(128) char g_xpk   [(size_t)MTOT * DIM * 2];
__device__ __align__(128) char g_wpk   [(size_t)3 * DIM * DIM * 2];
__device__ __align__(128) char g_w1pk  [(size_t)DIM * 2 * DIM * 2];
__device__ __align__(128) char g_w2pk  [(size_t)DIM * DIM * 2];
__device__ __align__(128) char g_qkvpk [(size_t)3 * MTOT * DIM * 2];  // q|k|v
__device__ __align__(128) char g_vtpk  [(size_t)BSZ * DIM * SEQ * 2];
__device__ __align__(128) float g_scores[(size_t)BSZ * SEQ * SEQ];
__device__ __align__(128) char g_ppk   [(size_t)BSZ * SEQ * SEQ * 2];
__device__ __align__(128) char g_apk   [(size_t)MTOT * DIM * 2];
__device__ __align__(128) char g_hpk   [(size_t)MTOT * DIM * 2];

// ---------------------------------------------------------------------------
// Helpers
// ---------------------------------------------------------------------------
__device__ __forceinline__ uint32_t smem_u32(const void* p) {
    uint32_t a;
    asm("{ .reg .u64 t; cvta.to.shared.u64 t, %1; cvt.u32.u64 %0, t; }" : "=r"(a) : "l"(p));
    return a;
}
__device__ __forceinline__ uint32_t swz(uint32_t x) { return x ^ ((x >> 3) & 0x70); }

__device__ __forceinline__ uint32_t f16pair(float v0, float v1) {
    uint32_t r;   // low16 = fp16(v0), high16 = fp16(v1)
    asm("cvt.rn.f16x2.f32 %0, %1, %2;" : "=r"(r) : "f"(v1), "f"(v0));
    return r;
}
__device__ __forceinline__ void ldsm4(uint32_t* r, uint32_t addr) {
    asm volatile("ldmatrix.sync.aligned.m8n8.x4.shared.b16 {%0,%1,%2,%3}, [%4];"
                 : "=r"(r[0]), "=r"(r[1]), "=r"(r[2]), "=r"(r[3]) : "r"(addr));
}
__device__ __forceinline__ void mma_f16(float* d, const uint32_t* a, const uint32_t* b) {
    asm volatile(
        "mma.sync.aligned.m16n8k16.row.col.f32.f16.f16.f32 "
        "{%0,%1,%2,%3}, {%4,%5,%6,%7}, {%8,%9}, {%0,%1,%2,%3};"
        : "+f"(d[0]), "+f"(d[1]), "+f"(d[2]), "+f"(d[3])
        : "r"(a[0]), "r"(a[1]), "r"(a[2]), "r"(a[3]), "r"(b[0]), "r"(b[1]));
}

// ---------------------------------------------------------------------------
// NT GEMM, 128(M)x64(N) tile, 8 warps (32x32 each), pure fp16 operands,
// fp32 accumulate. 3-stage cp.async pipeline, 1 sync/chunk.
// mode: 1=relu, 2=causal skip, 4=causal k-limit, 16=half packed out
// ---------------------------------------------------------------------------
#define TA_BYTES 16384
#define STG 24576
#define GEMM_SMEM (3 * STG)

__global__ __launch_bounds__(256, 3) void gemm_mma(
    const char* __restrict__ Ap, const char* __restrict__ Bp,
    long aRB, long bRB, long zsA, long zsB, int kc1,
    const char* __restrict__ Ap2, const char* __restrict__ Bp2,
    long aRB2, long bRB2, int kc2,
    void* Cout, long zsC, int ldc, long cRB,
    float scale, const float* __restrict__ bias, int mode)
{
    int m0 = blockIdx.y * 128, n0 = blockIdx.x * 64;
    if ((mode & 2) && n0 >= m0 + 128) return;
    if (mode & 4) { int ke = (m0 + 128) >> 5; if (ke < kc1) kc1 = ke; }
    int z = blockIdx.z;
    Ap += (long)z * zsA;
    Bp += (long)z * zsB;
    char* Cb = (char*)Cout + (long)z * zsC;

    extern __shared__ char smem[];
    uint32_t sb = smem_u32(smem);
    int tid = threadIdx.x;
    int nch = kc1 + kc2;

    auto issue = [&](int c) {
        uint32_t stg = sb + (uint32_t)(c % 3) * STG;
        int cc = c;
        const char* pa; const char* pb; long ra, rb;
        if (c < kc1) { pa = Ap;  pb = Bp;  ra = aRB;  rb = bRB; }
        else         { pa = Ap2; pb = Bp2; ra = aRB2; rb = bRB2; cc = c - kc1; }
        long cOff = (long)cc * 64;
#pragma unroll
        for (int j = 0; j < 3; j++) {
            int slot = tid + j * 256;
            const char* g; uint32_t d;
            if (slot < 512) {
                int row = slot >> 2, seg = slot & 3;
                g = pa + (long)(m0 + row) * ra + cOff + seg * 16;
                d = stg + swz((uint32_t)(row * 128 + seg * 16));
            } else {
                int local = slot - 512;
                int row = local >> 2, seg = local & 3;
                g = pb + (long)(n0 + row) * rb + cOff + seg * 16;
                d = stg + (uint32_t)TA_BYTES + swz((uint32_t)(row * 128 + seg * 16));
            }
            asm volatile("cp.async.cg.shared.global [%0], [%1], 16;" :: "r"(d), "l"(g));
        }
        asm volatile("cp.async.commit_group;" ::: "memory");
    };

    int wid = tid >> 5, lane = tid & 31;
    int wm = wid >> 1, wn = wid & 1;   // 4 (m) x 2 (n) warps
    float acc[2][4][4] = {};

    issue(0);
    if (nch > 1) issue(1);
    else asm volatile("cp.async.commit_group;" ::: "memory");

    uint32_t aRowLoc = (uint32_t)((wm * 32 + (lane & 15)) * 128 + ((lane >> 4) << 4));
    int bg = lane >> 3;
    uint32_t bRowLoc = (uint32_t)((wn * 32 + (lane & 7) + ((bg >> 1) << 3)) * 128 + ((bg & 1) << 4));

    for (int c = 0; c < nch; c++) {
        asm volatile("cp.async.wait_group 1;" ::: "memory");
        __syncthreads();
        if (c + 2 < nch) issue(c + 2);
        else asm volatile("cp.async.commit_group;" ::: "memory");

        uint32_t ta = sb + (uint32_t)(c % 3) * STG;
        uint32_t tb = ta + TA_BYTES;
#pragma unroll
        for (int s = 0; s < 2; s++) {
            int ko = s * 32;
            uint32_t Ah[2][4], Bh[2][4];
#pragma unroll
            for (int mt = 0; mt < 2; mt++)
                ldsm4(Ah[mt], ta + swz(aRowLoc + mt * 2048 + ko));
#pragma unroll
            for (int bt = 0; bt < 2; bt++)
                ldsm4(Bh[bt], tb + swz(bRowLoc + bt * 2048 + ko));
#pragma unroll
            for (int mt = 0; mt < 2; mt++)
#pragma unroll
                for (int nt = 0; nt < 4; nt++)
                    mma_f16(acc[mt][nt], Ah[mt], &Bh[nt >> 1][(nt & 1) * 2]);
        }
    }

    // Epilogue
    int ql = lane & 3;
    int r0 = m0 + wm * 32 + (lane >> 2);
    if (mode & 16) {           // half packed out
        int cw = (n0 + wn * 32) >> 5;
        char* cbase = Cb + (long)cw * 64;
#pragma unroll
        for (int mt = 0; mt < 2; mt++) {
#pragma unroll
            for (int half = 0; half < 2; half++) {
                long row = r0 + mt * 16 + half * 8;
                char* rp = cbase + row * cRB;
#pragma unroll
                for (int nt = 0; nt < 4; nt++) {
                    float v0 = acc[mt][nt][half * 2 + 0] * scale;
                    float v1 = acc[mt][nt][half * 2 + 1] * scale;
                    int col = n0 + wn * 32 + nt * 8 + ql * 2;
                    if (bias) { v0 += bias[col]; v1 += bias[col + 1]; }
                    if (mode & 1) { v0 = fmaxf(v0, 0.f); v1 = fmaxf(v1, 0.f); }
                    *(uint32_t*)(rp + (nt * 8 + ql * 2) * 2) = f16pair(v0, v1);
                }
            }
        }
    } else {                   // fp32 out
        float* Cf = (float*)Cb;
#pragma unroll
        for (int mt = 0; mt < 2; mt++) {
#pragma unroll
            for (int half = 0; half < 2; half++) {
                long row = r0 + mt * 16 + half * 8;
#pragma unroll
                for (int nt = 0; nt < 4; nt++) {
                    float v0 = acc[mt][nt][half * 2 + 0] * scale;
                    float v1 = acc[mt][nt][half * 2 + 1] * scale;
                    int col = n0 + wn * 32 + nt * 8 + ql * 2;
                    if (bias) { v0 += bias[col]; v1 += bias[col + 1]; }
                    if (mode & 1) { v0 = fmaxf(v0, 0.f); v1 = fmaxf(v1, 0.f); }
                    *(float2*)(Cf + row * (long)ldc + col) = make_float2(v0, v1);
                }
            }
        }
    }
}

// ---------------------------------------------------------------------------
// Pack fp32 [rows][K] -> HALF packed
// ---------------------------------------------------------------------------
__global__ __launch_bounds__(256) void k_pack(const float* __restrict__ src,
                                              char* __restrict__ dst, int K) {
    long j0 = ((long)blockIdx.x * 256 + threadIdx.x) * 8;
    float4 f0 = *(const float4*)(src + j0);
    float4 f1 = *(const float4*)(src + j0 + 4);
    long row = j0 / K;
    int k0 = (int)(j0 - row * K);
    uint32_t h0 = f16pair(f0.x, f0.y), h1 = f16pair(f0.z, f0.w);
    uint32_t h2 = f16pair(f1.x, f1.y), h3 = f16pair(f1.z, f1.w);
    char* p = dst + row * (long)K * 2 + (k0 >> 5) * 64 + (k0 & 31) * 2;
    *(uint4*)p = make_uint4(h0, h1, h2, h3);
}

// ---------------------------------------------------------------------------
// ALL weight transposes in one launch. z selects the weight:
//  z=0..2: Wq/Wk/Wv -> wpk planes (R=1024); z=3: W2 -> w2pk (R=1024);
//  z=4: W1 -> w1pk (R=2048). Grid y covers 64 tiles; square weights skip y>=32.
// in fp32 [R][1024] -> HALF packed rows=1024, K=R
// ---------------------------------------------------------------------------
__global__ __launch_bounds__(256) void k_wtrans(
    const float* __restrict__ Wq, const float* __restrict__ Wk,
    const float* __restrict__ Wv, const float* __restrict__ W1,
    const float* __restrict__ W2,
    char* __restrict__ wpk, char* __restrict__ w1pk, char* __restrict__ w2pk)
{
    const long WPL = (long)DIM * DIM * 2;
    int z = blockIdx.z;
    const float* in; char* out; int R;
    if (z == 0)      { in = Wq; out = wpk;           R = DIM; }
    else if (z == 1) { in = Wk; out = wpk + WPL;     R = DIM; }
    else if (z == 2) { in = Wv; out = wpk + 2 * WPL; R = DIM; }
    else if (z == 3) { in = W2; out = w2pk;          R = DIM; }
    else             { in = W1; out = w1pk;          R = 2 * DIM; }
    int r0 = blockIdx.y * 32;
    if (r0 >= R) return;
    int c0 = blockIdx.x * 32;

    __shared__ float t[32][33];
    int tx = threadIdx.x & 31, ty = threadIdx.x >> 5;
#pragma unroll
    for (int i = ty; i < 32; i += 8)
        t[i][tx] = in[(long)(r0 + i) * DIM + c0 + tx];
    __syncthreads();
    int i = threadIdx.x >> 3;
    int g = (threadIdx.x & 7) * 4;
    float v0 = t[g + 0][i], v1 = t[g + 1][i], v2 = t[g + 2][i], v3 = t[g + 3][i];
    uint32_t h0 = f16pair(v0, v1), h1 = f16pair(v2, v3);
    char* p = out + (long)(c0 + i) * ((long)R * 2) + (r0 >> 5) * 64 + g * 2;
    *(uint2*)p = make_uint2(h0, h1);
}

// ---------------------------------------------------------------------------
// fp16 packed transpose: in HALF packed [R rows][C cols] -> out HALF packed
// [C rows][K=R], per batch z. Lossless.
// ---------------------------------------------------------------------------
__global__ __launch_bounds__(256) void k_transpose_h(
    const char* __restrict__ in, char* __restrict__ out,
    int R, int C, long inPlane, long outPlane)
{
    in  += (long)blockIdx.z * inPlane;
    out += (long)blockIdx.z * outPlane;
    int c0 = blockIdx.x * 32, r0 = blockIdx.y * 32;

    __shared__ __half t[32][33];
    // load 32x32 fp16 tile: 128 threads x 8 fp16 (16B)
    if (threadIdx.x < 128) {
        int r = threadIdx.x >> 2, seg = threadIdx.x & 3;
        const char* src = in + (long)(r0 + r) * ((long)C * 2)
                             + (c0 >> 5) * 64 + seg * 16;
        uint4 v = *(const uint4*)src;
        __half* hp = (__half*)&v;
#pragma unroll
        for (int e = 0; e < 8; e++) t[r][seg * 8 + e] = hp[e];
    }
    __syncthreads();
    // write transposed: 256 threads, each writes 4B (2 fp16) -> out row c0+i
    int i = threadIdx.x >> 4;           // 0..15? need 32 rows
    // 256 threads: i = tid>>3 (0..31), kk = (tid&7)*4
    i = threadIdx.x >> 3;
    int kk = (threadIdx.x & 7) * 4;
    uint32_t p0 = ((uint32_t)__half_as_ushort(t[kk + 0][i])) |
                  ((uint32_t)__half_as_ushort(t[kk + 1][i]) << 16);
    uint32_t p1 = ((uint32_t)__half_as_ushort(t[kk + 2][i])) |
                  ((uint32_t)__half_as_ushort(t[kk + 3][i]) << 16);
    char* dst = out + (long)(c0 + i) * ((long)R * 2) + (r0 >> 5) * 64 + kk * 2;
    *(uint2*)dst = make_uint2(p0, p1);
}

// ---------------------------------------------------------------------------
// Causal softmax: fp32 scores row -> HALF packed probs row
// ---------------------------------------------------------------------------
__global__ __launch_bounds__(256) void k_softmax() {
    long rowi = blockIdx.x;
    const float* p = g_scores + rowi * SEQ;
    char* dst = g_ppk + rowi * (SEQ * 2);
    int cnt = (int)(rowi & (SEQ - 1)) + 1;
    int tid = threadIdx.x;
    int j0 = tid * 8;
    __shared__ float red[256];

    float v[8];
    float4 f0 = *(const float4*)(p + j0);
    float4 f1 = *(const float4*)(p + j0 + 4);
    v[0]=f0.x; v[1]=f0.y; v[2]=f0.z; v[3]=f0.w;
    v[4]=f1.x; v[5]=f1.y; v[6]=f1.z; v[7]=f1.w;
    float m = -3.4e38f;
#pragma unroll
    for (int i = 0; i < 8; i++) {
        if (j0 + i >= cnt) v[i] = -3.4e38f;
        m = fmaxf(m, v[i]);
    }
    red[tid] = m;
    __syncthreads();
    for (int s = 128; s > 0; s >>= 1) {
        if (tid < s) red[tid] = fmaxf(red[tid], red[tid + s]);
        __syncthreads();
    }
    m = red[0];
    __syncthreads();
    float sum = 0.f;
#pragma unroll
    for (int i = 0; i < 8; i++) {
        v[i] = (j0 + i < cnt) ? __expf(v[i] - m) : 0.f;
        sum += v[i];
    }
    red[tid] = sum;
    __syncthreads();
    for (int s = 128; s > 0; s >>= 1) {
        if (tid < s) red[tid] += red[tid + s];
        __syncthreads();
    }
    float inv = 1.0f / red[0];
#pragma unroll
    for (int i = 0; i < 8; i++) v[i] *= inv;

    uint32_t h0 = f16pair(v[0], v[1]), h1 = f16pair(v[2], v[3]);
    uint32_t h2 = f16pair(v[4], v[5]), h3 = f16pair(v[6], v[7]);
    char* q = dst + (tid >> 2) * 64 + (tid & 3) * 16;
    *(uint4*)q = make_uint4(h0, h1, h2, h3);
}

// ---------------------------------------------------------------------------
// Launch
// ---------------------------------------------------------------------------
extern "C" void kernel_launch(void* const* d_in, const int* in_sizes, int n_in,
                              void* d_out, int out_size) {
    const float* x  = (const float*)d_in[0];
    const float* Wq = (const float*)d_in[1];
    const float* Wk = (const float*)d_in[2];
    const float* Wv = (const float*)d_in[3];
    const float* W1 = (const float*)d_in[4];
    const float* b1 = (const float*)d_in[5];
    const float* W2 = (const float*)d_in[6];
    const float* b2 = (const float*)d_in[7];
    float* out = (float*)d_out;

    cudaFuncSetAttribute(gemm_mma, cudaFuncAttributeMaxDynamicSharedMemorySize, GEMM_SMEM);

    void* p;
    cudaGetSymbolAddress(&p, g_xpk);    char* xpk   = (char*)p;
    cudaGetSymbolAddress(&p, g_wpk);    char* wpk   = (char*)p;
    cudaGetSymbolAddress(&p, g_w1pk);   char* w1pk  = (char*)p;
    cudaGetSymbolAddress(&p, g_w2pk);   char* w2pk  = (char*)p;
    cudaGetSymbolAddress(&p, g_qkvpk);  char* qkvpk = (char*)p;
    cudaGetSymbolAddress(&p, g_vtpk);   char* vtpk  = (char*)p;
    cudaGetSymbolAddress(&p, g_scores); float* sc   = (float*)p;
    cudaGetSymbolAddress(&p, g_ppk);    char* ppk   = (char*)p;
    cudaGetSymbolAddress(&p, g_apk);    char* apk   = (char*)p;
    cudaGetSymbolAddress(&p, g_hpk);    char* hpk   = (char*)p;

    const long WPL  = (long)DIM * DIM * 2;     // half-packed weight plane
    const long QKVP = (long)MTOT * DIM * 2;    // per-tensor plane in qkvpk
    char* qpk = qkvpk;
    char* kpk = qkvpk + QKVP;
    char* vpk = qkvpk + 2 * QKVP;

    // Pack x; all 5 weight transposes in one launch
    k_pack<<<dim3((MTOT * DIM) / (8 * 256)), 256>>>(x, xpk, DIM);
    k_wtrans<<<dim3(32, 64, 5), 256>>>(Wq, Wk, Wv, W1, W2, wpk, w1pk, w2pk);

    // q,k,v = x @ W{q,k,v} in ONE launch (z over weight planes; HALF out)
    gemm_mma<<<dim3(16, 64, 3), 256, GEMM_SMEM>>>(
        xpk, wpk, DIM * 2, DIM * 2, 0, WPL, 32,
        0, 0, 0, 0, 0,
        qkvpk, QKVP, 0, DIM * 2,
        1.0f, 0, 16);

    // vT (fp16->fp16 lossless transpose) per batch
    k_transpose_h<<<dim3(DIM / 32, SEQ / 32, BSZ), 256>>>(
        vpk, vtpk, SEQ, DIM, (long)SEQ * DIM * 2, (long)DIM * SEQ * 2);

    // scores = q k^T / 32 (1-pass fp16; causal skip; fp32 out)
    gemm_mma<<<dim3(32, 16, BSZ), 256, GEMM_SMEM>>>(
        qpk, kpk, DIM * 2, DIM * 2,
        (long)SEQ * DIM * 2, (long)SEQ * DIM * 2, 32,
        0, 0, 0, 0, 0,
        sc, (long)SEQ * SEQ * 4, SEQ, 0,
        0.03125f, 0, 2);
    k_softmax<<<dim3(BSZ * SEQ), 256>>>();

    // attn = probs @ v (1-pass; causal k-limit; HALF out)
    gemm_mma<<<dim3(16, 16, BSZ), 256, GEMM_SMEM>>>(
        ppk, vtpk, SEQ * 2, SEQ * 2, (long)SEQ * SEQ * 2, (long)DIM * SEQ * 2, 64,
        0, 0, 0, 0, 0,
        apk, (long)SEQ * DIM * 2, 0, DIM * 2,
        1.0f, 0, 4 | 16);
    // h = relu([attn|x] @ W1 + b1) (1-pass; HALF out)
    gemm_mma<<<dim3(16, 64, 1), 256, GEMM_SMEM>>>(
        apk, w1pk, DIM * 2, 2 * DIM * 2, 0, 0, 32,
        xpk, w1pk + 2048, DIM * 2, 2 * DIM * 2, 32,
        hpk, 0, 0, DIM * 2,
        1.0f, b1, 1 | 16);
    // out = h @ W2 + b2 (1-pass; fp32 out)
    gemm_mma<<<dim3(16, 64, 1), 256, GEMM_SMEM>>>(
        hpk, w2pk, DIM * 2, DIM * 2, 0, 0, 32,
        0, 0, 0, 0, 0,
        out, 0, DIM, 0,
        1.0f, b2, 0);
}

// round 15
// speedup vs baseline: 2.7402x; 1.0151x over previous
#include <cuda_runtime.h>
#include <cuda_fp16.h>
#include <cstdint>

#define BSZ 4
#define SEQ 2048
#define DIM 1024
#define MTOT (BSZ*SEQ)

// ---------------------------------------------------------------------------
// HALF packed layout everywhere: per row of K floats, K/32 chunks of 64B
// [32 fp16], row stride K*2 bytes.
// ---------------------------------------------------------------------------
__device__ __align__(128) char g_xpk   [(size_t)MTOT * DIM * 2];
__device__ __align__(128) char g_wpk   [(size_t)3 * DIM * DIM * 2];
__device__ __align__(128) char g_w1pk  [(size_t)DIM * 2 * DIM * 2];
__device__ __align__(128) char g_w2pk  [(size_t)DIM * DIM * 2];
__device__ __align__(128) char g_qkvpk [(size_t)3 * MTOT * DIM * 2];  // q|k|v
__device__ __align__(128) char g_scores[(size_t)BSZ * SEQ * SEQ * 2]; // fp16
__device__ __align__(128) char g_ppk   [(size_t)BSZ * SEQ * SEQ * 2];
__device__ __align__(128) char g_apk   [(size_t)MTOT * DIM * 2];
__device__ __align__(128) char g_hpk   [(size_t)MTOT * DIM * 2];

// ---------------------------------------------------------------------------
// Helpers
// ---------------------------------------------------------------------------
__device__ __forceinline__ uint32_t smem_u32(const void* p) {
    uint32_t a;
    asm("{ .reg .u64 t; cvta.to.shared.u64 t, %1; cvt.u32.u64 %0, t; }" : "=r"(a) : "l"(p));
    return a;
}
__device__ __forceinline__ uint32_t swz(uint32_t x) { return x ^ ((x >> 3) & 0x70); }

__device__ __forceinline__ uint32_t f16pair(float v0, float v1) {
    uint32_t r;   // low16 = fp16(v0), high16 = fp16(v1)
    asm("cvt.rn.f16x2.f32 %0, %1, %2;" : "=r"(r) : "f"(v1), "f"(v0));
    return r;
}
__device__ __forceinline__ void ldsm4(uint32_t* r, uint32_t addr) {
    asm volatile("ldmatrix.sync.aligned.m8n8.x4.shared.b16 {%0,%1,%2,%3}, [%4];"
                 : "=r"(r[0]), "=r"(r[1]), "=r"(r[2]), "=r"(r[3]) : "r"(addr));
}
__device__ __forceinline__ void ldsm4t(uint32_t* r, uint32_t addr) {
    asm volatile("ldmatrix.sync.aligned.m8n8.x4.trans.shared.b16 {%0,%1,%2,%3}, [%4];"
                 : "=r"(r[0]), "=r"(r[1]), "=r"(r[2]), "=r"(r[3]) : "r"(addr));
}
__device__ __forceinline__ void mma_f16(float* d, const uint32_t* a, const uint32_t* b) {
    asm volatile(
        "mma.sync.aligned.m16n8k16.row.col.f32.f16.f16.f32 "
        "{%0,%1,%2,%3}, {%4,%5,%6,%7}, {%8,%9}, {%0,%1,%2,%3};"
        : "+f"(d[0]), "+f"(d[1]), "+f"(d[2]), "+f"(d[3])
        : "r"(a[0]), "r"(a[1]), "r"(a[2]), "r"(a[3]), "r"(b[0]), "r"(b[1]));
}

// ---------------------------------------------------------------------------
// NT GEMM, 128(M)x64(N) tile, 8 warps (32x32 each), pure fp16 operands,
// fp32 accumulate. 3-stage cp.async pipeline, 1 sync/chunk.
// BNN=0: B source is K-major [n rows][k]  (NT, ldmatrix non-trans)
// BNN=1: B source is row-major [k rows][n] (NN, ldmatrix.trans; B tile is
//        32 k-rows x 128B of contiguous n-chunks)
// mode: 1=relu, 2=causal skip, 4=causal k-limit, 16=half packed out
// ---------------------------------------------------------------------------
#define TA_BYTES 16384
#define STG 24576
#define GEMM_SMEM (3 * STG)

template <int BNN>
__global__ __launch_bounds__(256, 3) void gemm_mma(
    const char* __restrict__ Ap, const char* __restrict__ Bp,
    long aRB, long bRB, long zsA, long zsB, int kc1,
    const char* __restrict__ Ap2, const char* __restrict__ Bp2,
    long aRB2, long bRB2, int kc2,
    void* Cout, long zsC, int ldc, long cRB,
    float scale, const float* __restrict__ bias, int mode)
{
    int m0 = blockIdx.y * 128, n0 = blockIdx.x * 64;
    if ((mode & 2) && n0 >= m0 + 128) return;
    if (mode & 4) { int ke = (m0 + 128) >> 5; if (ke < kc1) kc1 = ke; }
    int z = blockIdx.z;
    Ap += (long)z * zsA;
    Bp += (long)z * zsB;
    char* Cb = (char*)Cout + (long)z * zsC;

    extern __shared__ char smem[];
    uint32_t sb = smem_u32(smem);
    int tid = threadIdx.x;
    int nch = kc1 + kc2;

    auto issue = [&](int c) {
        uint32_t stg = sb + (uint32_t)(c % 3) * STG;
        int cc = c;
        const char* pa; const char* pb; long ra, rb;
        if (c < kc1) { pa = Ap;  pb = Bp;  ra = aRB;  rb = bRB; }
        else         { pa = Ap2; pb = Bp2; ra = aRB2; rb = bRB2; cc = c - kc1; }
        long cOff = (long)cc * 64;
#pragma unroll
        for (int j = 0; j < 3; j++) {
            int slot = tid + j * 256;
            const char* g; uint32_t d;
            if (slot < 512) {
                int row = slot >> 2, seg = slot & 3;
                g = pa + (long)(m0 + row) * ra + cOff + seg * 16;
                d = stg + swz((uint32_t)(row * 128 + seg * 16));
            } else if (BNN) {
                // B tile: 32 k-rows x 128B (64 n fp16, chunks contiguous)
                int local = slot - 512;
                int row = local >> 3, seg = local & 7;
                g = pb + (long)(cc * 32 + row) * rb + (long)n0 * 2 + seg * 16;
                d = stg + (uint32_t)TA_BYTES + swz((uint32_t)(row * 128 + seg * 16));
            } else {
                int local = slot - 512;
                int row = local >> 2, seg = local & 3;
                g = pb + (long)(n0 + row) * rb + cOff + seg * 16;
                d = stg + (uint32_t)TA_BYTES + swz((uint32_t)(row * 128 + seg * 16));
            }
            asm volatile("cp.async.cg.shared.global [%0], [%1], 16;" :: "r"(d), "l"(g));
        }
        asm volatile("cp.async.commit_group;" ::: "memory");
    };

    int wid = tid >> 5, lane = tid & 31;
    int wm = wid >> 1, wn = wid & 1;   // 4 (m) x 2 (n) warps
    float acc[2][4][4] = {};

    issue(0);
    if (nch > 1) issue(1);
    else asm volatile("cp.async.commit_group;" ::: "memory");

    uint32_t aRowLoc = (uint32_t)((wm * 32 + (lane & 15)) * 128 + ((lane >> 4) << 4));
    int bg = lane >> 3;
    uint32_t bRowLoc = (uint32_t)((wn * 32 + (lane & 7) + ((bg >> 1) << 3)) * 128 + ((bg & 1) << 4));
    // trans layout: matrix g = lane>>3: row (k) = (g&1)*8 + (lane&7),
    // byte col = wn*64 + (g>>1)*16
    uint32_t bRowLocT = (uint32_t)((((lane >> 3) & 1) * 8 + (lane & 7)) * 128
                                   + wn * 64 + ((lane >> 4) << 4));

    for (int c = 0; c < nch; c++) {
        asm volatile("cp.async.wait_group 1;" ::: "memory");
        __syncthreads();
        if (c + 2 < nch) issue(c + 2);
        else asm volatile("cp.async.commit_group;" ::: "memory");

        uint32_t ta = sb + (uint32_t)(c % 3) * STG;
        uint32_t tb = ta + TA_BYTES;
#pragma unroll
        for (int s = 0; s < 2; s++) {
            int ko = s * 32;
            uint32_t Ah[2][4], Bh[2][4];
#pragma unroll
            for (int mt = 0; mt < 2; mt++)
                ldsm4(Ah[mt], ta + swz(aRowLoc + mt * 2048 + ko));
#pragma unroll
            for (int bt = 0; bt < 2; bt++) {
                if (BNN) ldsm4t(Bh[bt], tb + swz(bRowLocT + s * 2048 + bt * 32));
                else     ldsm4 (Bh[bt], tb + swz(bRowLoc + bt * 2048 + ko));
            }
#pragma unroll
            for (int mt = 0; mt < 2; mt++)
#pragma unroll
                for (int nt = 0; nt < 4; nt++)
                    mma_f16(acc[mt][nt], Ah[mt], &Bh[nt >> 1][(nt & 1) * 2]);
        }
    }

    // Epilogue
    int ql = lane & 3;
    int r0 = m0 + wm * 32 + (lane >> 2);
    if (mode & 16) {           // half packed out
        int cw = (n0 + wn * 32) >> 5;
        char* cbase = Cb + (long)cw * 64;
#pragma unroll
        for (int mt = 0; mt < 2; mt++) {
#pragma unroll
            for (int half = 0; half < 2; half++) {
                long row = r0 + mt * 16 + half * 8;
                char* rp = cbase + row * cRB;
#pragma unroll
                for (int nt = 0; nt < 4; nt++) {
                    float v0 = acc[mt][nt][half * 2 + 0] * scale;
                    float v1 = acc[mt][nt][half * 2 + 1] * scale;
                    int col = n0 + wn * 32 + nt * 8 + ql * 2;
                    if (bias) { v0 += bias[col]; v1 += bias[col + 1]; }
                    if (mode & 1) { v0 = fmaxf(v0, 0.f); v1 = fmaxf(v1, 0.f); }
                    *(uint32_t*)(rp + (nt * 8 + ql * 2) * 2) = f16pair(v0, v1);
                }
            }
        }
    } else {                   // fp32 out
        float* Cf = (float*)Cb;
#pragma unroll
        for (int mt = 0; mt < 2; mt++) {
#pragma unroll
            for (int half = 0; half < 2; half++) {
                long row = r0 + mt * 16 + half * 8;
#pragma unroll
                for (int nt = 0; nt < 4; nt++) {
                    float v0 = acc[mt][nt][half * 2 + 0] * scale;
                    float v1 = acc[mt][nt][half * 2 + 1] * scale;
                    int col = n0 + wn * 32 + nt * 8 + ql * 2;
                    if (bias) { v0 += bias[col]; v1 += bias[col + 1]; }
                    if (mode & 1) { v0 = fmaxf(v0, 0.f); v1 = fmaxf(v1, 0.f); }
                    *(float2*)(Cf + row * (long)ldc + col) = make_float2(v0, v1);
                }
            }
        }
    }
}

// ---------------------------------------------------------------------------
// Pack fp32 [rows][K] -> HALF packed
// ---------------------------------------------------------------------------
__global__ __launch_bounds__(256) void k_pack(const float* __restrict__ src,
                                              char* __restrict__ dst, int K) {
    long j0 = ((long)blockIdx.x * 256 + threadIdx.x) * 8;
    float4 f0 = *(const float4*)(src + j0);
    float4 f1 = *(const float4*)(src + j0 + 4);
    long row = j0 / K;
    int k0 = (int)(j0 - row * K);
    uint32_t h0 = f16pair(f0.x, f0.y), h1 = f16pair(f0.z, f0.w);
    uint32_t h2 = f16pair(f1.x, f1.y), h3 = f16pair(f1.z, f1.w);
    char* p = dst + row * (long)K * 2 + (k0 >> 5) * 64 + (k0 & 31) * 2;
    *(uint4*)p = make_uint4(h0, h1, h2, h3);
}

// ---------------------------------------------------------------------------
// ALL weight transposes in one launch (z: 0-2 Wq/Wk/Wv, 3 W2, 4 W1)
// ---------------------------------------------------------------------------
__global__ __launch_bounds__(256) void k_wtrans(
    const float* __restrict__ Wq, const float* __restrict__ Wk,
    const float* __restrict__ Wv, const float* __restrict__ W1,
    const float* __restrict__ W2,
    char* __restrict__ wpk, char* __restrict__ w1pk, char* __restrict__ w2pk)
{
    const long WPL = (long)DIM * DIM * 2;
    int z = blockIdx.z;
    const float* in; char* out; int R;
    if (z == 0)      { in = Wq; out = wpk;           R = DIM; }
    else if (z == 1) { in = Wk; out = wpk + WPL;     R = DIM; }
    else if (z == 2) { in = Wv; out = wpk + 2 * WPL; R = DIM; }
    else if (z == 3) { in = W2; out = w2pk;          R = DIM; }
    else             { in = W1; out = w1pk;          R = 2 * DIM; }
    int r0 = blockIdx.y * 32;
    if (r0 >= R) return;
    int c0 = blockIdx.x * 32;

    __shared__ float t[32][33];
    int tx = threadIdx.x & 31, ty = threadIdx.x >> 5;
#pragma unroll
    for (int i = ty; i < 32; i += 8)
        t[i][tx] = in[(long)(r0 + i) * DIM + c0 + tx];
    __syncthreads();
    int i = threadIdx.x >> 3;
    int g = (threadIdx.x & 7) * 4;
    float v0 = t[g + 0][i], v1 = t[g + 1][i], v2 = t[g + 2][i], v3 = t[g + 3][i];
    uint32_t h0 = f16pair(v0, v1), h1 = f16pair(v2, v3);
    char* p = out + (long)(c0 + i) * ((long)R * 2) + (r0 >> 5) * 64 + g * 2;
    *(uint2*)p = make_uint2(h0, h1);
}

// ---------------------------------------------------------------------------
// Causal softmax: HALF packed scores row -> HALF packed probs row
// ---------------------------------------------------------------------------
__global__ __launch_bounds__(256) void k_softmax() {
    long rowi = blockIdx.x;
    const char* p = g_scores + rowi * (SEQ * 2);
    char* dst = g_ppk + rowi * (SEQ * 2);
    int cnt = (int)(rowi & (SEQ - 1)) + 1;
    int tid = threadIdx.x;
    int j0 = tid * 8;
    __shared__ float red[256];

    uint4 raw = *(const uint4*)(p + (j0 >> 5) * 64 + (j0 & 31) * 2);
    __half* hp = (__half*)&raw;
    float v[8];
    float m = -3.4e38f;
#pragma unroll
    for (int i = 0; i < 8; i++) {
        v[i] = (j0 + i < cnt) ? __half2float(hp[i]) : -3.4e38f;
        m = fmaxf(m, v[i]);
    }
    red[tid] = m;
    __syncthreads();
    for (int s = 128; s > 0; s >>= 1) {
        if (tid < s) red[tid] = fmaxf(red[tid], red[tid + s]);
        __syncthreads();
    }
    m = red[0];
    __syncthreads();
    float sum = 0.f;
#pragma unroll
    for (int i = 0; i < 8; i++) {
        v[i] = (j0 + i < cnt) ? __expf(v[i] - m) : 0.f;
        sum += v[i];
    }
    red[tid] = sum;
    __syncthreads();
    for (int s = 128; s > 0; s >>= 1) {
        if (tid < s) red[tid] += red[tid + s];
        __syncthreads();
    }
    float inv = 1.0f / red[0];
#pragma unroll
    for (int i = 0; i < 8; i++) v[i] *= inv;

    uint32_t h0 = f16pair(v[0], v[1]), h1 = f16pair(v[2], v[3]);
    uint32_t h2 = f16pair(v[4], v[5]), h3 = f16pair(v[6], v[7]);
    char* q = dst + (j0 >> 5) * 64 + (j0 & 31) * 2;
    *(uint4*)q = make_uint4(h0, h1, h2, h3);
}

// ---------------------------------------------------------------------------
// Launch
// ---------------------------------------------------------------------------
extern "C" void kernel_launch(void* const* d_in, const int* in_sizes, int n_in,
                              void* d_out, int out_size) {
    const float* x  = (const float*)d_in[0];
    const float* Wq = (const float*)d_in[1];
    const float* Wk = (const float*)d_in[2];
    const float* Wv = (const float*)d_in[3];
    const float* W1 = (const float*)d_in[4];
    const float* b1 = (const float*)d_in[5];
    const float* W2 = (const float*)d_in[6];
    const float* b2 = (const float*)d_in[7];
    float* out = (float*)d_out;

    cudaFuncSetAttribute(gemm_mma<0>, cudaFuncAttributeMaxDynamicSharedMemorySize, GEMM_SMEM);
    cudaFuncSetAttribute(gemm_mma<1>, cudaFuncAttributeMaxDynamicSharedMemorySize, GEMM_SMEM);

    void* p;
    cudaGetSymbolAddress(&p, g_xpk);    char* xpk   = (char*)p;
    cudaGetSymbolAddress(&p, g_wpk);    char* wpk   = (char*)p;
    cudaGetSymbolAddress(&p, g_w1pk);   char* w1pk  = (char*)p;
    cudaGetSymbolAddress(&p, g_w2pk);   char* w2pk  = (char*)p;
    cudaGetSymbolAddress(&p, g_qkvpk);  char* qkvpk = (char*)p;
    cudaGetSymbolAddress(&p, g_scores); char* sc    = (char*)p;
    cudaGetSymbolAddress(&p, g_ppk);    char* ppk   = (char*)p;
    cudaGetSymbolAddress(&p, g_apk);    char* apk   = (char*)p;
    cudaGetSymbolAddress(&p, g_hpk);    char* hpk   = (char*)p;

    const long WPL  = (long)DIM * DIM * 2;
    const long QKVP = (long)MTOT * DIM * 2;
    char* qpk = qkvpk;
    char* kpk = qkvpk + QKVP;
    char* vpk = qkvpk + 2 * QKVP;

    k_pack<<<dim3((MTOT * DIM) / (8 * 256)), 256>>>(x, xpk, DIM);
    k_wtrans<<<dim3(32, 64, 5), 256>>>(Wq, Wk, Wv, W1, W2, wpk, w1pk, w2pk);

    // q,k,v = x @ W{q,k,v} in one launch (HALF out)
    gemm_mma<0><<<dim3(16, 64, 3), 256, GEMM_SMEM>>>(
        xpk, wpk, DIM * 2, DIM * 2, 0, WPL, 32,
        0, 0, 0, 0, 0,
        qkvpk, QKVP, 0, DIM * 2,
        1.0f, 0, 16);

    // scores = q k^T / 32 (fp16 out; causal skip)
    gemm_mma<0><<<dim3(32, 16, BSZ), 256, GEMM_SMEM>>>(
        qpk, kpk, DIM * 2, DIM * 2,
        (long)SEQ * DIM * 2, (long)SEQ * DIM * 2, 32,
        0, 0, 0, 0, 0,
        sc, (long)SEQ * SEQ * 2, 0, SEQ * 2,
        0.03125f, 0, 2 | 16);
    k_softmax<<<dim3(BSZ * SEQ), 256>>>();

    // attn = probs @ v  (B read NN from v's natural [s][d] layout; k-limit)
    gemm_mma<1><<<dim3(16, 16, BSZ), 256, GEMM_SMEM>>>(
        ppk, vpk, SEQ * 2, DIM * 2, (long)SEQ * SEQ * 2, (long)SEQ * DIM * 2, 64,
        0, 0, 0, 0, 0,
        apk, (long)SEQ * DIM * 2, 0, DIM * 2,
        1.0f, 0, 4 | 16);
    // h = relu([attn|x] @ W1 + b1)
    gemm_mma<0><<<dim3(16, 64, 1), 256, GEMM_SMEM>>>(
        apk, w1pk, DIM * 2, 2 * DIM * 2, 0, 0, 32,
        xpk, w1pk + 2048, DIM * 2, 2 * DIM * 2, 32,
        hpk, 0, 0, DIM * 2,
        1.0f, b1, 1 | 16);
    // out = h @ W2 + b2 (fp32 out)
    gemm_mma<0><<<dim3(16, 64, 1), 256, GEMM_SMEM>>>(
        hpk, w2pk, DIM * 2, DIM * 2, 0, 0, 32,
        0, 0, 0, 0, 0,
        out, 0, DIM, 0,
        1.0f, b2, 0);
}